// round 1
// baseline (speedup 1.0000x reference)
#include <cuda_runtime.h>
#include <cuda_bf16.h>
#include <math.h>

// ---------------------------------------------------------------------------
// ViT transformer block, fp32 SIMT baseline.
// B=2, P=8, N=1024, DIM=512, HEADS=8, DIM_HEAD=64, INNER=512, HIDDEN=2048
// Rows (tokens) = B*P*N = 16384. Attention batches z = B*H*P = 128.
// ---------------------------------------------------------------------------

#define ROWS   16384
#define DIM    512
#define INNER  512
#define QKVW   1536
#define HIDDEN 2048
#define NSEQ   1024
#define NZ     128
#define SCALE  0.125f   // 64^-0.5
#define EPS    1e-5f

// Scratch (device globals; allocation-free per harness rules)
__device__ float g_xn  [(size_t)ROWS * DIM];     //  33.5 MB  LN0 output (residual)
__device__ float g_h   [(size_t)ROWS * DIM];     //  33.5 MB  LN1 output
__device__ float g_qkv [(size_t)ROWS * QKVW];    // 100.7 MB
__device__ float g_sc  [(size_t)NZ * NSEQ * NSEQ]; // 536.9 MB attention scores
__device__ float g_ao  [(size_t)ROWS * DIM];     //  33.5 MB  rearranged attn out
__device__ float g_x2  [(size_t)ROWS * DIM];     //  33.5 MB  post-attn residual
__device__ float g_mid [(size_t)ROWS * HIDDEN];  // 134.2 MB  MLP hidden

// ---------------------------------------------------------------------------
// Reductions
// ---------------------------------------------------------------------------
__device__ __forceinline__ float block_sum(float v, float* sm) {
    #pragma unroll
    for (int o = 16; o > 0; o >>= 1) v += __shfl_down_sync(0xffffffffu, v, o);
    int lane = threadIdx.x & 31, wid = threadIdx.x >> 5;
    if (lane == 0) sm[wid] = v;
    __syncthreads();
    v = (threadIdx.x < 8) ? sm[threadIdx.x] : 0.0f;
    if (wid == 0) {
        #pragma unroll
        for (int o = 4; o > 0; o >>= 1) v += __shfl_down_sync(0xffffffffu, v, o);
        if (lane == 0) sm[0] = v;
    }
    __syncthreads();
    float r = sm[0];
    __syncthreads();
    return r;
}

__device__ __forceinline__ float block_max(float v, float* sm) {
    #pragma unroll
    for (int o = 16; o > 0; o >>= 1) v = fmaxf(v, __shfl_down_sync(0xffffffffu, v, o));
    int lane = threadIdx.x & 31, wid = threadIdx.x >> 5;
    if (lane == 0) sm[wid] = v;
    __syncthreads();
    v = (threadIdx.x < 8) ? sm[threadIdx.x] : -INFINITY;
    if (wid == 0) {
        #pragma unroll
        for (int o = 4; o > 0; o >>= 1) v = fmaxf(v, __shfl_down_sync(0xffffffffu, v, o));
        if (lane == 0) sm[0] = v;
    }
    __syncthreads();
    float r = sm[0];
    __syncthreads();
    return r;
}

// ---------------------------------------------------------------------------
// Fused LN0 + LN1: one block per row of 512
// ---------------------------------------------------------------------------
__global__ void __launch_bounds__(256) ln_kernel(
    const float* __restrict__ x,
    const float* __restrict__ w0, const float* __restrict__ b0,
    const float* __restrict__ w1, const float* __restrict__ b1,
    float* __restrict__ xn, float* __restrict__ h)
{
    __shared__ float sm[32];
    size_t row = blockIdx.x;
    const float* xr = x + row * DIM;
    int t = threadIdx.x;

    float v0 = xr[t], v1 = xr[t + 256];
    float mu = block_sum(v0 + v1, sm) * (1.0f / DIM);
    float d0 = v0 - mu, d1 = v1 - mu;
    float var = block_sum(d0 * d0 + d1 * d1, sm) * (1.0f / DIM);
    float r = rsqrtf(var + EPS);
    float y0 = d0 * r * w0[t] + b0[t];
    float y1 = d1 * r * w0[t + 256] + b0[t + 256];
    xn[row * DIM + t]       = y0;
    xn[row * DIM + t + 256] = y1;

    float mu2 = block_sum(y0 + y1, sm) * (1.0f / DIM);
    float e0 = y0 - mu2, e1 = y1 - mu2;
    float var2 = block_sum(e0 * e0 + e1 * e1, sm) * (1.0f / DIM);
    float r2 = rsqrtf(var2 + EPS);
    h[row * DIM + t]       = e0 * r2 * w1[t] + b1[t];
    h[row * DIM + t + 256] = e1 * r2 * w1[t + 256] + b1[t + 256];
}

// ---------------------------------------------------------------------------
// Generic NN GEMM: C[M,N] = A[M,K] @ B[K,N], 128x128x16 tile, 8x8/thread
// EPI: 0 = plain, 1 = +bias +res, 2 = gelu(+bias)
// Requires K % 16 == 0, K % 4 == 0, N % 4 == 0 (true for all call sites).
// ---------------------------------------------------------------------------
__device__ __forceinline__ float gelu_f(float x) {
    return 0.5f * x * (1.0f + erff(x * 0.7071067811865475f));
}

template <int EPI>
__global__ void __launch_bounds__(256) gemm_kernel(
    const float* __restrict__ A, const float* __restrict__ B, float* __restrict__ C,
    int M, int N, int K,
    const float* __restrict__ bias, const float* __restrict__ res)
{
    constexpr int BM = 128, BN = 128, BK = 16, TM = 8, TN = 8;
    __shared__ float As[BK][BM];
    __shared__ float Bs[BK][BN + 4];
    int tid = threadIdx.x;
    int tx = tid & 15, ty = tid >> 4;
    int row0 = blockIdx.y * BM;
    int col0 = blockIdx.x * BN;
    float acc[TM][TN] = {};

    for (int k0 = 0; k0 < K; k0 += BK) {
        #pragma unroll
        for (int l = 0; l < 2; l++) {
            int idx = tid + l * 256;           // 512 float4 slots for A tile
            int m = idx >> 2;
            int kk = (idx & 3) << 2;
            int gm = row0 + m;
            float4 v = make_float4(0.f, 0.f, 0.f, 0.f);
            if (gm < M) v = *(const float4*)(A + (size_t)gm * K + k0 + kk);
            As[kk + 0][m] = v.x; As[kk + 1][m] = v.y;
            As[kk + 2][m] = v.z; As[kk + 3][m] = v.w;
        }
        #pragma unroll
        for (int l = 0; l < 2; l++) {
            int idx = tid + l * 256;           // 512 float4 slots for B tile
            int kk = idx >> 5;
            int n4 = (idx & 31) << 2;
            int gn = col0 + n4;
            float4 v = make_float4(0.f, 0.f, 0.f, 0.f);
            if (gn < N) v = *(const float4*)(B + (size_t)(k0 + kk) * N + gn);
            *(float4*)&Bs[kk][n4] = v;
        }
        __syncthreads();
        #pragma unroll
        for (int kk = 0; kk < BK; kk++) {
            float ra[TM], rb[TN];
            #pragma unroll
            for (int i = 0; i < TM; i++) ra[i] = As[kk][ty * TM + i];
            #pragma unroll
            for (int j = 0; j < TN; j++) rb[j] = Bs[kk][tx * TN + j];
            #pragma unroll
            for (int i = 0; i < TM; i++)
                #pragma unroll
                for (int j = 0; j < TN; j++)
                    acc[i][j] = fmaf(ra[i], rb[j], acc[i][j]);
        }
        __syncthreads();
    }

    #pragma unroll
    for (int i = 0; i < TM; i++) {
        int gm = row0 + ty * TM + i;
        if (gm >= M) continue;
        #pragma unroll
        for (int j = 0; j < TN; j++) {
            int gn = col0 + tx * TN + j;
            if (gn >= N) continue;
            float v = acc[i][j];
            if (EPI == 1) v += bias[gn] + res[(size_t)gm * N + gn];
            if (EPI == 2) v = gelu_f(v + bias[gn]);
            C[(size_t)gm * N + gn] = v;
        }
    }
}

// ---------------------------------------------------------------------------
// QK^T: per batch z, scores[z][n][m] = SCALE * sum_d q[n,d]*k[m,d]
// q row stride 1536 inside g_qkv. grid (8, 8, 128)
// ---------------------------------------------------------------------------
__global__ void __launch_bounds__(256) qk_kernel(
    const float* __restrict__ qkv, float* __restrict__ scores)
{
    constexpr int BM = 128, BN = 128, BK = 16, TM = 8, TN = 8;
    __shared__ float As[BK][BM];
    __shared__ float Bs[BK][BN];
    int z = blockIdx.z;
    int b = z >> 6, hh = (z >> 3) & 7, p = z & 7;
    const float* qb = qkv + (size_t)((b * 8 + p) * NSEQ) * QKVW + hh * 64;
    const float* kb = qb + INNER;
    int tid = threadIdx.x;
    int tx = tid & 15, ty = tid >> 4;
    int row0 = blockIdx.y * BM, col0 = blockIdx.x * BN;
    float acc[TM][TN] = {};

    for (int k0 = 0; k0 < 64; k0 += BK) {
        #pragma unroll
        for (int l = 0; l < 2; l++) {
            int idx = tid + l * 256;
            int m = idx >> 2;
            int kk = (idx & 3) << 2;
            float4 v = *(const float4*)(qb + (size_t)(row0 + m) * QKVW + k0 + kk);
            As[kk + 0][m] = v.x; As[kk + 1][m] = v.y;
            As[kk + 2][m] = v.z; As[kk + 3][m] = v.w;
        }
        #pragma unroll
        for (int l = 0; l < 2; l++) {
            int idx = tid + l * 256;
            int n = idx >> 2;
            int kk = (idx & 3) << 2;
            float4 v = *(const float4*)(kb + (size_t)(col0 + n) * QKVW + k0 + kk);
            Bs[kk + 0][n] = v.x; Bs[kk + 1][n] = v.y;
            Bs[kk + 2][n] = v.z; Bs[kk + 3][n] = v.w;
        }
        __syncthreads();
        #pragma unroll
        for (int kk = 0; kk < BK; kk++) {
            float ra[TM], rb[TN];
            #pragma unroll
            for (int i = 0; i < TM; i++) ra[i] = As[kk][ty * TM + i];
            #pragma unroll
            for (int j = 0; j < TN; j++) rb[j] = Bs[kk][tx * TN + j];
            #pragma unroll
            for (int i = 0; i < TM; i++)
                #pragma unroll
                for (int j = 0; j < TN; j++)
                    acc[i][j] = fmaf(ra[i], rb[j], acc[i][j]);
        }
        __syncthreads();
    }

    float* out = scores + (size_t)z * NSEQ * NSEQ;
    #pragma unroll
    for (int i = 0; i < TM; i++) {
        size_t gm = row0 + ty * TM + i;
        #pragma unroll
        for (int j = 0; j < TN; j++)
            out[gm * NSEQ + col0 + tx * TN + j] = acc[i][j] * SCALE;
    }
}

// ---------------------------------------------------------------------------
// Row softmax over 1024 keys. grid = 131072 rows, 256 threads, 4 elems/thread
// ---------------------------------------------------------------------------
__global__ void __launch_bounds__(256) softmax_kernel(float* __restrict__ scores)
{
    __shared__ float sm[32];
    float* prow = scores + (size_t)blockIdx.x * NSEQ;
    int t = threadIdx.x;
    float v[4];
    #pragma unroll
    for (int i = 0; i < 4; i++) v[i] = prow[t + i * 256];
    float m = fmaxf(fmaxf(v[0], v[1]), fmaxf(v[2], v[3]));
    m = block_max(m, sm);
    float s = 0.f;
    #pragma unroll
    for (int i = 0; i < 4; i++) { v[i] = __expf(v[i] - m); s += v[i]; }
    s = block_sum(s, sm);
    float inv = 1.0f / s;
    #pragma unroll
    for (int i = 0; i < 4; i++) prow[t + i * 256] = v[i] * inv;
}

// ---------------------------------------------------------------------------
// AV: per batch z, out[n,d] = sum_m attn[n,m]*v[m,d]  (M=1024, N=64, K=1024)
// Scatter epilogue implements the buggy rearrange:
//   ao[(b*8+hh)*1024 + n][p*64 + d]
// grid (8, 128); tile 128x64x16, 8x4/thread
// ---------------------------------------------------------------------------
__global__ void __launch_bounds__(256) av_kernel(
    const float* __restrict__ qkv, const float* __restrict__ scores,
    float* __restrict__ ao)
{
    constexpr int BM = 128, BN = 64, BK = 16, TM = 8, TN = 4;
    __shared__ float As[BK][BM];
    __shared__ float Bs[BK][BN + 4];
    int z = blockIdx.y;
    int b = z >> 6, hh = (z >> 3) & 7, p = z & 7;
    const float* ab = scores + (size_t)z * NSEQ * NSEQ;
    const float* vb = qkv + (size_t)((b * 8 + p) * NSEQ) * QKVW + 2 * INNER + hh * 64;
    int tid = threadIdx.x;
    int tx = tid & 15, ty = tid >> 4;
    int row0 = blockIdx.x * BM;
    float acc[TM][TN] = {};

    for (int k0 = 0; k0 < NSEQ; k0 += BK) {
        #pragma unroll
        for (int l = 0; l < 2; l++) {
            int idx = tid + l * 256;
            int m = idx >> 2;
            int kk = (idx & 3) << 2;
            float4 v = *(const float4*)(ab + (size_t)(row0 + m) * NSEQ + k0 + kk);
            As[kk + 0][m] = v.x; As[kk + 1][m] = v.y;
            As[kk + 2][m] = v.z; As[kk + 3][m] = v.w;
        }
        {
            int kk = tid >> 4;            // 0..15
            int n4 = (tid & 15) << 2;     // 0..60
            float4 v = *(const float4*)(vb + (size_t)(k0 + kk) * QKVW + n4);
            *(float4*)&Bs[kk][n4] = v;
        }
        __syncthreads();
        #pragma unroll
        for (int kk = 0; kk < BK; kk++) {
            float ra[TM], rb[TN];
            #pragma unroll
            for (int i = 0; i < TM; i++) ra[i] = As[kk][ty * TM + i];
            #pragma unroll
            for (int j = 0; j < TN; j++) rb[j] = Bs[kk][tx * TN + j];
            #pragma unroll
            for (int i = 0; i < TM; i++)
                #pragma unroll
                for (int j = 0; j < TN; j++)
                    acc[i][j] = fmaf(ra[i], rb[j], acc[i][j]);
        }
        __syncthreads();
    }

    size_t obase = (size_t)(b * 8 + hh) * NSEQ;
    #pragma unroll
    for (int i = 0; i < TM; i++) {
        size_t n = row0 + ty * TM + i;
        #pragma unroll
        for (int j = 0; j < TN; j++) {
            int d = tx * TN + j;
            ao[(obase + n) * DIM + p * 64 + d] = acc[i][j];
        }
    }
}

// ---------------------------------------------------------------------------
// Launch
// ---------------------------------------------------------------------------
extern "C" void kernel_launch(void* const* d_in, const int* in_sizes, int n_in,
                              void* d_out, int out_size)
{
    (void)in_sizes; (void)n_in; (void)out_size;
    const float* x     = (const float*)d_in[0];
    const float* ln0_w = (const float*)d_in[1];
    const float* ln0_b = (const float*)d_in[2];
    const float* ln1_w = (const float*)d_in[3];
    const float* ln1_b = (const float*)d_in[4];
    const float* w_qkv = (const float*)d_in[5];
    const float* w_o   = (const float*)d_in[6];
    const float* b_o   = (const float*)d_in[7];
    const float* w1    = (const float*)d_in[8];
    const float* b1    = (const float*)d_in[9];
    const float* w2    = (const float*)d_in[10];
    const float* b2    = (const float*)d_in[11];
    float* out = (float*)d_out;

    void *p_xn, *p_h, *p_qkv, *p_sc, *p_ao, *p_x2, *p_mid;
    cudaGetSymbolAddress(&p_xn,  g_xn);
    cudaGetSymbolAddress(&p_h,   g_h);
    cudaGetSymbolAddress(&p_qkv, g_qkv);
    cudaGetSymbolAddress(&p_sc,  g_sc);
    cudaGetSymbolAddress(&p_ao,  g_ao);
    cudaGetSymbolAddress(&p_x2,  g_x2);
    cudaGetSymbolAddress(&p_mid, g_mid);
    float* xn  = (float*)p_xn;
    float* h   = (float*)p_h;
    float* qkv = (float*)p_qkv;
    float* sc  = (float*)p_sc;
    float* ao  = (float*)p_ao;
    float* x2  = (float*)p_x2;
    float* mid = (float*)p_mid;

    // 1) LN0 + LN1
    ln_kernel<<<ROWS, 256>>>(x, ln0_w, ln0_b, ln1_w, ln1_b, xn, h);
    // 2) QKV GEMM: [16384,512] @ [512,1536]
    gemm_kernel<0><<<dim3(QKVW / 128, ROWS / 128), 256>>>(
        h, w_qkv, qkv, ROWS, QKVW, DIM, nullptr, nullptr);
    // 3) scores = q @ k^T * scale
    qk_kernel<<<dim3(8, 8, NZ), 256>>>(qkv, sc);
    // 4) softmax
    softmax_kernel<<<NZ * NSEQ, 256>>>(sc);
    // 5) out = attn @ v, scattered into rearranged layout
    av_kernel<<<dim3(8, NZ), 256>>>(qkv, sc, ao);
    // 6) proj: x2 = ao @ w_o + b_o + xn
    gemm_kernel<1><<<dim3(DIM / 128, ROWS / 128), 256>>>(
        ao, w_o, x2, ROWS, DIM, INNER, b_o, xn);
    // 7) mid = gelu(x2 @ w1 + b1)
    gemm_kernel<2><<<dim3(HIDDEN / 128, ROWS / 128), 256>>>(
        x2, w1, mid, ROWS, HIDDEN, DIM, b1, nullptr);
    // 8) out = mid @ w2 + b2 + x2
    gemm_kernel<1><<<dim3(DIM / 128, ROWS / 128), 256>>>(
        mid, w2, out, ROWS, DIM, HIDDEN, b2, x2);
}

// round 3
// speedup vs baseline: 4.1108x; 4.1108x over previous
#include <cuda_runtime.h>
#include <cuda_bf16.h>
#include <cstdint>
#include <math.h>

// ---------------------------------------------------------------------------
// ViT transformer block on mma.sync (HMMA) split-bf16 3-pass tensor cores.
// B=2, P=8, N=1024, DIM=512, HEADS=8, DIM_HEAD=64, INNER=512, HIDDEN=2048
// ---------------------------------------------------------------------------

#define ROWS   16384
#define DIM    512
#define INNER  512
#define QKVW   1536
#define HIDDEN 2048
#define NSEQ   1024
#define NZ     128
#define SCALE  0.125f
#define EPS    1e-5f

typedef __nv_bfloat16 bf16;

// ------------------------- device scratch ---------------------------------
__device__ __align__(256) float g_xn  [(size_t)ROWS * DIM];
__device__ __align__(256) bf16  g_hh  [(size_t)ROWS * DIM];
__device__ __align__(256) bf16  g_hl  [(size_t)ROWS * DIM];
__device__ __align__(256) bf16  g_qkvh[(size_t)ROWS * QKVW];
__device__ __align__(256) bf16  g_qkvl[(size_t)ROWS * QKVW];
__device__ __align__(256) float g_sc  [(size_t)NZ * NSEQ * NSEQ];
__device__ __align__(256) bf16  g_ath [(size_t)NZ * NSEQ * NSEQ];
__device__ __align__(256) bf16  g_atl [(size_t)NZ * NSEQ * NSEQ];
__device__ __align__(256) bf16  g_aoh [(size_t)ROWS * DIM];
__device__ __align__(256) bf16  g_aol [(size_t)ROWS * DIM];
__device__ __align__(256) float g_x2  [(size_t)ROWS * DIM];
__device__ __align__(256) bf16  g_x2h [(size_t)ROWS * DIM];
__device__ __align__(256) bf16  g_x2l [(size_t)ROWS * DIM];
__device__ __align__(256) bf16  g_midh[(size_t)ROWS * HIDDEN];
__device__ __align__(256) bf16  g_midl[(size_t)ROWS * HIDDEN];
// transposed/split weights [N, K]
__device__ __align__(256) bf16  g_wqkvt_h[(size_t)QKVW * DIM];
__device__ __align__(256) bf16  g_wqkvt_l[(size_t)QKVW * DIM];
__device__ __align__(256) bf16  g_wot_h  [(size_t)DIM * INNER];
__device__ __align__(256) bf16  g_wot_l  [(size_t)DIM * INNER];
__device__ __align__(256) bf16  g_w1t_h  [(size_t)HIDDEN * DIM];
__device__ __align__(256) bf16  g_w1t_l  [(size_t)HIDDEN * DIM];
__device__ __align__(256) bf16  g_w2t_h  [(size_t)DIM * HIDDEN];
__device__ __align__(256) bf16  g_w2t_l  [(size_t)DIM * HIDDEN];

// ------------------------- PTX helpers ------------------------------------
__device__ __forceinline__ uint32_t smem_u32(const void* p) {
    uint32_t a;
    asm("{ .reg .u64 t; cvta.to.shared.u64 t, %1; cvt.u32.u64 %0, t; }"
        : "=r"(a) : "l"(p));
    return a;
}
#define CP_ASYNC_16(sa, ga) \
    asm volatile("cp.async.cg.shared.global [%0], [%1], 16;" \
                 :: "r"((uint32_t)(sa)), "l"(ga) : "memory")
#define CP_COMMIT() asm volatile("cp.async.commit_group;" ::: "memory")
#define CP_WAIT0()  asm volatile("cp.async.wait_group 0;" ::: "memory")
#define CP_WAIT1()  asm volatile("cp.async.wait_group 1;" ::: "memory")

__device__ __forceinline__ void ldsm4(uint32_t* r, uint32_t addr) {
    asm volatile("ldmatrix.sync.aligned.m8n8.x4.shared.b16 {%0,%1,%2,%3}, [%4];"
        : "=r"(r[0]), "=r"(r[1]), "=r"(r[2]), "=r"(r[3]) : "r"(addr));
}
__device__ __forceinline__ void ldsm4t(uint32_t* r, uint32_t addr) {
    asm volatile("ldmatrix.sync.aligned.m8n8.x4.trans.shared.b16 {%0,%1,%2,%3}, [%4];"
        : "=r"(r[0]), "=r"(r[1]), "=r"(r[2]), "=r"(r[3]) : "r"(addr));
}
__device__ __forceinline__ void mma_bf16(float* c, const uint32_t* a, const uint32_t* b) {
    asm volatile(
        "mma.sync.aligned.m16n8k16.row.col.f32.bf16.bf16.f32 "
        "{%0,%1,%2,%3}, {%4,%5,%6,%7}, {%8,%9}, {%0,%1,%2,%3};"
        : "+f"(c[0]), "+f"(c[1]), "+f"(c[2]), "+f"(c[3])
        : "r"(a[0]), "r"(a[1]), "r"(a[2]), "r"(a[3]), "r"(b[0]), "r"(b[1]));
}

__device__ __forceinline__ float gelu_f(float x) {
    return 0.5f * x * (1.0f + erff(x * 0.7071067811865475f));
}
__device__ __forceinline__ void split_bf16(float v, bf16& h, bf16& l) {
    h = __float2bfloat16(v);
    l = __float2bfloat16(v - __bfloat162float(h));
}

// swizzled smem addr for a 64B-row tile (rows x 32 bf16)
__device__ __forceinline__ uint32_t sw64(uint32_t base, int row, int chunk) {
    return base + row * 64 + ((chunk ^ ((row >> 1) & 3)) << 4);
}
// swizzled smem addr for a 128B-row tile (rows x 64 bf16)
__device__ __forceinline__ uint32_t sw128(uint32_t base, int row, int chunk) {
    return base + row * 128 + ((chunk ^ (row & 7)) << 4);
}

// ---------------------------------------------------------------------------
// Generic split-bf16 MMA GEMM: C[M,N] = A[M,K] @ Bt[N,K]^T
// BM=128, BN=128, BK=32. 8 warps (2x4), warp tile 64x32.
// EPI: 1 split-only; 2 fp32(acc+bias+res)+split; 3 split(gelu(acc+bias));
//      4 fp32(acc+bias+res); 5 fp32(acc*SCALE)
// QKMODE: pointers offset per attention batch z = blockIdx.z
// ---------------------------------------------------------------------------
#define GSTAGE 32768
#define GSMEM  (2 * GSTAGE)

template <int EPI, int QKMODE>
__global__ void __launch_bounds__(256, 1) mma_gemm(
    const bf16* __restrict__ Ahi, const bf16* __restrict__ Alo,
    const bf16* __restrict__ Bhi, const bf16* __restrict__ Blo,
    int M, int N, int K, int lda, int ldb,
    const float* __restrict__ bias, const float* __restrict__ res,
    float* __restrict__ Cf, bf16* __restrict__ Chi, bf16* __restrict__ Clo)
{
    extern __shared__ char smem[];
    uint32_t sb = smem_u32(smem);
    int tid = threadIdx.x, wid = tid >> 5, lane = tid & 31;
    int row0 = blockIdx.y * 128, col0 = blockIdx.x * 128;

    if (QKMODE) {
        int z = blockIdx.z;
        int b = z >> 6, h = (z >> 3) & 7, p = z & 7;
        size_t rb = (size_t)((b * 8 + p)) * NSEQ;
        Ahi += rb * lda + h * 64;        Alo += rb * lda + h * 64;
        Bhi += rb * ldb + 512 + h * 64;  Blo += rb * ldb + 512 + h * 64;
        Cf  += (size_t)z * NSEQ * NSEQ;
    }

    const int NC = K >> 5;

    auto load_stage = [&](int c) {
        uint32_t st = sb + (c & 1) * GSTAGE;
        int k0 = c << 5;
        #pragma unroll
        for (int l = 0; l < 8; l++) {
            int idx = tid + l * 256;
            int mat = idx >> 9, r = (idx >> 2) & 127, ch = idx & 3;
            uint32_t dst = sw64(st + mat * 8192, r, ch);
            const bf16* src;
            if (mat == 0)      src = Ahi + (size_t)(row0 + r) * lda + k0 + ch * 8;
            else if (mat == 1) src = Alo + (size_t)(row0 + r) * lda + k0 + ch * 8;
            else if (mat == 2) src = Bhi + (size_t)(col0 + r) * ldb + k0 + ch * 8;
            else               src = Blo + (size_t)(col0 + r) * ldb + k0 + ch * 8;
            CP_ASYNC_16(dst, src);
        }
        CP_COMMIT();
    };

    float acc[4][4][4] = {};
    int mi = lane >> 3, lr = lane & 7;
    int wm = (wid >> 2) * 64;   // warp row origin in tile
    int wn = (wid & 3) * 32;    // warp col origin in tile

    load_stage(0);

    for (int c = 0; c < NC; c++) {
        uint32_t st = sb + (c & 1) * GSTAGE;
        if (c + 1 < NC) { load_stage(c + 1); CP_WAIT1(); }
        else            { CP_WAIT0(); }
        __syncthreads();

        #pragma unroll
        for (int s16 = 0; s16 < 2; s16++) {
            uint32_t ah[4][4], al[4][4], bh[2][4], bl[2][4];
            #pragma unroll
            for (int t = 0; t < 4; t++) {
                int row = wm + t * 16 + ((mi & 1) << 3) + lr;
                int ch  = s16 * 2 + (mi >> 1);
                ldsm4(ah[t], sw64(st,        row, ch));
                ldsm4(al[t], sw64(st + 8192, row, ch));
            }
            #pragma unroll
            for (int p = 0; p < 2; p++) {
                int row = wn + p * 16 + ((mi >> 1) << 3) + lr;
                int ch  = s16 * 2 + (mi & 1);
                ldsm4(bh[p], sw64(st + 16384, row, ch));
                ldsm4(bl[p], sw64(st + 24576, row, ch));
            }
            #pragma unroll
            for (int tm = 0; tm < 4; tm++)
                #pragma unroll
                for (int tn = 0; tn < 4; tn++) {
                    uint32_t* BH = &bh[tn >> 1][(tn & 1) * 2];
                    uint32_t* BL = &bl[tn >> 1][(tn & 1) * 2];
                    mma_bf16(acc[tm][tn], ah[tm], BH);
                    mma_bf16(acc[tm][tn], ah[tm], BL);
                    mma_bf16(acc[tm][tn], al[tm], BH);
                }
        }
        __syncthreads();
    }

    // epilogue (direct global stores)
    int g = lane >> 2, tc = lane & 3;
    #pragma unroll
    for (int tm = 0; tm < 4; tm++) {
        #pragma unroll
        for (int tn = 0; tn < 4; tn++) {
            int rr = row0 + wm + tm * 16 + g;
            int cc = col0 + wn + tn * 8 + tc * 2;
            #pragma unroll
            for (int half = 0; half < 2; half++) {
                int r_ = rr + half * 8;
                float v0 = acc[tm][tn][half * 2 + 0];
                float v1 = acc[tm][tn][half * 2 + 1];
                size_t off = (size_t)r_ * N + cc;
                if (EPI == 5) {
                    *(float2*)(Cf + off) = make_float2(v0 * SCALE, v1 * SCALE);
                } else if (EPI == 4 || EPI == 2) {
                    float2 b2 = *(const float2*)(bias + cc);
                    float2 r2 = *(const float2*)(res + off);
                    v0 += b2.x + r2.x; v1 += b2.y + r2.y;
                    *(float2*)(Cf + off) = make_float2(v0, v1);
                } else if (EPI == 3) {
                    float2 b2 = *(const float2*)(bias + cc);
                    v0 = gelu_f(v0 + b2.x); v1 = gelu_f(v1 + b2.y);
                }
                if (EPI == 1 || EPI == 2 || EPI == 3) {
                    bf16 h0, l0, h1, l1;
                    split_bf16(v0, h0, l0); split_bf16(v1, h1, l1);
                    *(__nv_bfloat162*)(Chi + off) = __nv_bfloat162(h0, h1);
                    *(__nv_bfloat162*)(Clo + off) = __nv_bfloat162(l0, l1);
                }
            }
        }
    }
}

// ---------------------------------------------------------------------------
// AV: per z, out[n,d] = sum_m attn[n,m] * v[m,d]; buggy-rearrange scatter.
// BM=128 (attn rows), BN=64 (d), BK=32 (m). 8 warps 4x2, warp tile 32x32.
// A = attn (k-contig), V via ldmatrix.trans from [m][d] tiles.
// ---------------------------------------------------------------------------
#define AVSTAGE 24576
#define AVSMEM  (2 * AVSTAGE)

__global__ void __launch_bounds__(256, 1) av_mma(
    const bf16* __restrict__ ath, const bf16* __restrict__ atl,
    const bf16* __restrict__ qkvh, const bf16* __restrict__ qkvl,
    bf16* __restrict__ aoh, bf16* __restrict__ aol)
{
    extern __shared__ char smem[];
    uint32_t sb = smem_u32(smem);
    int tid = threadIdx.x, wid = tid >> 5, lane = tid & 31;
    int z = blockIdx.y;
    int b = z >> 6, h = (z >> 3) & 7, p = z & 7;
    int row0 = blockIdx.x * 128;

    const bf16* Ah = ath + ((size_t)z << 20);
    const bf16* Al = atl + ((size_t)z << 20);
    size_t vbase = (size_t)((b * 8 + p)) * NSEQ * QKVW + 2 * INNER + h * 64;
    const bf16* Vh = qkvh + vbase;
    const bf16* Vl = qkvl + vbase;

    const int NC = NSEQ >> 5;   // 32

    auto load_stage = [&](int c) {
        uint32_t st = sb + (c & 1) * AVSTAGE;
        int k0 = c << 5;
        #pragma unroll
        for (int l = 0; l < 6; l++) {
            int idx = tid + l * 256;
            if (idx < 1024) {
                int mat = idx >> 9, r = (idx >> 2) & 127, ch = idx & 3;
                uint32_t dst = sw64(st + mat * 8192, r, ch);
                const bf16* src = (mat == 0 ? Ah : Al) + (size_t)(row0 + r) * NSEQ + k0 + ch * 8;
                CP_ASYNC_16(dst, src);
            } else {
                int i2 = idx - 1024;
                int mat = i2 >> 8, r = (i2 >> 3) & 31, ch = i2 & 7;
                uint32_t dst = sw128(st + 16384 + mat * 4096, r, ch);
                const bf16* src = (mat == 0 ? Vh : Vl) + (size_t)(k0 + r) * QKVW + ch * 8;
                CP_ASYNC_16(dst, src);
            }
        }
        CP_COMMIT();
    };

    float acc[2][4][4] = {};
    int mi = lane >> 3, lr = lane & 7;
    int wm = (wid >> 1) * 32;
    int wn = (wid & 1) * 32;

    load_stage(0);

    for (int c = 0; c < NC; c++) {
        uint32_t st = sb + (c & 1) * AVSTAGE;
        if (c + 1 < NC) { load_stage(c + 1); CP_WAIT1(); }
        else            { CP_WAIT0(); }
        __syncthreads();

        #pragma unroll
        for (int s16 = 0; s16 < 2; s16++) {
            uint32_t ah[2][4], al[2][4], bh[2][4], bl[2][4];
            #pragma unroll
            for (int t = 0; t < 2; t++) {
                int row = wm + t * 16 + ((mi & 1) << 3) + lr;
                int ch  = s16 * 2 + (mi >> 1);
                ldsm4(ah[t], sw64(st,        row, ch));
                ldsm4(al[t], sw64(st + 8192, row, ch));
            }
            #pragma unroll
            for (int pp = 0; pp < 2; pp++) {
                int row = s16 * 16 + ((mi & 1) << 3) + lr;
                int chk = (wn + pp * 16 + ((mi >> 1) << 3)) >> 3;
                ldsm4t(bh[pp], sw128(st + 16384, row, chk));
                ldsm4t(bl[pp], sw128(st + 20480, row, chk));
            }
            #pragma unroll
            for (int tm = 0; tm < 2; tm++)
                #pragma unroll
                for (int tn = 0; tn < 4; tn++) {
                    uint32_t* BH = &bh[tn >> 1][(tn & 1) * 2];
                    uint32_t* BL = &bl[tn >> 1][(tn & 1) * 2];
                    mma_bf16(acc[tm][tn], ah[tm], BH);
                    mma_bf16(acc[tm][tn], ah[tm], BL);
                    mma_bf16(acc[tm][tn], al[tm], BH);
                }
        }
        __syncthreads();
    }

    // scatter epilogue: ao[(b*8+h)*1024 + n][p*64 + d], split bf16
    int g = lane >> 2, tc = lane & 3;
    size_t obase = (size_t)(b * 8 + h) * NSEQ;
    #pragma unroll
    for (int tm = 0; tm < 2; tm++) {
        #pragma unroll
        for (int tn = 0; tn < 4; tn++) {
            int n_ = row0 + wm + tm * 16 + g;
            int d_ = wn + tn * 8 + tc * 2;
            #pragma unroll
            for (int half = 0; half < 2; half++) {
                int nn = n_ + half * 8;
                float v0 = acc[tm][tn][half * 2 + 0];
                float v1 = acc[tm][tn][half * 2 + 1];
                size_t off = (obase + nn) * DIM + p * 64 + d_;
                bf16 h0, l0, h1, l1;
                split_bf16(v0, h0, l0); split_bf16(v1, h1, l1);
                *(__nv_bfloat162*)(aoh + off) = __nv_bfloat162(h0, h1);
                *(__nv_bfloat162*)(aol + off) = __nv_bfloat162(l0, l1);
            }
        }
    }
}

// ---------------------------------------------------------------------------
// Weight transpose + split: W[K,N] fp32 -> Th/Tl[N,K] bf16
// ---------------------------------------------------------------------------
__global__ void __launch_bounds__(256) tsplit_kernel(
    const float* __restrict__ W, bf16* __restrict__ Th, bf16* __restrict__ Tl,
    int K, int N)
{
    int id = blockIdx.x * 256 + threadIdx.x;
    if (id >= K * N) return;
    int n = id / K, k = id - n * K;
    float v = W[(size_t)k * N + n];
    bf16 h, l;
    split_bf16(v, h, l);
    Th[id] = h; Tl[id] = l;
}

// ---------------------------------------------------------------------------
// Reductions + LN + softmax
// ---------------------------------------------------------------------------
__device__ __forceinline__ float block_sum(float v, float* sm) {
    #pragma unroll
    for (int o = 16; o > 0; o >>= 1) v += __shfl_down_sync(0xffffffffu, v, o);
    int lane = threadIdx.x & 31, wid = threadIdx.x >> 5;
    if (lane == 0) sm[wid] = v;
    __syncthreads();
    v = (threadIdx.x < 8) ? sm[threadIdx.x] : 0.0f;
    if (wid == 0) {
        #pragma unroll
        for (int o = 4; o > 0; o >>= 1) v += __shfl_down_sync(0xffffffffu, v, o);
        if (lane == 0) sm[0] = v;
    }
    __syncthreads();
    float r = sm[0];
    __syncthreads();
    return r;
}
__device__ __forceinline__ float block_max(float v, float* sm) {
    #pragma unroll
    for (int o = 16; o > 0; o >>= 1) v = fmaxf(v, __shfl_down_sync(0xffffffffu, v, o));
    int lane = threadIdx.x & 31, wid = threadIdx.x >> 5;
    if (lane == 0) sm[wid] = v;
    __syncthreads();
    v = (threadIdx.x < 8) ? sm[threadIdx.x] : -INFINITY;
    if (wid == 0) {
        #pragma unroll
        for (int o = 4; o > 0; o >>= 1) v = fmaxf(v, __shfl_down_sync(0xffffffffu, v, o));
        if (lane == 0) sm[0] = v;
    }
    __syncthreads();
    float r = sm[0];
    __syncthreads();
    return r;
}

__global__ void __launch_bounds__(256) ln_kernel(
    const float* __restrict__ x,
    const float* __restrict__ w0, const float* __restrict__ b0,
    const float* __restrict__ w1, const float* __restrict__ b1,
    float* __restrict__ xn, bf16* __restrict__ hh, bf16* __restrict__ hl)
{
    __shared__ float sm[32];
    size_t row = blockIdx.x;
    const float* xr = x + row * DIM;
    int t = threadIdx.x;

    float v0 = xr[t], v1 = xr[t + 256];
    float mu = block_sum(v0 + v1, sm) * (1.0f / DIM);
    float d0 = v0 - mu, d1 = v1 - mu;
    float var = block_sum(d0 * d0 + d1 * d1, sm) * (1.0f / DIM);
    float r = rsqrtf(var + EPS);
    float y0 = d0 * r * w0[t] + b0[t];
    float y1 = d1 * r * w0[t + 256] + b0[t + 256];
    xn[row * DIM + t]       = y0;
    xn[row * DIM + t + 256] = y1;

    float mu2 = block_sum(y0 + y1, sm) * (1.0f / DIM);
    float e0 = y0 - mu2, e1 = y1 - mu2;
    float var2 = block_sum(e0 * e0 + e1 * e1, sm) * (1.0f / DIM);
    float r2 = rsqrtf(var2 + EPS);
    float h0 = e0 * r2 * w1[t] + b1[t];
    float h1 = e1 * r2 * w1[t + 256] + b1[t + 256];
    bf16 a, b;
    split_bf16(h0, a, b); hh[row * DIM + t] = a;       hl[row * DIM + t] = b;
    split_bf16(h1, a, b); hh[row * DIM + t + 256] = a; hl[row * DIM + t + 256] = b;
}

__global__ void __launch_bounds__(256) softmax_kernel(
    const float* __restrict__ scores, bf16* __restrict__ ath, bf16* __restrict__ atl)
{
    __shared__ float sm[32];
    size_t base = (size_t)blockIdx.x * NSEQ;
    const float* prow = scores + base;
    int t = threadIdx.x;
    float v[4];
    #pragma unroll
    for (int i = 0; i < 4; i++) v[i] = prow[t + i * 256];
    float m = fmaxf(fmaxf(v[0], v[1]), fmaxf(v[2], v[3]));
    m = block_max(m, sm);
    float s = 0.f;
    #pragma unroll
    for (int i = 0; i < 4; i++) { v[i] = __expf(v[i] - m); s += v[i]; }
    s = block_sum(s, sm);
    float inv = 1.0f / s;
    #pragma unroll
    for (int i = 0; i < 4; i++) {
        float a = v[i] * inv;
        bf16 h, l;
        split_bf16(a, h, l);
        ath[base + t + i * 256] = h;
        atl[base + t + i * 256] = l;
    }
}

// ---------------------------------------------------------------------------
// Launch
// ---------------------------------------------------------------------------
extern "C" void kernel_launch(void* const* d_in, const int* in_sizes, int n_in,
                              void* d_out, int out_size)
{
    (void)in_sizes; (void)n_in; (void)out_size;
    const float* x     = (const float*)d_in[0];
    const float* ln0_w = (const float*)d_in[1];
    const float* ln0_b = (const float*)d_in[2];
    const float* ln1_w = (const float*)d_in[3];
    const float* ln1_b = (const float*)d_in[4];
    const float* w_qkv = (const float*)d_in[5];
    const float* w_o   = (const float*)d_in[6];
    const float* b_o   = (const float*)d_in[7];
    const float* w1    = (const float*)d_in[8];
    const float* b1    = (const float*)d_in[9];
    const float* w2    = (const float*)d_in[10];
    const float* b2    = (const float*)d_in[11];
    float* out = (float*)d_out;

    void *p;
    cudaGetSymbolAddress(&p, g_xn);   float* xn   = (float*)p;
    cudaGetSymbolAddress(&p, g_hh);   bf16* hh    = (bf16*)p;
    cudaGetSymbolAddress(&p, g_hl);   bf16* hl    = (bf16*)p;
    cudaGetSymbolAddress(&p, g_qkvh); bf16* qkvh  = (bf16*)p;
    cudaGetSymbolAddress(&p, g_qkvl); bf16* qkvl  = (bf16*)p;
    cudaGetSymbolAddress(&p, g_sc);   float* sc   = (float*)p;
    cudaGetSymbolAddress(&p, g_ath);  bf16* ath   = (bf16*)p;
    cudaGetSymbolAddress(&p, g_atl);  bf16* atl   = (bf16*)p;
    cudaGetSymbolAddress(&p, g_aoh);  bf16* aoh   = (bf16*)p;
    cudaGetSymbolAddress(&p, g_aol);  bf16* aol   = (bf16*)p;
    cudaGetSymbolAddress(&p, g_x2);   float* x2   = (float*)p;
    cudaGetSymbolAddress(&p, g_x2h);  bf16* x2h   = (bf16*)p;
    cudaGetSymbolAddress(&p, g_x2l);  bf16* x2l   = (bf16*)p;
    cudaGetSymbolAddress(&p, g_midh); bf16* midh  = (bf16*)p;
    cudaGetSymbolAddress(&p, g_midl); bf16* midl  = (bf16*)p;
    cudaGetSymbolAddress(&p, g_wqkvt_h); bf16* wqkvt_h = (bf16*)p;
    cudaGetSymbolAddress(&p, g_wqkvt_l); bf16* wqkvt_l = (bf16*)p;
    cudaGetSymbolAddress(&p, g_wot_h);   bf16* wot_h   = (bf16*)p;
    cudaGetSymbolAddress(&p, g_wot_l);   bf16* wot_l   = (bf16*)p;
    cudaGetSymbolAddress(&p, g_w1t_h);   bf16* w1t_h   = (bf16*)p;
    cudaGetSymbolAddress(&p, g_w1t_l);   bf16* w1t_l   = (bf16*)p;
    cudaGetSymbolAddress(&p, g_w2t_h);   bf16* w2t_h   = (bf16*)p;
    cudaGetSymbolAddress(&p, g_w2t_l);   bf16* w2t_l   = (bf16*)p;

    cudaFuncSetAttribute(mma_gemm<1,0>, cudaFuncAttributeMaxDynamicSharedMemorySize, GSMEM);
    cudaFuncSetAttribute(mma_gemm<2,0>, cudaFuncAttributeMaxDynamicSharedMemorySize, GSMEM);
    cudaFuncSetAttribute(mma_gemm<3,0>, cudaFuncAttributeMaxDynamicSharedMemorySize, GSMEM);
    cudaFuncSetAttribute(mma_gemm<4,0>, cudaFuncAttributeMaxDynamicSharedMemorySize, GSMEM);
    cudaFuncSetAttribute(mma_gemm<5,1>, cudaFuncAttributeMaxDynamicSharedMemorySize, GSMEM);
    cudaFuncSetAttribute(av_mma,        cudaFuncAttributeMaxDynamicSharedMemorySize, AVSMEM);

    // weight prep
    tsplit_kernel<<<(DIM * QKVW + 255) / 256, 256>>>(w_qkv, wqkvt_h, wqkvt_l, DIM, QKVW);
    tsplit_kernel<<<(INNER * DIM + 255) / 256, 256>>>(w_o, wot_h, wot_l, INNER, DIM);
    tsplit_kernel<<<(DIM * HIDDEN + 255) / 256, 256>>>(w1, w1t_h, w1t_l, DIM, HIDDEN);
    tsplit_kernel<<<(HIDDEN * DIM + 255) / 256, 256>>>(w2, w2t_h, w2t_l, HIDDEN, DIM);

    // 1) LN0 + LN1
    ln_kernel<<<ROWS, 256>>>(x, ln0_w, ln0_b, ln1_w, ln1_b, xn, hh, hl);
    // 2) qkv = h @ w_qkv  (split out)
    mma_gemm<1,0><<<dim3(QKVW / 128, ROWS / 128), 256, GSMEM>>>(
        hh, hl, wqkvt_h, wqkvt_l, ROWS, QKVW, DIM, DIM, DIM,
        nullptr, nullptr, nullptr, qkvh, qkvl);
    // 3) scores = q @ k^T * scale
    mma_gemm<5,1><<<dim3(8, 8, NZ), 256, GSMEM>>>(
        qkvh, qkvl, qkvh, qkvl, NSEQ, NSEQ, 64, QKVW, QKVW,
        nullptr, nullptr, sc, nullptr, nullptr);
    // 4) softmax -> split attn
    softmax_kernel<<<NZ * NSEQ, 256>>>(sc, ath, atl);
    // 5) out = attn @ v, scattered (split out)
    av_mma<<<dim3(8, NZ), 256, AVSMEM>>>(ath, atl, qkvh, qkvl, aoh, aol);
    // 6) x2 = ao @ w_o + b_o + xn  (fp32 + split)
    mma_gemm<2,0><<<dim3(DIM / 128, ROWS / 128), 256, GSMEM>>>(
        aoh, aol, wot_h, wot_l, ROWS, DIM, INNER, INNER, INNER,
        b_o, xn, x2, x2h, x2l);
    // 7) mid = gelu(x2 @ w1 + b1)  (split out)
    mma_gemm<3,0><<<dim3(HIDDEN / 128, ROWS / 128), 256, GSMEM>>>(
        x2h, x2l, w1t_h, w1t_l, ROWS, HIDDEN, DIM, DIM, DIM,
        b1, nullptr, nullptr, midh, midl);
    // 8) out = mid @ w2 + b2 + x2  (fp32)
    mma_gemm<4,0><<<dim3(DIM / 128, ROWS / 128), 256, GSMEM>>>(
        midh, midl, w2t_h, w2t_l, ROWS, DIM, HIDDEN, HIDDEN, HIDDEN,
        b2, x2, out, nullptr, nullptr);
}

// round 4
// speedup vs baseline: 5.0646x; 1.2320x over previous
#include <cuda_runtime.h>
#include <cuda_bf16.h>
#include <cstdint>
#include <math.h>

// ---------------------------------------------------------------------------
// ViT transformer block. mma.sync split-bf16 3-pass GEMMs + fused flash attn.
// B=2, P=8, N=1024, DIM=512, HEADS=8, DIM_HEAD=64, INNER=512, HIDDEN=2048
// ---------------------------------------------------------------------------

#define ROWS   16384
#define DIM    512
#define INNER  512
#define QKVW   1536
#define HIDDEN 2048
#define NSEQ   1024
#define NZ     128
#define SCALE  0.125f
#define EPS    1e-5f

typedef __nv_bfloat16 bf16;

// ------------------------- device scratch ---------------------------------
__device__ __align__(256) float g_xn  [(size_t)ROWS * DIM];
__device__ __align__(256) bf16  g_hh  [(size_t)ROWS * DIM];
__device__ __align__(256) bf16  g_hl  [(size_t)ROWS * DIM];
__device__ __align__(256) bf16  g_qkvh[(size_t)ROWS * QKVW];
__device__ __align__(256) bf16  g_qkvl[(size_t)ROWS * QKVW];
__device__ __align__(256) bf16  g_aoh [(size_t)ROWS * DIM];
__device__ __align__(256) bf16  g_aol [(size_t)ROWS * DIM];
__device__ __align__(256) float g_x2  [(size_t)ROWS * DIM];
__device__ __align__(256) bf16  g_x2h [(size_t)ROWS * DIM];
__device__ __align__(256) bf16  g_x2l [(size_t)ROWS * DIM];
__device__ __align__(256) bf16  g_midh[(size_t)ROWS * HIDDEN];
__device__ __align__(256) bf16  g_midl[(size_t)ROWS * HIDDEN];
// transposed/split weights [N, K]
__device__ __align__(256) bf16  g_wqkvt_h[(size_t)QKVW * DIM];
__device__ __align__(256) bf16  g_wqkvt_l[(size_t)QKVW * DIM];
__device__ __align__(256) bf16  g_wot_h  [(size_t)DIM * INNER];
__device__ __align__(256) bf16  g_wot_l  [(size_t)DIM * INNER];
__device__ __align__(256) bf16  g_w1t_h  [(size_t)HIDDEN * DIM];
__device__ __align__(256) bf16  g_w1t_l  [(size_t)HIDDEN * DIM];
__device__ __align__(256) bf16  g_w2t_h  [(size_t)DIM * HIDDEN];
__device__ __align__(256) bf16  g_w2t_l  [(size_t)DIM * HIDDEN];

// ------------------------- PTX helpers ------------------------------------
__device__ __forceinline__ uint32_t smem_u32(const void* p) {
    uint32_t a;
    asm("{ .reg .u64 t; cvta.to.shared.u64 t, %1; cvt.u32.u64 %0, t; }"
        : "=r"(a) : "l"(p));
    return a;
}
#define CP_ASYNC_16(sa, ga) \
    asm volatile("cp.async.cg.shared.global [%0], [%1], 16;" \
                 :: "r"((uint32_t)(sa)), "l"(ga) : "memory")
#define CP_COMMIT() asm volatile("cp.async.commit_group;" ::: "memory")
#define CP_WAIT0()  asm volatile("cp.async.wait_group 0;" ::: "memory")
#define CP_WAIT1()  asm volatile("cp.async.wait_group 1;" ::: "memory")

__device__ __forceinline__ void ldsm4(uint32_t* r, uint32_t addr) {
    asm volatile("ldmatrix.sync.aligned.m8n8.x4.shared.b16 {%0,%1,%2,%3}, [%4];"
        : "=r"(r[0]), "=r"(r[1]), "=r"(r[2]), "=r"(r[3]) : "r"(addr));
}
__device__ __forceinline__ void ldsm4t(uint32_t* r, uint32_t addr) {
    asm volatile("ldmatrix.sync.aligned.m8n8.x4.trans.shared.b16 {%0,%1,%2,%3}, [%4];"
        : "=r"(r[0]), "=r"(r[1]), "=r"(r[2]), "=r"(r[3]) : "r"(addr));
}
__device__ __forceinline__ void mma_bf16(float* c, const uint32_t* a, const uint32_t* b) {
    asm volatile(
        "mma.sync.aligned.m16n8k16.row.col.f32.bf16.bf16.f32 "
        "{%0,%1,%2,%3}, {%4,%5,%6,%7}, {%8,%9}, {%0,%1,%2,%3};"
        : "+f"(c[0]), "+f"(c[1]), "+f"(c[2]), "+f"(c[3])
        : "r"(a[0]), "r"(a[1]), "r"(a[2]), "r"(a[3]), "r"(b[0]), "r"(b[1]));
}

__device__ __forceinline__ float gelu_f(float x) {
    return 0.5f * x * (1.0f + erff(x * 0.7071067811865475f));
}
__device__ __forceinline__ void split_bf16(float v, bf16& h, bf16& l) {
    h = __float2bfloat16(v);
    l = __float2bfloat16(v - __bfloat162float(h));
}

// swizzled smem addr for a 64B-row tile (rows x 32 bf16)
__device__ __forceinline__ uint32_t sw64(uint32_t base, int row, int chunk) {
    return base + row * 64 + ((chunk ^ ((row >> 1) & 3)) << 4);
}
// swizzled smem addr for a 128B-row tile (rows x 64 bf16)
__device__ __forceinline__ uint32_t sw128(uint32_t base, int row, int chunk) {
    return base + row * 128 + ((chunk ^ (row & 7)) << 4);
}

// ---------------------------------------------------------------------------
// Generic split-bf16 MMA GEMM: C[M,N] = A[M,K] @ Bt[N,K]^T
// BM=128, BN=128, BK=32. 8 warps (2x4), warp tile 64x32.
// EPI: 1 split-only; 2 fp32(acc+bias+res)+split; 3 split(gelu(acc+bias));
//      4 fp32(acc+bias+res)
// ---------------------------------------------------------------------------
#define GSTAGE 32768
#define GSMEM  (2 * GSTAGE)

template <int EPI>
__global__ void __launch_bounds__(256, 1) mma_gemm(
    const bf16* __restrict__ Ahi, const bf16* __restrict__ Alo,
    const bf16* __restrict__ Bhi, const bf16* __restrict__ Blo,
    int M, int N, int K, int lda, int ldb,
    const float* __restrict__ bias, const float* __restrict__ res,
    float* __restrict__ Cf, bf16* __restrict__ Chi, bf16* __restrict__ Clo)
{
    extern __shared__ char smem[];
    uint32_t sb = smem_u32(smem);
    int tid = threadIdx.x, wid = tid >> 5, lane = tid & 31;
    int row0 = blockIdx.y * 128, col0 = blockIdx.x * 128;

    const int NC = K >> 5;

    auto load_stage = [&](int c) {
        uint32_t st = sb + (c & 1) * GSTAGE;
        int k0 = c << 5;
        #pragma unroll
        for (int l = 0; l < 8; l++) {
            int idx = tid + l * 256;
            int mat = idx >> 9, r = (idx >> 2) & 127, ch = idx & 3;
            uint32_t dst = sw64(st + mat * 8192, r, ch);
            const bf16* src;
            if (mat == 0)      src = Ahi + (size_t)(row0 + r) * lda + k0 + ch * 8;
            else if (mat == 1) src = Alo + (size_t)(row0 + r) * lda + k0 + ch * 8;
            else if (mat == 2) src = Bhi + (size_t)(col0 + r) * ldb + k0 + ch * 8;
            else               src = Blo + (size_t)(col0 + r) * ldb + k0 + ch * 8;
            CP_ASYNC_16(dst, src);
        }
        CP_COMMIT();
    };

    float acc[4][4][4] = {};
    int mi = lane >> 3, lr = lane & 7;
    int wm = (wid >> 2) * 64;
    int wn = (wid & 3) * 32;

    load_stage(0);

    for (int c = 0; c < NC; c++) {
        uint32_t st = sb + (c & 1) * GSTAGE;
        if (c + 1 < NC) { load_stage(c + 1); CP_WAIT1(); }
        else            { CP_WAIT0(); }
        __syncthreads();

        #pragma unroll
        for (int s16 = 0; s16 < 2; s16++) {
            uint32_t ah[4][4], al[4][4], bh[2][4], bl[2][4];
            #pragma unroll
            for (int t = 0; t < 4; t++) {
                int row = wm + t * 16 + ((mi & 1) << 3) + lr;
                int ch  = s16 * 2 + (mi >> 1);
                ldsm4(ah[t], sw64(st,        row, ch));
                ldsm4(al[t], sw64(st + 8192, row, ch));
            }
            #pragma unroll
            for (int p = 0; p < 2; p++) {
                int row = wn + p * 16 + ((mi >> 1) << 3) + lr;
                int ch  = s16 * 2 + (mi & 1);
                ldsm4(bh[p], sw64(st + 16384, row, ch));
                ldsm4(bl[p], sw64(st + 24576, row, ch));
            }
            #pragma unroll
            for (int tm = 0; tm < 4; tm++)
                #pragma unroll
                for (int tn = 0; tn < 4; tn++) {
                    uint32_t* BH = &bh[tn >> 1][(tn & 1) * 2];
                    uint32_t* BL = &bl[tn >> 1][(tn & 1) * 2];
                    mma_bf16(acc[tm][tn], ah[tm], BH);
                    mma_bf16(acc[tm][tn], ah[tm], BL);
                    mma_bf16(acc[tm][tn], al[tm], BH);
                }
        }
        __syncthreads();
    }

    int g = lane >> 2, tc = lane & 3;
    #pragma unroll
    for (int tm = 0; tm < 4; tm++) {
        #pragma unroll
        for (int tn = 0; tn < 4; tn++) {
            int rr = row0 + wm + tm * 16 + g;
            int cc = col0 + wn + tn * 8 + tc * 2;
            #pragma unroll
            for (int half = 0; half < 2; half++) {
                int r_ = rr + half * 8;
                float v0 = acc[tm][tn][half * 2 + 0];
                float v1 = acc[tm][tn][half * 2 + 1];
                size_t off = (size_t)r_ * N + cc;
                if (EPI == 4 || EPI == 2) {
                    float2 b2 = *(const float2*)(bias + cc);
                    float2 r2 = *(const float2*)(res + off);
                    v0 += b2.x + r2.x; v1 += b2.y + r2.y;
                    *(float2*)(Cf + off) = make_float2(v0, v1);
                } else if (EPI == 3) {
                    float2 b2 = *(const float2*)(bias + cc);
                    v0 = gelu_f(v0 + b2.x); v1 = gelu_f(v1 + b2.y);
                }
                if (EPI == 1 || EPI == 2 || EPI == 3) {
                    bf16 h0, l0, h1, l1;
                    split_bf16(v0, h0, l0); split_bf16(v1, h1, l1);
                    *(__nv_bfloat162*)(Chi + off) = __nv_bfloat162(h0, h1);
                    *(__nv_bfloat162*)(Clo + off) = __nv_bfloat162(l0, l1);
                }
            }
        }
    }
}

// ---------------------------------------------------------------------------
// Fused flash attention. grid (8 q-blocks, 128 z). 8 warps, 16 q-rows/warp.
// Q tile 128x64 (hi/lo) resident; K/V tiles 64x64 (hi/lo) double-buffered.
// Online softmax in log2 domain; P split-bf16 in registers; scatter epilogue
// implements the buggy rearrange: ao[(b*8+h)*1024 + n][p*64 + d].
// ---------------------------------------------------------------------------
#define FA_SMEM 98304

__global__ void __launch_bounds__(256, 1) flash_kernel(
    const bf16* __restrict__ qkvh, const bf16* __restrict__ qkvl,
    bf16* __restrict__ aoh, bf16* __restrict__ aol)
{
    extern __shared__ char smem[];
    uint32_t sb = smem_u32(smem);
    int tid = threadIdx.x, wid = tid >> 5, lane = tid & 31;
    int mi = lane >> 3, lr = lane & 7;
    int g = lane >> 2, tc = lane & 3;
    int z = blockIdx.y;
    int b = z >> 6, h = (z >> 3) & 7, p = z & 7;
    int row0 = blockIdx.x * 128;
    size_t base = (size_t)((b * 8 + p)) * NSEQ * QKVW + h * 64;
    const bf16* Qh = qkvh + base;        const bf16* Ql = qkvl + base;
    const bf16* Kh = qkvh + base + 512;  const bf16* Kl = qkvl + base + 512;
    const bf16* Vh = qkvh + base + 1024; const bf16* Vl = qkvl + base + 1024;

    uint32_t qoff = sb;           // Qh 16KB, Ql 16KB
    uint32_t soff = sb + 32768;   // 2 stages x 32KB (Kh,Kl,Vh,Vl @ 8KB)

    // Q tile: 128 rows x 64 bf16 (128B rows, sw128), hi+lo
    #pragma unroll
    for (int l = 0; l < 8; l++) {
        int idx = tid + l * 256;
        int mat = idx >> 10, r = (idx >> 3) & 127, ch = idx & 7;
        const bf16* src = (mat == 0 ? Qh : Ql) + (size_t)(row0 + r) * QKVW + ch * 8;
        CP_ASYNC_16(sw128(qoff + mat * 16384, r, ch), src);
    }

    auto load_stage = [&](int c) {
        uint32_t st = soff + (c & 1) * 32768;
        int kv0 = c << 6;
        #pragma unroll
        for (int l = 0; l < 8; l++) {
            int idx = tid + l * 256;
            int mat = idx >> 9, r = (idx >> 3) & 63, ch = idx & 7;
            const bf16* src;
            if (mat == 0)      src = Kh + (size_t)(kv0 + r) * QKVW + ch * 8;
            else if (mat == 1) src = Kl + (size_t)(kv0 + r) * QKVW + ch * 8;
            else if (mat == 2) src = Vh + (size_t)(kv0 + r) * QKVW + ch * 8;
            else               src = Vl + (size_t)(kv0 + r) * QKVW + ch * 8;
            CP_ASYNC_16(sw128(st + mat * 8192, r, ch), src);
        }
        CP_COMMIT();
    };

    load_stage(0);   // commits {Q, stage0}
    load_stage(1);

    float m_r[2] = {-1e30f, -1e30f};
    float l_r[2] = {0.f, 0.f};
    float O[8][4] = {};
    int qr0 = wid * 16;
    const float LS = SCALE * 1.4426950408889634f;   // SCALE * log2(e)

    for (int c = 0; c < 16; c++) {
        if (c == 0)       { CP_WAIT1(); }
        else if (c < 15)  { load_stage(c + 1); CP_WAIT1(); }
        else              { CP_WAIT0(); }
        __syncthreads();

        uint32_t st = soff + (c & 1) * 32768;
        uint32_t kh_o = st, kl_o = st + 8192, vh_o = st + 16384, vl_o = st + 24576;

        // S = Q K^T  (16x64 per warp), 3 split passes
        float S[8][4] = {};
        #pragma unroll
        for (int ks = 0; ks < 4; ks++) {
            uint32_t ah[4], al[4];
            {
                int row = qr0 + ((mi & 1) << 3) + lr;
                int ch  = ks * 2 + (mi >> 1);
                ldsm4(ah, sw128(qoff,         row, ch));
                ldsm4(al, sw128(qoff + 16384, row, ch));
            }
            #pragma unroll
            for (int np = 0; np < 4; np++) {
                uint32_t bh[4], bl[4];
                int row = np * 16 + ((mi >> 1) << 3) + lr;
                int ch  = ks * 2 + (mi & 1);
                ldsm4(bh, sw128(kh_o, row, ch));
                ldsm4(bl, sw128(kl_o, row, ch));
                mma_bf16(S[np * 2],     ah, &bh[0]);
                mma_bf16(S[np * 2 + 1], ah, &bh[2]);
                mma_bf16(S[np * 2],     ah, &bl[0]);
                mma_bf16(S[np * 2 + 1], ah, &bl[2]);
                mma_bf16(S[np * 2],     al, &bh[0]);
                mma_bf16(S[np * 2 + 1], al, &bh[2]);
            }
        }

        // online softmax (log2 domain); rows live in lane groups of 4 (tc)
        #pragma unroll
        for (int hf = 0; hf < 2; hf++) {
            float mx = -1e30f;
            #pragma unroll
            for (int j = 0; j < 8; j++) {
                S[j][hf * 2]     *= LS;
                S[j][hf * 2 + 1] *= LS;
                mx = fmaxf(mx, fmaxf(S[j][hf * 2], S[j][hf * 2 + 1]));
            }
            mx = fmaxf(mx, __shfl_xor_sync(0xffffffffu, mx, 1));
            mx = fmaxf(mx, __shfl_xor_sync(0xffffffffu, mx, 2));
            float mnew = fmaxf(m_r[hf], mx);
            float alpha = exp2f(m_r[hf] - mnew);
            m_r[hf] = mnew;
            float s = 0.f;
            #pragma unroll
            for (int j = 0; j < 8; j++) {
                float p0 = exp2f(S[j][hf * 2]     - mnew);
                float p1 = exp2f(S[j][hf * 2 + 1] - mnew);
                S[j][hf * 2] = p0; S[j][hf * 2 + 1] = p1;
                s += p0 + p1;
            }
            s += __shfl_xor_sync(0xffffffffu, s, 1);
            s += __shfl_xor_sync(0xffffffffu, s, 2);
            l_r[hf] = l_r[hf] * alpha + s;
            #pragma unroll
            for (int j = 0; j < 8; j++) {
                O[j][hf * 2]     *= alpha;
                O[j][hf * 2 + 1] *= alpha;
            }
        }

        // pack P (C-frag -> A-frag correspondence), split hi/lo
        uint32_t ph[4][4], pl[4][4];
        #pragma unroll
        for (int s_ = 0; s_ < 4; s_++) {
            #pragma unroll
            for (int q4 = 0; q4 < 4; q4++) {
                int j  = s_ * 2 + (q4 >> 1);
                int k0 = (q4 & 1) * 2;
                bf16 h0, l0, h1, l1;
                split_bf16(S[j][k0],     h0, l0);
                split_bf16(S[j][k0 + 1], h1, l1);
                __nv_bfloat162 hh2(h0, h1), ll2(l0, l1);
                ph[s_][q4] = *(uint32_t*)&hh2;
                pl[s_][q4] = *(uint32_t*)&ll2;
            }
        }

        // O += P V  (3 split passes), V via ldmatrix.trans
        #pragma unroll
        for (int s_ = 0; s_ < 4; s_++) {
            #pragma unroll
            for (int dp = 0; dp < 4; dp++) {
                uint32_t vhh[4], vll[4];
                int row = s_ * 16 + ((mi & 1) << 3) + lr;
                int chk = dp * 2 + (mi >> 1);
                ldsm4t(vhh, sw128(vh_o, row, chk));
                ldsm4t(vll, sw128(vl_o, row, chk));
                mma_bf16(O[dp * 2],     ph[s_], &vhh[0]);
                mma_bf16(O[dp * 2 + 1], ph[s_], &vhh[2]);
                mma_bf16(O[dp * 2],     ph[s_], &vll[0]);
                mma_bf16(O[dp * 2 + 1], ph[s_], &vll[2]);
                mma_bf16(O[dp * 2],     pl[s_], &vhh[0]);
                mma_bf16(O[dp * 2 + 1], pl[s_], &vhh[2]);
            }
        }
        __syncthreads();
    }

    // epilogue: normalize, split, buggy-rearrange scatter
    float inv0 = 1.0f / l_r[0], inv1 = 1.0f / l_r[1];
    size_t obase = (size_t)(b * 8 + h) * NSEQ;
    #pragma unroll
    for (int dp = 0; dp < 8; dp++) {
        int d = dp * 8 + tc * 2;
        #pragma unroll
        for (int hf = 0; hf < 2; hf++) {
            float inv = hf ? inv1 : inv0;
            int n = row0 + qr0 + g + hf * 8;
            float v0 = O[dp][hf * 2]     * inv;
            float v1 = O[dp][hf * 2 + 1] * inv;
            size_t off = (obase + n) * DIM + p * 64 + d;
            bf16 h0, l0, h1, l1;
            split_bf16(v0, h0, l0); split_bf16(v1, h1, l1);
            *(__nv_bfloat162*)(aoh + off) = __nv_bfloat162(h0, h1);
            *(__nv_bfloat162*)(aol + off) = __nv_bfloat162(l0, l1);
        }
    }
}

// ---------------------------------------------------------------------------
// Weight transpose + split: W[K,N] fp32 -> Th/Tl[N,K] bf16
// ---------------------------------------------------------------------------
__global__ void __launch_bounds__(256) tsplit_kernel(
    const float* __restrict__ W, bf16* __restrict__ Th, bf16* __restrict__ Tl,
    int K, int N)
{
    int id = blockIdx.x * 256 + threadIdx.x;
    if (id >= K * N) return;
    int n = id / K, k = id - n * K;
    float v = W[(size_t)k * N + n];
    bf16 h, l;
    split_bf16(v, h, l);
    Th[id] = h; Tl[id] = l;
}

// ---------------------------------------------------------------------------
// LN0 + LN1
// ---------------------------------------------------------------------------
__device__ __forceinline__ float block_sum(float v, float* sm) {
    #pragma unroll
    for (int o = 16; o > 0; o >>= 1) v += __shfl_down_sync(0xffffffffu, v, o);
    int lane = threadIdx.x & 31, wid = threadIdx.x >> 5;
    if (lane == 0) sm[wid] = v;
    __syncthreads();
    v = (threadIdx.x < 8) ? sm[threadIdx.x] : 0.0f;
    if (wid == 0) {
        #pragma unroll
        for (int o = 4; o > 0; o >>= 1) v += __shfl_down_sync(0xffffffffu, v, o);
        if (lane == 0) sm[0] = v;
    }
    __syncthreads();
    float r = sm[0];
    __syncthreads();
    return r;
}

__global__ void __launch_bounds__(256) ln_kernel(
    const float* __restrict__ x,
    const float* __restrict__ w0, const float* __restrict__ b0,
    const float* __restrict__ w1, const float* __restrict__ b1,
    float* __restrict__ xn, bf16* __restrict__ hh, bf16* __restrict__ hl)
{
    __shared__ float sm[32];
    size_t row = blockIdx.x;
    const float* xr = x + row * DIM;
    int t = threadIdx.x;

    float v0 = xr[t], v1 = xr[t + 256];
    float mu = block_sum(v0 + v1, sm) * (1.0f / DIM);
    float d0 = v0 - mu, d1 = v1 - mu;
    float var = block_sum(d0 * d0 + d1 * d1, sm) * (1.0f / DIM);
    float r = rsqrtf(var + EPS);
    float y0 = d0 * r * w0[t] + b0[t];
    float y1 = d1 * r * w0[t + 256] + b0[t + 256];
    xn[row * DIM + t]       = y0;
    xn[row * DIM + t + 256] = y1;

    float mu2 = block_sum(y0 + y1, sm) * (1.0f / DIM);
    float e0 = y0 - mu2, e1 = y1 - mu2;
    float var2 = block_sum(e0 * e0 + e1 * e1, sm) * (1.0f / DIM);
    float r2 = rsqrtf(var2 + EPS);
    float h0 = e0 * r2 * w1[t] + b1[t];
    float h1 = e1 * r2 * w1[t + 256] + b1[t + 256];
    bf16 a, b;
    split_bf16(h0, a, b); hh[row * DIM + t] = a;       hl[row * DIM + t] = b;
    split_bf16(h1, a, b); hh[row * DIM + t + 256] = a; hl[row * DIM + t + 256] = b;
}

// ---------------------------------------------------------------------------
// Launch
// ---------------------------------------------------------------------------
extern "C" void kernel_launch(void* const* d_in, const int* in_sizes, int n_in,
                              void* d_out, int out_size)
{
    (void)in_sizes; (void)n_in; (void)out_size;
    const float* x     = (const float*)d_in[0];
    const float* ln0_w = (const float*)d_in[1];
    const float* ln0_b = (const float*)d_in[2];
    const float* ln1_w = (const float*)d_in[3];
    const float* ln1_b = (const float*)d_in[4];
    const float* w_qkv = (const float*)d_in[5];
    const float* w_o   = (const float*)d_in[6];
    const float* b_o   = (const float*)d_in[7];
    const float* w1    = (const float*)d_in[8];
    const float* b1    = (const float*)d_in[9];
    const float* w2    = (const float*)d_in[10];
    const float* b2    = (const float*)d_in[11];
    float* out = (float*)d_out;

    void *p;
    cudaGetSymbolAddress(&p, g_xn);   float* xn   = (float*)p;
    cudaGetSymbolAddress(&p, g_hh);   bf16* hh    = (bf16*)p;
    cudaGetSymbolAddress(&p, g_hl);   bf16* hl    = (bf16*)p;
    cudaGetSymbolAddress(&p, g_qkvh); bf16* qkvh  = (bf16*)p;
    cudaGetSymbolAddress(&p, g_qkvl); bf16* qkvl  = (bf16*)p;
    cudaGetSymbolAddress(&p, g_aoh);  bf16* aoh   = (bf16*)p;
    cudaGetSymbolAddress(&p, g_aol);  bf16* aol   = (bf16*)p;
    cudaGetSymbolAddress(&p, g_x2);   float* x2   = (float*)p;
    cudaGetSymbolAddress(&p, g_x2h);  bf16* x2h   = (bf16*)p;
    cudaGetSymbolAddress(&p, g_x2l);  bf16* x2l   = (bf16*)p;
    cudaGetSymbolAddress(&p, g_midh); bf16* midh  = (bf16*)p;
    cudaGetSymbolAddress(&p, g_midl); bf16* midl  = (bf16*)p;
    cudaGetSymbolAddress(&p, g_wqkvt_h); bf16* wqkvt_h = (bf16*)p;
    cudaGetSymbolAddress(&p, g_wqkvt_l); bf16* wqkvt_l = (bf16*)p;
    cudaGetSymbolAddress(&p, g_wot_h);   bf16* wot_h   = (bf16*)p;
    cudaGetSymbolAddress(&p, g_wot_l);   bf16* wot_l   = (bf16*)p;
    cudaGetSymbolAddress(&p, g_w1t_h);   bf16* w1t_h   = (bf16*)p;
    cudaGetSymbolAddress(&p, g_w1t_l);   bf16* w1t_l   = (bf16*)p;
    cudaGetSymbolAddress(&p, g_w2t_h);   bf16* w2t_h   = (bf16*)p;
    cudaGetSymbolAddress(&p, g_w2t_l);   bf16* w2t_l   = (bf16*)p;

    cudaFuncSetAttribute(mma_gemm<1>, cudaFuncAttributeMaxDynamicSharedMemorySize, GSMEM);
    cudaFuncSetAttribute(mma_gemm<2>, cudaFuncAttributeMaxDynamicSharedMemorySize, GSMEM);
    cudaFuncSetAttribute(mma_gemm<3>, cudaFuncAttributeMaxDynamicSharedMemorySize, GSMEM);
    cudaFuncSetAttribute(mma_gemm<4>, cudaFuncAttributeMaxDynamicSharedMemorySize, GSMEM);
    cudaFuncSetAttribute(flash_kernel, cudaFuncAttributeMaxDynamicSharedMemorySize, FA_SMEM);

    // weight prep
    tsplit_kernel<<<(DIM * QKVW + 255) / 256, 256>>>(w_qkv, wqkvt_h, wqkvt_l, DIM, QKVW);
    tsplit_kernel<<<(INNER * DIM + 255) / 256, 256>>>(w_o, wot_h, wot_l, INNER, DIM);
    tsplit_kernel<<<(DIM * HIDDEN + 255) / 256, 256>>>(w1, w1t_h, w1t_l, DIM, HIDDEN);
    tsplit_kernel<<<(HIDDEN * DIM + 255) / 256, 256>>>(w2, w2t_h, w2t_l, HIDDEN, DIM);

    // 1) LN0 + LN1
    ln_kernel<<<ROWS, 256>>>(x, ln0_w, ln0_b, ln1_w, ln1_b, xn, hh, hl);
    // 2) qkv = h @ w_qkv  (split out)
    mma_gemm<1><<<dim3(QKVW / 128, ROWS / 128), 256, GSMEM>>>(
        hh, hl, wqkvt_h, wqkvt_l, ROWS, QKVW, DIM, DIM, DIM,
        nullptr, nullptr, nullptr, qkvh, qkvl);
    // 3) fused attention
    flash_kernel<<<dim3(8, NZ), 256, FA_SMEM>>>(qkvh, qkvl, aoh, aol);
    // 4) x2 = ao @ w_o + b_o + xn  (fp32 + split)
    mma_gemm<2><<<dim3(DIM / 128, ROWS / 128), 256, GSMEM>>>(
        aoh, aol, wot_h, wot_l, ROWS, DIM, INNER, INNER, INNER,
        b_o, xn, x2, x2h, x2l);
    // 5) mid = gelu(x2 @ w1 + b1)  (split out)
    mma_gemm<3><<<dim3(HIDDEN / 128, ROWS / 128), 256, GSMEM>>>(
        x2h, x2l, w1t_h, w1t_l, ROWS, HIDDEN, DIM, DIM, DIM,
        b1, nullptr, nullptr, midh, midl);
    // 6) out = mid @ w2 + b2 + x2  (fp32)
    mma_gemm<4><<<dim3(DIM / 128, ROWS / 128), 256, GSMEM>>>(
        midh, midl, w2t_h, w2t_l, ROWS, DIM, HIDDEN, HIDDEN, HIDDEN,
        b2, x2, out, nullptr, nullptr);
}

// round 5
// speedup vs baseline: 6.9732x; 1.3769x over previous
#include <cuda_runtime.h>
#include <cuda_fp16.h>
#include <cstdint>
#include <math.h>

// ---------------------------------------------------------------------------
// ViT transformer block. fp16 2-pass one-sided-split mma.sync GEMMs
// (weights corrected hi+lo, activations hi-only) + fused flash attention
// (Q corrected hi+lo resident, K/V hi-only streamed, P split in registers).
// B=2, P=8, N=1024, DIM=512, HEADS=8, DIM_HEAD=64, INNER=512, HIDDEN=2048
// ---------------------------------------------------------------------------

#define ROWS   16384
#define DIM    512
#define INNER  512
#define QKVW   1536
#define HIDDEN 2048
#define NSEQ   1024
#define NZ     128
#define SCALE  0.125f
#define EPS    1e-5f

typedef __half fp16;

// ------------------------- device scratch ---------------------------------
__device__ __align__(256) float g_xn  [(size_t)ROWS * DIM];
__device__ __align__(256) fp16  g_hh  [(size_t)ROWS * DIM];
__device__ __align__(256) fp16  g_qkvh[(size_t)ROWS * QKVW];
__device__ __align__(256) fp16  g_qlo [(size_t)ROWS * 512];
__device__ __align__(256) fp16  g_aoh [(size_t)ROWS * DIM];
__device__ __align__(256) float g_x2  [(size_t)ROWS * DIM];
__device__ __align__(256) fp16  g_x2h [(size_t)ROWS * DIM];
__device__ __align__(256) fp16  g_midh[(size_t)ROWS * HIDDEN];
// transposed/split weights [N, K]
__device__ __align__(256) fp16  g_wqkvt_h[(size_t)QKVW * DIM];
__device__ __align__(256) fp16  g_wqkvt_l[(size_t)QKVW * DIM];
__device__ __align__(256) fp16  g_wot_h  [(size_t)DIM * INNER];
__device__ __align__(256) fp16  g_wot_l  [(size_t)DIM * INNER];
__device__ __align__(256) fp16  g_w1t_h  [(size_t)HIDDEN * DIM];
__device__ __align__(256) fp16  g_w1t_l  [(size_t)HIDDEN * DIM];
__device__ __align__(256) fp16  g_w2t_h  [(size_t)DIM * HIDDEN];
__device__ __align__(256) fp16  g_w2t_l  [(size_t)DIM * HIDDEN];

// ------------------------- PTX helpers ------------------------------------
__device__ __forceinline__ uint32_t smem_u32(const void* p) {
    uint32_t a;
    asm("{ .reg .u64 t; cvta.to.shared.u64 t, %1; cvt.u32.u64 %0, t; }"
        : "=r"(a) : "l"(p));
    return a;
}
#define CP_ASYNC_16(sa, ga) \
    asm volatile("cp.async.cg.shared.global [%0], [%1], 16;" \
                 :: "r"((uint32_t)(sa)), "l"(ga) : "memory")
#define CP_COMMIT() asm volatile("cp.async.commit_group;" ::: "memory")
#define CP_WAIT0()  asm volatile("cp.async.wait_group 0;" ::: "memory")
#define CP_WAIT1()  asm volatile("cp.async.wait_group 1;" ::: "memory")
#define CP_WAIT2()  asm volatile("cp.async.wait_group 2;" ::: "memory")

__device__ __forceinline__ void ldsm4(uint32_t* r, uint32_t addr) {
    asm volatile("ldmatrix.sync.aligned.m8n8.x4.shared.b16 {%0,%1,%2,%3}, [%4];"
        : "=r"(r[0]), "=r"(r[1]), "=r"(r[2]), "=r"(r[3]) : "r"(addr));
}
__device__ __forceinline__ void ldsm4t(uint32_t* r, uint32_t addr) {
    asm volatile("ldmatrix.sync.aligned.m8n8.x4.trans.shared.b16 {%0,%1,%2,%3}, [%4];"
        : "=r"(r[0]), "=r"(r[1]), "=r"(r[2]), "=r"(r[3]) : "r"(addr));
}
__device__ __forceinline__ void mma_fp16(float* c, const uint32_t* a, const uint32_t* b) {
    asm volatile(
        "mma.sync.aligned.m16n8k16.row.col.f32.f16.f16.f32 "
        "{%0,%1,%2,%3}, {%4,%5,%6,%7}, {%8,%9}, {%0,%1,%2,%3};"
        : "+f"(c[0]), "+f"(c[1]), "+f"(c[2]), "+f"(c[3])
        : "r"(a[0]), "r"(a[1]), "r"(a[2]), "r"(a[3]), "r"(b[0]), "r"(b[1]));
}

__device__ __forceinline__ float gelu_f(float x) {
    return 0.5f * x * (1.0f + erff(x * 0.7071067811865475f));
}
__device__ __forceinline__ void split_h(float v, fp16& h, fp16& l) {
    h = __float2half_rn(v);
    l = __float2half_rn(v - __half2float(h));
}
__device__ __forceinline__ uint32_t pack_h2(fp16 a, fp16 b) {
    __half2 t = __halves2half2(a, b);
    return *(uint32_t*)&t;
}

// swizzled smem addr for a 64B-row tile (rows x 32 fp16)
__device__ __forceinline__ uint32_t sw64(uint32_t base, int row, int chunk) {
    return base + row * 64 + ((chunk ^ ((row >> 1) & 3)) << 4);
}
// swizzled smem addr for a 128B-row tile (rows x 64 fp16)
__device__ __forceinline__ uint32_t sw128(uint32_t base, int row, int chunk) {
    return base + row * 128 + ((chunk ^ (row & 7)) << 4);
}

// ---------------------------------------------------------------------------
// 2-pass one-sided split GEMM: C[M,N] = A[M,K] @ Bt[N,K]^T
// A fp16 hi only; Bt hi+lo. acc = Ah*Bh + Ah*Bl.
// BM=128, BN=128, BK=32, 3-stage cp.async. 8 warps (2x4), warp tile 64x32.
// EPI: 1 hi out (+ q-lo out for cols<512); 2 fp32(acc+bias+res) + hi;
//      3 hi(gelu(acc+bias)); 4 fp32(acc+bias+res)
// ---------------------------------------------------------------------------
#define GSTAGE 24576
#define GSMEM  (3 * GSTAGE)

template <int EPI>
__global__ void __launch_bounds__(256, 1) mma_gemm(
    const fp16* __restrict__ Ahi,
    const fp16* __restrict__ Bhi, const fp16* __restrict__ Blo,
    int M, int N, int K, int lda, int ldb,
    const float* __restrict__ bias, const float* __restrict__ res,
    float* __restrict__ Cf, fp16* __restrict__ Chi, fp16* __restrict__ Clo)
{
    extern __shared__ char smem[];
    uint32_t sb = smem_u32(smem);
    int tid = threadIdx.x, wid = tid >> 5, lane = tid & 31;
    int row0 = blockIdx.y * 128, col0 = blockIdx.x * 128;

    const int NC = K >> 5;

    auto load_stage = [&](int c) {
        uint32_t st = sb + (c % 3) * GSTAGE;
        int k0 = c << 5;
        #pragma unroll
        for (int l = 0; l < 6; l++) {
            int idx = tid + l * 256;        // 1536 chunks of 16B
            int mat = idx >> 9, r = (idx >> 2) & 127, ch = idx & 3;
            uint32_t dst = sw64(st + mat * 8192, r, ch);
            const fp16* src;
            if (mat == 0)      src = Ahi + (size_t)(row0 + r) * lda + k0 + ch * 8;
            else if (mat == 1) src = Bhi + (size_t)(col0 + r) * ldb + k0 + ch * 8;
            else               src = Blo + (size_t)(col0 + r) * ldb + k0 + ch * 8;
            CP_ASYNC_16(dst, src);
        }
        CP_COMMIT();
    };

    float acc[4][4][4] = {};
    int mi = lane >> 3, lr = lane & 7;
    int wm = (wid >> 2) * 64;
    int wn = (wid & 3) * 32;

    load_stage(0);
    load_stage(1);

    for (int c = 0; c < NC; c++) {
        uint32_t st = sb + (c % 3) * GSTAGE;
        if (c + 2 < NC)      { load_stage(c + 2); CP_WAIT2(); }
        else if (c + 1 < NC) { CP_WAIT1(); }
        else                 { CP_WAIT0(); }
        __syncthreads();

        #pragma unroll
        for (int s16 = 0; s16 < 2; s16++) {
            uint32_t ah[4][4], bh[2][4], bl[2][4];
            #pragma unroll
            for (int t = 0; t < 4; t++) {
                int row = wm + t * 16 + ((mi & 1) << 3) + lr;
                int ch  = s16 * 2 + (mi >> 1);
                ldsm4(ah[t], sw64(st, row, ch));
            }
            #pragma unroll
            for (int p = 0; p < 2; p++) {
                int row = wn + p * 16 + ((mi >> 1) << 3) + lr;
                int ch  = s16 * 2 + (mi & 1);
                ldsm4(bh[p], sw64(st + 8192,  row, ch));
                ldsm4(bl[p], sw64(st + 16384, row, ch));
            }
            #pragma unroll
            for (int tm = 0; tm < 4; tm++)
                #pragma unroll
                for (int tn = 0; tn < 4; tn++) {
                    uint32_t* BH = &bh[tn >> 1][(tn & 1) * 2];
                    uint32_t* BL = &bl[tn >> 1][(tn & 1) * 2];
                    mma_fp16(acc[tm][tn], ah[tm], BH);
                    mma_fp16(acc[tm][tn], ah[tm], BL);
                }
        }
        __syncthreads();
    }

    int g = lane >> 2, tc = lane & 3;
    #pragma unroll
    for (int tm = 0; tm < 4; tm++) {
        #pragma unroll
        for (int tn = 0; tn < 4; tn++) {
            int rr = row0 + wm + tm * 16 + g;
            int cc = col0 + wn + tn * 8 + tc * 2;
            #pragma unroll
            for (int half_ = 0; half_ < 2; half_++) {
                int r_ = rr + half_ * 8;
                float v0 = acc[tm][tn][half_ * 2 + 0];
                float v1 = acc[tm][tn][half_ * 2 + 1];
                size_t off = (size_t)r_ * N + cc;
                if (EPI == 2 || EPI == 4) {
                    float2 b2 = *(const float2*)(bias + cc);
                    float2 r2 = *(const float2*)(res + off);
                    v0 += b2.x + r2.x; v1 += b2.y + r2.y;
                    *(float2*)(Cf + off) = make_float2(v0, v1);
                } else if (EPI == 3) {
                    float2 b2 = *(const float2*)(bias + cc);
                    v0 = gelu_f(v0 + b2.x); v1 = gelu_f(v1 + b2.y);
                }
                if (EPI == 1) {
                    fp16 h0, l0, h1, l1;
                    split_h(v0, h0, l0); split_h(v1, h1, l1);
                    *(uint32_t*)(Chi + off) = pack_h2(h0, h1);
                    if (cc < 512)   // q columns: store lo for flash correction
                        *(uint32_t*)(Clo + (size_t)r_ * 512 + cc) = pack_h2(l0, l1);
                } else if (EPI == 2 || EPI == 3) {
                    *(uint32_t*)(Chi + off) =
                        pack_h2(__float2half_rn(v0), __float2half_rn(v1));
                }
            }
        }
    }
}

// ---------------------------------------------------------------------------
// Fused flash attention. grid (8 q-blocks, 128 z). 8 warps, 16 q-rows/warp.
// Q hi+lo resident (32KB); K/V hi-only 64x64 tiles double-buffered (16KB/stage).
// S = Qh*Kh + Ql*Kh (2-pass); online softmax (log2); P split in registers;
// O += Ph*Vh + Pl*Vh. Scatter epilogue: ao[(b*8+h)*1024 + n][p*64 + d], hi only.
// ---------------------------------------------------------------------------
#define FA_SMEM 65536

__global__ void __launch_bounds__(256, 1) flash_kernel(
    const fp16* __restrict__ qkvh, const fp16* __restrict__ qlo,
    fp16* __restrict__ aoh)
{
    extern __shared__ char smem[];
    uint32_t sb = smem_u32(smem);
    int tid = threadIdx.x, wid = tid >> 5, lane = tid & 31;
    int mi = lane >> 3, lr = lane & 7;
    int g = lane >> 2, tc = lane & 3;
    int z = blockIdx.y;
    int b = z >> 6, h = (z >> 3) & 7, p = z & 7;
    int row0 = blockIdx.x * 128;
    size_t base = (size_t)((b * 8 + p)) * NSEQ * QKVW + h * 64;
    const fp16* Qh = qkvh + base;
    const fp16* Ql = qlo + (size_t)((b * 8 + p)) * NSEQ * 512 + h * 64;
    const fp16* Kh = qkvh + base + 512;
    const fp16* Vh = qkvh + base + 1024;

    uint32_t qoff = sb;           // Qh 16KB, Ql 16KB
    uint32_t soff = sb + 32768;   // 2 stages x 16KB (Kh, Vh @ 8KB)

    // Q tiles: 128 rows x 64 fp16 (128B rows, sw128), hi + lo
    #pragma unroll
    for (int l = 0; l < 8; l++) {
        int idx = tid + l * 256;
        int mat = idx >> 10, r = (idx >> 3) & 127, ch = idx & 7;
        const fp16* src = mat == 0 ? Qh + (size_t)(row0 + r) * QKVW + ch * 8
                                   : Ql + (size_t)(row0 + r) * 512  + ch * 8;
        CP_ASYNC_16(sw128(qoff + mat * 16384, r, ch), src);
    }

    auto load_stage = [&](int c) {
        uint32_t st = soff + (c & 1) * 16384;
        int kv0 = c << 6;
        #pragma unroll
        for (int l = 0; l < 4; l++) {
            int idx = tid + l * 256;
            int mat = idx >> 9, r = (idx >> 3) & 63, ch = idx & 7;
            const fp16* src = (mat == 0 ? Kh : Vh) + (size_t)(kv0 + r) * QKVW + ch * 8;
            CP_ASYNC_16(sw128(st + mat * 8192, r, ch), src);
        }
        CP_COMMIT();
    };

    load_stage(0);   // commits {Q, stage0}
    load_stage(1);

    float m_r[2] = {-1e30f, -1e30f};
    float l_r[2] = {0.f, 0.f};
    float O[8][4] = {};
    int qr0 = wid * 16;
    const float LS = SCALE * 1.4426950408889634f;   // SCALE * log2(e)

    for (int c = 0; c < 16; c++) {
        if (c == 0)       { CP_WAIT1(); }
        else if (c < 15)  { load_stage(c + 1); CP_WAIT1(); }
        else              { CP_WAIT0(); }
        __syncthreads();

        uint32_t st = soff + (c & 1) * 16384;
        uint32_t kh_o = st, vh_o = st + 8192;

        // S = Q K^T  (16x64 per warp), 2-pass (Q corrected)
        float S[8][4] = {};
        #pragma unroll
        for (int ks = 0; ks < 4; ks++) {
            uint32_t ah[4], al[4];
            {
                int row = qr0 + ((mi & 1) << 3) + lr;
                int ch  = ks * 2 + (mi >> 1);
                ldsm4(ah, sw128(qoff,         row, ch));
                ldsm4(al, sw128(qoff + 16384, row, ch));
            }
            #pragma unroll
            for (int np = 0; np < 4; np++) {
                uint32_t bh[4];
                int row = np * 16 + ((mi >> 1) << 3) + lr;
                int ch  = ks * 2 + (mi & 1);
                ldsm4(bh, sw128(kh_o, row, ch));
                mma_fp16(S[np * 2],     ah, &bh[0]);
                mma_fp16(S[np * 2 + 1], ah, &bh[2]);
                mma_fp16(S[np * 2],     al, &bh[0]);
                mma_fp16(S[np * 2 + 1], al, &bh[2]);
            }
        }

        // online softmax (log2 domain)
        #pragma unroll
        for (int hf = 0; hf < 2; hf++) {
            float mx = -1e30f;
            #pragma unroll
            for (int j = 0; j < 8; j++) {
                S[j][hf * 2]     *= LS;
                S[j][hf * 2 + 1] *= LS;
                mx = fmaxf(mx, fmaxf(S[j][hf * 2], S[j][hf * 2 + 1]));
            }
            mx = fmaxf(mx, __shfl_xor_sync(0xffffffffu, mx, 1));
            mx = fmaxf(mx, __shfl_xor_sync(0xffffffffu, mx, 2));
            float mnew = fmaxf(m_r[hf], mx);
            float alpha = exp2f(m_r[hf] - mnew);
            m_r[hf] = mnew;
            float s = 0.f;
            #pragma unroll
            for (int j = 0; j < 8; j++) {
                float p0 = exp2f(S[j][hf * 2]     - mnew);
                float p1 = exp2f(S[j][hf * 2 + 1] - mnew);
                S[j][hf * 2] = p0; S[j][hf * 2 + 1] = p1;
                s += p0 + p1;
            }
            s += __shfl_xor_sync(0xffffffffu, s, 1);
            s += __shfl_xor_sync(0xffffffffu, s, 2);
            l_r[hf] = l_r[hf] * alpha + s;
            #pragma unroll
            for (int j = 0; j < 8; j++) {
                O[j][hf * 2]     *= alpha;
                O[j][hf * 2 + 1] *= alpha;
            }
        }

        // pack P (C-frag -> A-frag), split hi/lo in registers
        uint32_t ph[4][4], pl[4][4];
        #pragma unroll
        for (int s_ = 0; s_ < 4; s_++) {
            #pragma unroll
            for (int q4 = 0; q4 < 4; q4++) {
                int j  = s_ * 2 + (q4 >> 1);
                int k0 = (q4 & 1) * 2;
                fp16 h0, l0, h1, l1;
                split_h(S[j][k0],     h0, l0);
                split_h(S[j][k0 + 1], h1, l1);
                ph[s_][q4] = pack_h2(h0, h1);
                pl[s_][q4] = pack_h2(l0, l1);
            }
        }

        // O += P V  (2-pass, P corrected), V via ldmatrix.trans
        #pragma unroll
        for (int s_ = 0; s_ < 4; s_++) {
            #pragma unroll
            for (int dp = 0; dp < 4; dp++) {
                uint32_t vhh[4];
                int row = s_ * 16 + ((mi & 1) << 3) + lr;
                int chk = dp * 2 + (mi >> 1);
                ldsm4t(vhh, sw128(vh_o, row, chk));
                mma_fp16(O[dp * 2],     ph[s_], &vhh[0]);
                mma_fp16(O[dp * 2 + 1], ph[s_], &vhh[2]);
                mma_fp16(O[dp * 2],     pl[s_], &vhh[0]);
                mma_fp16(O[dp * 2 + 1], pl[s_], &vhh[2]);
            }
        }
        __syncthreads();
    }

    // epilogue: normalize, buggy-rearrange scatter (hi only)
    float inv0 = 1.0f / l_r[0], inv1 = 1.0f / l_r[1];
    size_t obase = (size_t)(b * 8 + h) * NSEQ;
    #pragma unroll
    for (int dp = 0; dp < 8; dp++) {
        int d = dp * 8 + tc * 2;
        #pragma unroll
        for (int hf = 0; hf < 2; hf++) {
            float inv = hf ? inv1 : inv0;
            int n = row0 + qr0 + g + hf * 8;
            float v0 = O[dp][hf * 2]     * inv;
            float v1 = O[dp][hf * 2 + 1] * inv;
            size_t off = (obase + n) * DIM + p * 64 + d;
            *(uint32_t*)(aoh + off) =
                pack_h2(__float2half_rn(v0), __float2half_rn(v1));
        }
    }
}

// ---------------------------------------------------------------------------
// Weight transpose + split: W[K,N] fp32 -> Th/Tl[N,K] fp16
// ---------------------------------------------------------------------------
__global__ void __launch_bounds__(256) tsplit_kernel(
    const float* __restrict__ W, fp16* __restrict__ Th, fp16* __restrict__ Tl,
    int K, int N)
{
    int id = blockIdx.x * 256 + threadIdx.x;
    if (id >= K * N) return;
    int n = id / K, k = id - n * K;
    float v = W[(size_t)k * N + n];
    fp16 h, l;
    split_h(v, h, l);
    Th[id] = h; Tl[id] = l;
}

// ---------------------------------------------------------------------------
// LN0 + LN1
// ---------------------------------------------------------------------------
__device__ __forceinline__ float block_sum(float v, float* sm) {
    #pragma unroll
    for (int o = 16; o > 0; o >>= 1) v += __shfl_down_sync(0xffffffffu, v, o);
    int lane = threadIdx.x & 31, wid = threadIdx.x >> 5;
    if (lane == 0) sm[wid] = v;
    __syncthreads();
    v = (threadIdx.x < 8) ? sm[threadIdx.x] : 0.0f;
    if (wid == 0) {
        #pragma unroll
        for (int o = 4; o > 0; o >>= 1) v += __shfl_down_sync(0xffffffffu, v, o);
        if (lane == 0) sm[0] = v;
    }
    __syncthreads();
    float r = sm[0];
    __syncthreads();
    return r;
}

__global__ void __launch_bounds__(256) ln_kernel(
    const float* __restrict__ x,
    const float* __restrict__ w0, const float* __restrict__ b0,
    const float* __restrict__ w1, const float* __restrict__ b1,
    float* __restrict__ xn, fp16* __restrict__ hh)
{
    __shared__ float sm[32];
    size_t row = blockIdx.x;
    const float* xr = x + row * DIM;
    int t = threadIdx.x;

    float v0 = xr[t], v1 = xr[t + 256];
    float mu = block_sum(v0 + v1, sm) * (1.0f / DIM);
    float d0 = v0 - mu, d1 = v1 - mu;
    float var = block_sum(d0 * d0 + d1 * d1, sm) * (1.0f / DIM);
    float r = rsqrtf(var + EPS);
    float y0 = d0 * r * w0[t] + b0[t];
    float y1 = d1 * r * w0[t + 256] + b0[t + 256];
    xn[row * DIM + t]       = y0;
    xn[row * DIM + t + 256] = y1;

    float mu2 = block_sum(y0 + y1, sm) * (1.0f / DIM);
    float e0 = y0 - mu2, e1 = y1 - mu2;
    float var2 = block_sum(e0 * e0 + e1 * e1, sm) * (1.0f / DIM);
    float r2 = rsqrtf(var2 + EPS);
    hh[row * DIM + t]       = __float2half_rn(e0 * r2 * w1[t] + b1[t]);
    hh[row * DIM + t + 256] = __float2half_rn(e1 * r2 * w1[t + 256] + b1[t + 256]);
}

// ---------------------------------------------------------------------------
// Launch
// ---------------------------------------------------------------------------
extern "C" void kernel_launch(void* const* d_in, const int* in_sizes, int n_in,
                              void* d_out, int out_size)
{
    (void)in_sizes; (void)n_in; (void)out_size;
    const float* x     = (const float*)d_in[0];
    const float* ln0_w = (const float*)d_in[1];
    const float* ln0_b = (const float*)d_in[2];
    const float* ln1_w = (const float*)d_in[3];
    const float* ln1_b = (const float*)d_in[4];
    const float* w_qkv = (const float*)d_in[5];
    const float* w_o   = (const float*)d_in[6];
    const float* b_o   = (const float*)d_in[7];
    const float* w1    = (const float*)d_in[8];
    const float* b1    = (const float*)d_in[9];
    const float* w2    = (const float*)d_in[10];
    const float* b2    = (const float*)d_in[11];
    float* out = (float*)d_out;

    void *p;
    cudaGetSymbolAddress(&p, g_xn);   float* xn   = (float*)p;
    cudaGetSymbolAddress(&p, g_hh);   fp16* hh    = (fp16*)p;
    cudaGetSymbolAddress(&p, g_qkvh); fp16* qkvh  = (fp16*)p;
    cudaGetSymbolAddress(&p, g_qlo);  fp16* qlo   = (fp16*)p;
    cudaGetSymbolAddress(&p, g_aoh);  fp16* aoh   = (fp16*)p;
    cudaGetSymbolAddress(&p, g_x2);   float* x2   = (float*)p;
    cudaGetSymbolAddress(&p, g_x2h);  fp16* x2h   = (fp16*)p;
    cudaGetSymbolAddress(&p, g_midh); fp16* midh  = (fp16*)p;
    cudaGetSymbolAddress(&p, g_wqkvt_h); fp16* wqkvt_h = (fp16*)p;
    cudaGetSymbolAddress(&p, g_wqkvt_l); fp16* wqkvt_l = (fp16*)p;
    cudaGetSymbolAddress(&p, g_wot_h);   fp16* wot_h   = (fp16*)p;
    cudaGetSymbolAddress(&p, g_wot_l);   fp16* wot_l   = (fp16*)p;
    cudaGetSymbolAddress(&p, g_w1t_h);   fp16* w1t_h   = (fp16*)p;
    cudaGetSymbolAddress(&p, g_w1t_l);   fp16* w1t_l   = (fp16*)p;
    cudaGetSymbolAddress(&p, g_w2t_h);   fp16* w2t_h   = (fp16*)p;
    cudaGetSymbolAddress(&p, g_w2t_l);   fp16* w2t_l   = (fp16*)p;

    cudaFuncSetAttribute(mma_gemm<1>, cudaFuncAttributeMaxDynamicSharedMemorySize, GSMEM);
    cudaFuncSetAttribute(mma_gemm<2>, cudaFuncAttributeMaxDynamicSharedMemorySize, GSMEM);
    cudaFuncSetAttribute(mma_gemm<3>, cudaFuncAttributeMaxDynamicSharedMemorySize, GSMEM);
    cudaFuncSetAttribute(mma_gemm<4>, cudaFuncAttributeMaxDynamicSharedMemorySize, GSMEM);
    cudaFuncSetAttribute(flash_kernel, cudaFuncAttributeMaxDynamicSharedMemorySize, FA_SMEM);

    // weight prep
    tsplit_kernel<<<(DIM * QKVW + 255) / 256, 256>>>(w_qkv, wqkvt_h, wqkvt_l, DIM, QKVW);
    tsplit_kernel<<<(INNER * DIM + 255) / 256, 256>>>(w_o, wot_h, wot_l, INNER, DIM);
    tsplit_kernel<<<(DIM * HIDDEN + 255) / 256, 256>>>(w1, w1t_h, w1t_l, DIM, HIDDEN);
    tsplit_kernel<<<(HIDDEN * DIM + 255) / 256, 256>>>(w2, w2t_h, w2t_l, HIDDEN, DIM);

    // 1) LN0 + LN1
    ln_kernel<<<ROWS, 256>>>(x, ln0_w, ln0_b, ln1_w, ln1_b, xn, hh);
    // 2) qkv = h @ w_qkv  (hi out; q-lo out)
    mma_gemm<1><<<dim3(QKVW / 128, ROWS / 128), 256, GSMEM>>>(
        hh, wqkvt_h, wqkvt_l, ROWS, QKVW, DIM, DIM, DIM,
        nullptr, nullptr, nullptr, qkvh, qlo);
    // 3) fused attention
    flash_kernel<<<dim3(8, NZ), 256, FA_SMEM>>>(qkvh, qlo, aoh);
    // 4) x2 = ao @ w_o + b_o + xn  (fp32 + hi)
    mma_gemm<2><<<dim3(DIM / 128, ROWS / 128), 256, GSMEM>>>(
        aoh, wot_h, wot_l, ROWS, DIM, INNER, INNER, INNER,
        b_o, xn, x2, x2h, nullptr);
    // 5) mid = gelu(x2 @ w1 + b1)  (hi out)
    mma_gemm<3><<<dim3(HIDDEN / 128, ROWS / 128), 256, GSMEM>>>(
        x2h, w1t_h, w1t_l, ROWS, HIDDEN, DIM, DIM, DIM,
        b1, nullptr, nullptr, midh, nullptr);
    // 6) out = mid @ w2 + b2 + x2  (fp32)
    mma_gemm<4><<<dim3(DIM / 128, ROWS / 128), 256, GSMEM>>>(
        midh, w2t_h, w2t_l, ROWS, DIM, HIDDEN, HIDDEN, HIDDEN,
        b2, x2, out, nullptr, nullptr);
}

// round 6
// speedup vs baseline: 9.1195x; 1.3078x over previous
#include <cuda_runtime.h>
#include <cuda_fp16.h>
#include <cstdint>
#include <math.h>

// ---------------------------------------------------------------------------
// ViT transformer block. fp16 single-pass dense GEMMs (weights hi-only),
// flash attention with Q/P hi+lo correction (2-pass QK & PV).
// B=2, P=8, N=1024, DIM=512, HEADS=8, DIM_HEAD=64, INNER=512, HIDDEN=2048
// ---------------------------------------------------------------------------

#define ROWS   16384
#define DIM    512
#define INNER  512
#define QKVW   1536
#define HIDDEN 2048
#define NSEQ   1024
#define NZ     128
#define SCALE  0.125f
#define EPS    1e-5f

typedef __half fp16;

// ------------------------- device scratch ---------------------------------
__device__ __align__(256) float g_xn  [(size_t)ROWS * DIM];
__device__ __align__(256) fp16  g_hh  [(size_t)ROWS * DIM];
__device__ __align__(256) fp16  g_qkvh[(size_t)ROWS * QKVW];
__device__ __align__(256) fp16  g_qlo [(size_t)ROWS * 512];
__device__ __align__(256) fp16  g_aoh [(size_t)ROWS * DIM];
__device__ __align__(256) float g_x2  [(size_t)ROWS * DIM];
__device__ __align__(256) fp16  g_x2h [(size_t)ROWS * DIM];
__device__ __align__(256) fp16  g_midh[(size_t)ROWS * HIDDEN];
// transposed weights [N, K], fp16 hi
__device__ __align__(256) fp16  g_wqkvt[(size_t)QKVW * DIM];
__device__ __align__(256) fp16  g_wot  [(size_t)DIM * INNER];
__device__ __align__(256) fp16  g_w1t  [(size_t)HIDDEN * DIM];
__device__ __align__(256) fp16  g_w2t  [(size_t)DIM * HIDDEN];

// ------------------------- PTX helpers ------------------------------------
__device__ __forceinline__ uint32_t smem_u32(const void* p) {
    uint32_t a;
    asm("{ .reg .u64 t; cvta.to.shared.u64 t, %1; cvt.u32.u64 %0, t; }"
        : "=r"(a) : "l"(p));
    return a;
}
#define CP_ASYNC_16(sa, ga) \
    asm volatile("cp.async.cg.shared.global [%0], [%1], 16;" \
                 :: "r"((uint32_t)(sa)), "l"(ga) : "memory")
#define CP_COMMIT() asm volatile("cp.async.commit_group;" ::: "memory")
#define CP_WAIT0()  asm volatile("cp.async.wait_group 0;" ::: "memory")
#define CP_WAIT1()  asm volatile("cp.async.wait_group 1;" ::: "memory")
#define CP_WAIT2()  asm volatile("cp.async.wait_group 2;" ::: "memory")
#define CP_WAIT3()  asm volatile("cp.async.wait_group 3;" ::: "memory")

__device__ __forceinline__ void ldsm4(uint32_t* r, uint32_t addr) {
    asm volatile("ldmatrix.sync.aligned.m8n8.x4.shared.b16 {%0,%1,%2,%3}, [%4];"
        : "=r"(r[0]), "=r"(r[1]), "=r"(r[2]), "=r"(r[3]) : "r"(addr));
}
__device__ __forceinline__ void ldsm4t(uint32_t* r, uint32_t addr) {
    asm volatile("ldmatrix.sync.aligned.m8n8.x4.trans.shared.b16 {%0,%1,%2,%3}, [%4];"
        : "=r"(r[0]), "=r"(r[1]), "=r"(r[2]), "=r"(r[3]) : "r"(addr));
}
__device__ __forceinline__ void mma_fp16(float* c, const uint32_t* a, const uint32_t* b) {
    asm volatile(
        "mma.sync.aligned.m16n8k16.row.col.f32.f16.f16.f32 "
        "{%0,%1,%2,%3}, {%4,%5,%6,%7}, {%8,%9}, {%0,%1,%2,%3};"
        : "+f"(c[0]), "+f"(c[1]), "+f"(c[2]), "+f"(c[3])
        : "r"(a[0]), "r"(a[1]), "r"(a[2]), "r"(a[3]), "r"(b[0]), "r"(b[1]));
}

__device__ __forceinline__ float gelu_f(float x) {
    return 0.5f * x * (1.0f + erff(x * 0.7071067811865475f));
}
__device__ __forceinline__ void split_h(float v, fp16& h, fp16& l) {
    h = __float2half_rn(v);
    l = __float2half_rn(v - __half2float(h));
}
__device__ __forceinline__ uint32_t pack_h2(fp16 a, fp16 b) {
    __half2 t = __halves2half2(a, b);
    return *(uint32_t*)&t;
}

// swizzled smem addr for a 64B-row tile (rows x 32 fp16)
__device__ __forceinline__ uint32_t sw64(uint32_t base, int row, int chunk) {
    return base + row * 64 + ((chunk ^ ((row >> 1) & 3)) << 4);
}
// swizzled smem addr for a 128B-row tile (rows x 64 fp16)
__device__ __forceinline__ uint32_t sw128(uint32_t base, int row, int chunk) {
    return base + row * 128 + ((chunk ^ (row & 7)) << 4);
}

// ---------------------------------------------------------------------------
// Single-pass fp16 GEMM: C[M,N] = A[M,K] @ Bt[N,K]^T
// BM=128, BN=128, BK=32, 4-stage cp.async. 8 warps (2x4), warp tile 64x32.
// EPI: 1 hi out (+ q-lo out for cols<512); 2 fp32(acc+bias+res) + hi;
//      3 hi(gelu(acc+bias)); 4 fp32(acc+bias+res)
// ---------------------------------------------------------------------------
#define GSTAGE 16384
#define GSMEM  (4 * GSTAGE)

template <int EPI>
__global__ void __launch_bounds__(256, 1) mma_gemm(
    const fp16* __restrict__ Ahi, const fp16* __restrict__ Bhi,
    int M, int N, int K, int lda, int ldb,
    const float* __restrict__ bias, const float* __restrict__ res,
    float* __restrict__ Cf, fp16* __restrict__ Chi, fp16* __restrict__ Clo)
{
    extern __shared__ char smem[];
    uint32_t sb = smem_u32(smem);
    int tid = threadIdx.x, wid = tid >> 5, lane = tid & 31;
    int row0 = blockIdx.y * 128, col0 = blockIdx.x * 128;

    const int NC = K >> 5;

    auto load_stage = [&](int c) {
        uint32_t st = sb + (c & 3) * GSTAGE;
        int k0 = c << 5;
        #pragma unroll
        for (int l = 0; l < 4; l++) {
            int idx = tid + l * 256;        // 1024 chunks of 16B (A 512, B 512)
            int mat = idx >> 9, r = (idx >> 2) & 127, ch = idx & 3;
            uint32_t dst = sw64(st + mat * 8192, r, ch);
            const fp16* src = mat == 0
                ? Ahi + (size_t)(row0 + r) * lda + k0 + ch * 8
                : Bhi + (size_t)(col0 + r) * ldb + k0 + ch * 8;
            CP_ASYNC_16(dst, src);
        }
        CP_COMMIT();
    };

    float acc[4][4][4] = {};
    int mi = lane >> 3, lr = lane & 7;
    int wm = (wid >> 2) * 64;
    int wn = (wid & 3) * 32;

    load_stage(0);
    load_stage(1);
    load_stage(2);

    for (int c = 0; c < NC; c++) {
        uint32_t st = sb + (c & 3) * GSTAGE;
        if (c + 3 < NC)      { load_stage(c + 3); CP_WAIT3(); }
        else if (c + 2 < NC) { CP_WAIT2(); }
        else if (c + 1 < NC) { CP_WAIT1(); }
        else                 { CP_WAIT0(); }
        __syncthreads();

        #pragma unroll
        for (int s16 = 0; s16 < 2; s16++) {
            uint32_t ah[4][4], bh[2][4];
            #pragma unroll
            for (int t = 0; t < 4; t++) {
                int row = wm + t * 16 + ((mi & 1) << 3) + lr;
                int ch  = s16 * 2 + (mi >> 1);
                ldsm4(ah[t], sw64(st, row, ch));
            }
            #pragma unroll
            for (int p = 0; p < 2; p++) {
                int row = wn + p * 16 + ((mi >> 1) << 3) + lr;
                int ch  = s16 * 2 + (mi & 1);
                ldsm4(bh[p], sw64(st + 8192, row, ch));
            }
            #pragma unroll
            for (int tm = 0; tm < 4; tm++)
                #pragma unroll
                for (int tn = 0; tn < 4; tn++)
                    mma_fp16(acc[tm][tn], ah[tm], &bh[tn >> 1][(tn & 1) * 2]);
        }
        __syncthreads();
    }

    int g = lane >> 2, tc = lane & 3;
    #pragma unroll
    for (int tm = 0; tm < 4; tm++) {
        #pragma unroll
        for (int tn = 0; tn < 4; tn++) {
            int rr = row0 + wm + tm * 16 + g;
            int cc = col0 + wn + tn * 8 + tc * 2;
            #pragma unroll
            for (int half_ = 0; half_ < 2; half_++) {
                int r_ = rr + half_ * 8;
                float v0 = acc[tm][tn][half_ * 2 + 0];
                float v1 = acc[tm][tn][half_ * 2 + 1];
                size_t off = (size_t)r_ * N + cc;
                if (EPI == 2 || EPI == 4) {
                    float2 b2 = *(const float2*)(bias + cc);
                    float2 r2 = *(const float2*)(res + off);
                    v0 += b2.x + r2.x; v1 += b2.y + r2.y;
                    *(float2*)(Cf + off) = make_float2(v0, v1);
                } else if (EPI == 3) {
                    float2 b2 = *(const float2*)(bias + cc);
                    v0 = gelu_f(v0 + b2.x); v1 = gelu_f(v1 + b2.y);
                }
                if (EPI == 1) {
                    fp16 h0, l0, h1, l1;
                    split_h(v0, h0, l0); split_h(v1, h1, l1);
                    *(uint32_t*)(Chi + off) = pack_h2(h0, h1);
                    if (cc < 512)   // q columns: store lo for flash correction
                        *(uint32_t*)(Clo + (size_t)r_ * 512 + cc) = pack_h2(l0, l1);
                } else if (EPI == 2 || EPI == 3) {
                    *(uint32_t*)(Chi + off) =
                        pack_h2(__float2half_rn(v0), __float2half_rn(v1));
                }
            }
        }
    }
}

// ---------------------------------------------------------------------------
// Fused flash attention (unchanged from round 5 — Q/P corrected, K/V hi-only)
// ---------------------------------------------------------------------------
#define FA_SMEM 65536

__global__ void __launch_bounds__(256, 1) flash_kernel(
    const fp16* __restrict__ qkvh, const fp16* __restrict__ qlo,
    fp16* __restrict__ aoh)
{
    extern __shared__ char smem[];
    uint32_t sb = smem_u32(smem);
    int tid = threadIdx.x, wid = tid >> 5, lane = tid & 31;
    int mi = lane >> 3, lr = lane & 7;
    int g = lane >> 2, tc = lane & 3;
    int z = blockIdx.y;
    int b = z >> 6, h = (z >> 3) & 7, p = z & 7;
    int row0 = blockIdx.x * 128;
    size_t base = (size_t)((b * 8 + p)) * NSEQ * QKVW + h * 64;
    const fp16* Qh = qkvh + base;
    const fp16* Ql = qlo + (size_t)((b * 8 + p)) * NSEQ * 512 + h * 64;
    const fp16* Kh = qkvh + base + 512;
    const fp16* Vh = qkvh + base + 1024;

    uint32_t qoff = sb;           // Qh 16KB, Ql 16KB
    uint32_t soff = sb + 32768;   // 2 stages x 16KB (Kh, Vh @ 8KB)

    #pragma unroll
    for (int l = 0; l < 8; l++) {
        int idx = tid + l * 256;
        int mat = idx >> 10, r = (idx >> 3) & 127, ch = idx & 7;
        const fp16* src = mat == 0 ? Qh + (size_t)(row0 + r) * QKVW + ch * 8
                                   : Ql + (size_t)(row0 + r) * 512  + ch * 8;
        CP_ASYNC_16(sw128(qoff + mat * 16384, r, ch), src);
    }

    auto load_stage = [&](int c) {
        uint32_t st = soff + (c & 1) * 16384;
        int kv0 = c << 6;
        #pragma unroll
        for (int l = 0; l < 4; l++) {
            int idx = tid + l * 256;
            int mat = idx >> 9, r = (idx >> 3) & 63, ch = idx & 7;
            const fp16* src = (mat == 0 ? Kh : Vh) + (size_t)(kv0 + r) * QKVW + ch * 8;
            CP_ASYNC_16(sw128(st + mat * 8192, r, ch), src);
        }
        CP_COMMIT();
    };

    load_stage(0);
    load_stage(1);

    float m_r[2] = {-1e30f, -1e30f};
    float l_r[2] = {0.f, 0.f};
    float O[8][4] = {};
    int qr0 = wid * 16;
    const float LS = SCALE * 1.4426950408889634f;

    for (int c = 0; c < 16; c++) {
        if (c == 0)       { CP_WAIT1(); }
        else if (c < 15)  { load_stage(c + 1); CP_WAIT1(); }
        else              { CP_WAIT0(); }
        __syncthreads();

        uint32_t st = soff + (c & 1) * 16384;
        uint32_t kh_o = st, vh_o = st + 8192;

        float S[8][4] = {};
        #pragma unroll
        for (int ks = 0; ks < 4; ks++) {
            uint32_t ah[4], al[4];
            {
                int row = qr0 + ((mi & 1) << 3) + lr;
                int ch  = ks * 2 + (mi >> 1);
                ldsm4(ah, sw128(qoff,         row, ch));
                ldsm4(al, sw128(qoff + 16384, row, ch));
            }
            #pragma unroll
            for (int np = 0; np < 4; np++) {
                uint32_t bh[4];
                int row = np * 16 + ((mi >> 1) << 3) + lr;
                int ch  = ks * 2 + (mi & 1);
                ldsm4(bh, sw128(kh_o, row, ch));
                mma_fp16(S[np * 2],     ah, &bh[0]);
                mma_fp16(S[np * 2 + 1], ah, &bh[2]);
                mma_fp16(S[np * 2],     al, &bh[0]);
                mma_fp16(S[np * 2 + 1], al, &bh[2]);
            }
        }

        #pragma unroll
        for (int hf = 0; hf < 2; hf++) {
            float mx = -1e30f;
            #pragma unroll
            for (int j = 0; j < 8; j++) {
                S[j][hf * 2]     *= LS;
                S[j][hf * 2 + 1] *= LS;
                mx = fmaxf(mx, fmaxf(S[j][hf * 2], S[j][hf * 2 + 1]));
            }
            mx = fmaxf(mx, __shfl_xor_sync(0xffffffffu, mx, 1));
            mx = fmaxf(mx, __shfl_xor_sync(0xffffffffu, mx, 2));
            float mnew = fmaxf(m_r[hf], mx);
            float alpha = exp2f(m_r[hf] - mnew);
            m_r[hf] = mnew;
            float s = 0.f;
            #pragma unroll
            for (int j = 0; j < 8; j++) {
                float p0 = exp2f(S[j][hf * 2]     - mnew);
                float p1 = exp2f(S[j][hf * 2 + 1] - mnew);
                S[j][hf * 2] = p0; S[j][hf * 2 + 1] = p1;
                s += p0 + p1;
            }
            s += __shfl_xor_sync(0xffffffffu, s, 1);
            s += __shfl_xor_sync(0xffffffffu, s, 2);
            l_r[hf] = l_r[hf] * alpha + s;
            #pragma unroll
            for (int j = 0; j < 8; j++) {
                O[j][hf * 2]     *= alpha;
                O[j][hf * 2 + 1] *= alpha;
            }
        }

        uint32_t ph[4][4], pl[4][4];
        #pragma unroll
        for (int s_ = 0; s_ < 4; s_++) {
            #pragma unroll
            for (int q4 = 0; q4 < 4; q4++) {
                int j  = s_ * 2 + (q4 >> 1);
                int k0 = (q4 & 1) * 2;
                fp16 h0, l0, h1, l1;
                split_h(S[j][k0],     h0, l0);
                split_h(S[j][k0 + 1], h1, l1);
                ph[s_][q4] = pack_h2(h0, h1);
                pl[s_][q4] = pack_h2(l0, l1);
            }
        }

        #pragma unroll
        for (int s_ = 0; s_ < 4; s_++) {
            #pragma unroll
            for (int dp = 0; dp < 4; dp++) {
                uint32_t vhh[4];
                int row = s_ * 16 + ((mi & 1) << 3) + lr;
                int chk = dp * 2 + (mi >> 1);
                ldsm4t(vhh, sw128(vh_o, row, chk));
                mma_fp16(O[dp * 2],     ph[s_], &vhh[0]);
                mma_fp16(O[dp * 2 + 1], ph[s_], &vhh[2]);
                mma_fp16(O[dp * 2],     pl[s_], &vhh[0]);
                mma_fp16(O[dp * 2 + 1], pl[s_], &vhh[2]);
            }
        }
        __syncthreads();
    }

    float inv0 = 1.0f / l_r[0], inv1 = 1.0f / l_r[1];
    size_t obase = (size_t)(b * 8 + h) * NSEQ;
    #pragma unroll
    for (int dp = 0; dp < 8; dp++) {
        int d = dp * 8 + tc * 2;
        #pragma unroll
        for (int hf = 0; hf < 2; hf++) {
            float inv = hf ? inv1 : inv0;
            int n = row0 + qr0 + g + hf * 8;
            float v0 = O[dp][hf * 2]     * inv;
            float v1 = O[dp][hf * 2 + 1] * inv;
            size_t off = (obase + n) * DIM + p * 64 + d;
            *(uint32_t*)(aoh + off) =
                pack_h2(__float2half_rn(v0), __float2half_rn(v1));
        }
    }
}

// ---------------------------------------------------------------------------
// Weight transpose + cast: W[K,N] fp32 -> T[N,K] fp16
// ---------------------------------------------------------------------------
__global__ void __launch_bounds__(256) tcast_kernel(
    const float* __restrict__ W, fp16* __restrict__ Th, int K, int N)
{
    int id = blockIdx.x * 256 + threadIdx.x;
    if (id >= K * N) return;
    int n = id / K, k = id - n * K;
    Th[id] = __float2half_rn(W[(size_t)k * N + n]);
}

// ---------------------------------------------------------------------------
// LN0 + LN1
// ---------------------------------------------------------------------------
__device__ __forceinline__ float block_sum(float v, float* sm) {
    #pragma unroll
    for (int o = 16; o > 0; o >>= 1) v += __shfl_down_sync(0xffffffffu, v, o);
    int lane = threadIdx.x & 31, wid = threadIdx.x >> 5;
    if (lane == 0) sm[wid] = v;
    __syncthreads();
    v = (threadIdx.x < 8) ? sm[threadIdx.x] : 0.0f;
    if (wid == 0) {
        #pragma unroll
        for (int o = 4; o > 0; o >>= 1) v += __shfl_down_sync(0xffffffffu, v, o);
        if (lane == 0) sm[0] = v;
    }
    __syncthreads();
    float r = sm[0];
    __syncthreads();
    return r;
}

__global__ void __launch_bounds__(256) ln_kernel(
    const float* __restrict__ x,
    const float* __restrict__ w0, const float* __restrict__ b0,
    const float* __restrict__ w1, const float* __restrict__ b1,
    float* __restrict__ xn, fp16* __restrict__ hh)
{
    __shared__ float sm[32];
    size_t row = blockIdx.x;
    const float* xr = x + row * DIM;
    int t = threadIdx.x;

    float v0 = xr[t], v1 = xr[t + 256];
    float mu = block_sum(v0 + v1, sm) * (1.0f / DIM);
    float d0 = v0 - mu, d1 = v1 - mu;
    float var = block_sum(d0 * d0 + d1 * d1, sm) * (1.0f / DIM);
    float r = rsqrtf(var + EPS);
    float y0 = d0 * r * w0[t] + b0[t];
    float y1 = d1 * r * w0[t + 256] + b0[t + 256];
    xn[row * DIM + t]       = y0;
    xn[row * DIM + t + 256] = y1;

    float mu2 = block_sum(y0 + y1, sm) * (1.0f / DIM);
    float e0 = y0 - mu2, e1 = y1 - mu2;
    float var2 = block_sum(e0 * e0 + e1 * e1, sm) * (1.0f / DIM);
    float r2 = rsqrtf(var2 + EPS);
    hh[row * DIM + t]       = __float2half_rn(e0 * r2 * w1[t] + b1[t]);
    hh[row * DIM + t + 256] = __float2half_rn(e1 * r2 * w1[t + 256] + b1[t + 256]);
}

// ---------------------------------------------------------------------------
// Launch
// ---------------------------------------------------------------------------
extern "C" void kernel_launch(void* const* d_in, const int* in_sizes, int n_in,
                              void* d_out, int out_size)
{
    (void)in_sizes; (void)n_in; (void)out_size;
    const float* x     = (const float*)d_in[0];
    const float* ln0_w = (const float*)d_in[1];
    const float* ln0_b = (const float*)d_in[2];
    const float* ln1_w = (const float*)d_in[3];
    const float* ln1_b = (const float*)d_in[4];
    const float* w_qkv = (const float*)d_in[5];
    const float* w_o   = (const float*)d_in[6];
    const float* b_o   = (const float*)d_in[7];
    const float* w1    = (const float*)d_in[8];
    const float* b1    = (const float*)d_in[9];
    const float* w2    = (const float*)d_in[10];
    const float* b2    = (const float*)d_in[11];
    float* out = (float*)d_out;

    void *p;
    cudaGetSymbolAddress(&p, g_xn);    float* xn   = (float*)p;
    cudaGetSymbolAddress(&p, g_hh);    fp16* hh    = (fp16*)p;
    cudaGetSymbolAddress(&p, g_qkvh);  fp16* qkvh  = (fp16*)p;
    cudaGetSymbolAddress(&p, g_qlo);   fp16* qlo   = (fp16*)p;
    cudaGetSymbolAddress(&p, g_aoh);   fp16* aoh   = (fp16*)p;
    cudaGetSymbolAddress(&p, g_x2);    float* x2   = (float*)p;
    cudaGetSymbolAddress(&p, g_x2h);   fp16* x2h   = (fp16*)p;
    cudaGetSymbolAddress(&p, g_midh);  fp16* midh  = (fp16*)p;
    cudaGetSymbolAddress(&p, g_wqkvt); fp16* wqkvt = (fp16*)p;
    cudaGetSymbolAddress(&p, g_wot);   fp16* wot   = (fp16*)p;
    cudaGetSymbolAddress(&p, g_w1t);   fp16* w1t   = (fp16*)p;
    cudaGetSymbolAddress(&p, g_w2t);   fp16* w2t   = (fp16*)p;

    cudaFuncSetAttribute(mma_gemm<1>, cudaFuncAttributeMaxDynamicSharedMemorySize, GSMEM);
    cudaFuncSetAttribute(mma_gemm<2>, cudaFuncAttributeMaxDynamicSharedMemorySize, GSMEM);
    cudaFuncSetAttribute(mma_gemm<3>, cudaFuncAttributeMaxDynamicSharedMemorySize, GSMEM);
    cudaFuncSetAttribute(mma_gemm<4>, cudaFuncAttributeMaxDynamicSharedMemorySize, GSMEM);
    cudaFuncSetAttribute(flash_kernel, cudaFuncAttributeMaxDynamicSharedMemorySize, FA_SMEM);

    // weight prep (transpose + cast)
    tcast_kernel<<<(DIM * QKVW + 255) / 256, 256>>>(w_qkv, wqkvt, DIM, QKVW);
    tcast_kernel<<<(INNER * DIM + 255) / 256, 256>>>(w_o, wot, INNER, DIM);
    tcast_kernel<<<(DIM * HIDDEN + 255) / 256, 256>>>(w1, w1t, DIM, HIDDEN);
    tcast_kernel<<<(HIDDEN * DIM + 255) / 256, 256>>>(w2, w2t, HIDDEN, DIM);

    // 1) LN0 + LN1
    ln_kernel<<<ROWS, 256>>>(x, ln0_w, ln0_b, ln1_w, ln1_b, xn, hh);
    // 2) qkv = h @ w_qkv  (hi out; q-lo out)
    mma_gemm<1><<<dim3(QKVW / 128, ROWS / 128), 256, GSMEM>>>(
        hh, wqkvt, ROWS, QKVW, DIM, DIM, DIM,
        nullptr, nullptr, nullptr, qkvh, qlo);
    // 3) fused attention
    flash_kernel<<<dim3(8, NZ), 256, FA_SMEM>>>(qkvh, qlo, aoh);
    // 4) x2 = ao @ w_o + b_o + xn  (fp32 + hi)
    mma_gemm<2><<<dim3(DIM / 128, ROWS / 128), 256, GSMEM>>>(
        aoh, wot, ROWS, DIM, INNER, INNER, INNER,
        b_o, xn, x2, x2h, nullptr);
    // 5) mid = gelu(x2 @ w1 + b1)  (hi out)
    mma_gemm<3><<<dim3(HIDDEN / 128, ROWS / 128), 256, GSMEM>>>(
        x2h, w1t, ROWS, HIDDEN, DIM, DIM, DIM,
        b1, nullptr, nullptr, midh, nullptr);
    // 6) out = mid @ w2 + b2 + x2  (fp32)
    mma_gemm<4><<<dim3(DIM / 128, ROWS / 128), 256, GSMEM>>>(
        midh, w2t, ROWS, DIM, HIDDEN, HIDDEN, HIDDEN,
        b2, x2, out, nullptr, nullptr);
}

// round 7
// speedup vs baseline: 9.5716x; 1.0496x over previous
#include <cuda_runtime.h>
#include <cuda_fp16.h>
#include <cstdint>
#include <math.h>

// ---------------------------------------------------------------------------
// ViT transformer block. fp16 single-pass dense GEMMs (weights hi-only),
// flash attention: QK 2-pass (Q hi+lo), PV single-pass (P hi-only).
// B=2, P=8, N=1024, DIM=512, HEADS=8, DIM_HEAD=64, INNER=512, HIDDEN=2048
// ---------------------------------------------------------------------------

#define ROWS   16384
#define DIM    512
#define INNER  512
#define QKVW   1536
#define HIDDEN 2048
#define NSEQ   1024
#define NZ     128
#define SCALE  0.125f
#define EPS    1e-5f

typedef __half fp16;

// ------------------------- device scratch ---------------------------------
__device__ __align__(256) float g_xn  [(size_t)ROWS * DIM];
__device__ __align__(256) fp16  g_hh  [(size_t)ROWS * DIM];
__device__ __align__(256) fp16  g_qkvh[(size_t)ROWS * QKVW];
__device__ __align__(256) fp16  g_qlo [(size_t)ROWS * 512];
__device__ __align__(256) fp16  g_aoh [(size_t)ROWS * DIM];
__device__ __align__(256) float g_x2  [(size_t)ROWS * DIM];
__device__ __align__(256) fp16  g_x2h [(size_t)ROWS * DIM];
__device__ __align__(256) fp16  g_midh[(size_t)ROWS * HIDDEN];
// transposed weights [N, K], fp16 hi
__device__ __align__(256) fp16  g_wqkvt[(size_t)QKVW * DIM];
__device__ __align__(256) fp16  g_wot  [(size_t)DIM * INNER];
__device__ __align__(256) fp16  g_w1t  [(size_t)HIDDEN * DIM];
__device__ __align__(256) fp16  g_w2t  [(size_t)DIM * HIDDEN];

// ------------------------- PTX helpers ------------------------------------
__device__ __forceinline__ uint32_t smem_u32(const void* p) {
    uint32_t a;
    asm("{ .reg .u64 t; cvta.to.shared.u64 t, %1; cvt.u32.u64 %0, t; }"
        : "=r"(a) : "l"(p));
    return a;
}
#define CP_ASYNC_16(sa, ga) \
    asm volatile("cp.async.cg.shared.global [%0], [%1], 16;" \
                 :: "r"((uint32_t)(sa)), "l"(ga) : "memory")
#define CP_COMMIT() asm volatile("cp.async.commit_group;" ::: "memory")
#define CP_WAIT0()  asm volatile("cp.async.wait_group 0;" ::: "memory")
#define CP_WAIT1()  asm volatile("cp.async.wait_group 1;" ::: "memory")
#define CP_WAIT2()  asm volatile("cp.async.wait_group 2;" ::: "memory")
#define CP_WAIT3()  asm volatile("cp.async.wait_group 3;" ::: "memory")

__device__ __forceinline__ void ldsm4(uint32_t* r, uint32_t addr) {
    asm volatile("ldmatrix.sync.aligned.m8n8.x4.shared.b16 {%0,%1,%2,%3}, [%4];"
        : "=r"(r[0]), "=r"(r[1]), "=r"(r[2]), "=r"(r[3]) : "r"(addr));
}
__device__ __forceinline__ void ldsm4t(uint32_t* r, uint32_t addr) {
    asm volatile("ldmatrix.sync.aligned.m8n8.x4.trans.shared.b16 {%0,%1,%2,%3}, [%4];"
        : "=r"(r[0]), "=r"(r[1]), "=r"(r[2]), "=r"(r[3]) : "r"(addr));
}
__device__ __forceinline__ void mma_fp16(float* c, const uint32_t* a, const uint32_t* b) {
    asm volatile(
        "mma.sync.aligned.m16n8k16.row.col.f32.f16.f16.f32 "
        "{%0,%1,%2,%3}, {%4,%5,%6,%7}, {%8,%9}, {%0,%1,%2,%3};"
        : "+f"(c[0]), "+f"(c[1]), "+f"(c[2]), "+f"(c[3])
        : "r"(a[0]), "r"(a[1]), "r"(a[2]), "r"(a[3]), "r"(b[0]), "r"(b[1]));
}

__device__ __forceinline__ float gelu_f(float x) {
    return 0.5f * x * (1.0f + erff(x * 0.7071067811865475f));
}
__device__ __forceinline__ void split_h(float v, fp16& h, fp16& l) {
    h = __float2half_rn(v);
    l = __float2half_rn(v - __half2float(h));
}
__device__ __forceinline__ uint32_t pack_h2(fp16 a, fp16 b) {
    __half2 t = __halves2half2(a, b);
    return *(uint32_t*)&t;
}

// swizzled smem addr for a 64B-row tile (rows x 32 fp16)
__device__ __forceinline__ uint32_t sw64(uint32_t base, int row, int chunk) {
    return base + row * 64 + ((chunk ^ ((row >> 1) & 3)) << 4);
}
// swizzled smem addr for a 128B-row tile (rows x 64 fp16)
__device__ __forceinline__ uint32_t sw128(uint32_t base, int row, int chunk) {
    return base + row * 128 + ((chunk ^ (row & 7)) << 4);
}

// ---------------------------------------------------------------------------
// Single-pass fp16 GEMM: C[M,N] = A[M,K] @ Bt[N,K]^T
// BM=128, BN=128, BK=32, 4-stage cp.async. 8 warps (2x4), warp tile 64x32.
// EPI: 1 hi out (+ q-lo out for cols<512); 2 fp32(acc+bias+res) + hi;
//      3 hi(gelu(acc+bias)); 4 fp32(acc+bias+res)
// ---------------------------------------------------------------------------
#define GSTAGE 16384
#define GSMEM  (4 * GSTAGE)

template <int EPI>
__global__ void __launch_bounds__(256, 1) mma_gemm(
    const fp16* __restrict__ Ahi, const fp16* __restrict__ Bhi,
    int M, int N, int K, int lda, int ldb,
    const float* __restrict__ bias, const float* __restrict__ res,
    float* __restrict__ Cf, fp16* __restrict__ Chi, fp16* __restrict__ Clo)
{
    extern __shared__ char smem[];
    uint32_t sb = smem_u32(smem);
    int tid = threadIdx.x, wid = tid >> 5, lane = tid & 31;
    int row0 = blockIdx.y * 128, col0 = blockIdx.x * 128;

    const int NC = K >> 5;

    auto load_stage = [&](int c) {
        uint32_t st = sb + (c & 3) * GSTAGE;
        int k0 = c << 5;
        #pragma unroll
        for (int l = 0; l < 4; l++) {
            int idx = tid + l * 256;
            int mat = idx >> 9, r = (idx >> 2) & 127, ch = idx & 3;
            uint32_t dst = sw64(st + mat * 8192, r, ch);
            const fp16* src = mat == 0
                ? Ahi + (size_t)(row0 + r) * lda + k0 + ch * 8
                : Bhi + (size_t)(col0 + r) * ldb + k0 + ch * 8;
            CP_ASYNC_16(dst, src);
        }
        CP_COMMIT();
    };

    float acc[4][4][4] = {};
    int mi = lane >> 3, lr = lane & 7;
    int wm = (wid >> 2) * 64;
    int wn = (wid & 3) * 32;

    load_stage(0);
    load_stage(1);
    load_stage(2);

    for (int c = 0; c < NC; c++) {
        uint32_t st = sb + (c & 3) * GSTAGE;
        if (c + 3 < NC)      { load_stage(c + 3); CP_WAIT3(); }
        else if (c + 2 < NC) { CP_WAIT2(); }
        else if (c + 1 < NC) { CP_WAIT1(); }
        else                 { CP_WAIT0(); }
        __syncthreads();

        #pragma unroll
        for (int s16 = 0; s16 < 2; s16++) {
            uint32_t ah[4][4], bh[2][4];
            #pragma unroll
            for (int t = 0; t < 4; t++) {
                int row = wm + t * 16 + ((mi & 1) << 3) + lr;
                int ch  = s16 * 2 + (mi >> 1);
                ldsm4(ah[t], sw64(st, row, ch));
            }
            #pragma unroll
            for (int p = 0; p < 2; p++) {
                int row = wn + p * 16 + ((mi >> 1) << 3) + lr;
                int ch  = s16 * 2 + (mi & 1);
                ldsm4(bh[p], sw64(st + 8192, row, ch));
            }
            #pragma unroll
            for (int tm = 0; tm < 4; tm++)
                #pragma unroll
                for (int tn = 0; tn < 4; tn++)
                    mma_fp16(acc[tm][tn], ah[tm], &bh[tn >> 1][(tn & 1) * 2]);
        }
        __syncthreads();
    }

    int g = lane >> 2, tc = lane & 3;
    #pragma unroll
    for (int tm = 0; tm < 4; tm++) {
        #pragma unroll
        for (int tn = 0; tn < 4; tn++) {
            int rr = row0 + wm + tm * 16 + g;
            int cc = col0 + wn + tn * 8 + tc * 2;
            #pragma unroll
            for (int half_ = 0; half_ < 2; half_++) {
                int r_ = rr + half_ * 8;
                float v0 = acc[tm][tn][half_ * 2 + 0];
                float v1 = acc[tm][tn][half_ * 2 + 1];
                size_t off = (size_t)r_ * N + cc;
                if (EPI == 2 || EPI == 4) {
                    float2 b2 = *(const float2*)(bias + cc);
                    float2 r2 = *(const float2*)(res + off);
                    v0 += b2.x + r2.x; v1 += b2.y + r2.y;
                    *(float2*)(Cf + off) = make_float2(v0, v1);
                } else if (EPI == 3) {
                    float2 b2 = *(const float2*)(bias + cc);
                    v0 = gelu_f(v0 + b2.x); v1 = gelu_f(v1 + b2.y);
                }
                if (EPI == 1) {
                    fp16 h0, l0, h1, l1;
                    split_h(v0, h0, l0); split_h(v1, h1, l1);
                    *(uint32_t*)(Chi + off) = pack_h2(h0, h1);
                    if (cc < 512)   // q columns: store lo for flash correction
                        *(uint32_t*)(Clo + (size_t)r_ * 512 + cc) = pack_h2(l0, l1);
                } else if (EPI == 2 || EPI == 3) {
                    *(uint32_t*)(Chi + off) =
                        pack_h2(__float2half_rn(v0), __float2half_rn(v1));
                }
            }
        }
    }
}

// ---------------------------------------------------------------------------
// Fused flash attention. QK 2-pass (Q hi+lo), PV single-pass (P hi-only).
// ---------------------------------------------------------------------------
#define FA_SMEM 65536

__global__ void __launch_bounds__(256, 1) flash_kernel(
    const fp16* __restrict__ qkvh, const fp16* __restrict__ qlo,
    fp16* __restrict__ aoh)
{
    extern __shared__ char smem[];
    uint32_t sb = smem_u32(smem);
    int tid = threadIdx.x, wid = tid >> 5, lane = tid & 31;
    int mi = lane >> 3, lr = lane & 7;
    int g = lane >> 2, tc = lane & 3;
    int z = blockIdx.y;
    int b = z >> 6, h = (z >> 3) & 7, p = z & 7;
    int row0 = blockIdx.x * 128;
    size_t base = (size_t)((b * 8 + p)) * NSEQ * QKVW + h * 64;
    const fp16* Qh = qkvh + base;
    const fp16* Ql = qlo + (size_t)((b * 8 + p)) * NSEQ * 512 + h * 64;
    const fp16* Kh = qkvh + base + 512;
    const fp16* Vh = qkvh + base + 1024;

    uint32_t qoff = sb;           // Qh 16KB, Ql 16KB
    uint32_t soff = sb + 32768;   // 2 stages x 16KB (Kh, Vh @ 8KB)

    #pragma unroll
    for (int l = 0; l < 8; l++) {
        int idx = tid + l * 256;
        int mat = idx >> 10, r = (idx >> 3) & 127, ch = idx & 7;
        const fp16* src = mat == 0 ? Qh + (size_t)(row0 + r) * QKVW + ch * 8
                                   : Ql + (size_t)(row0 + r) * 512  + ch * 8;
        CP_ASYNC_16(sw128(qoff + mat * 16384, r, ch), src);
    }

    auto load_stage = [&](int c) {
        uint32_t st = soff + (c & 1) * 16384;
        int kv0 = c << 6;
        #pragma unroll
        for (int l = 0; l < 4; l++) {
            int idx = tid + l * 256;
            int mat = idx >> 9, r = (idx >> 3) & 63, ch = idx & 7;
            const fp16* src = (mat == 0 ? Kh : Vh) + (size_t)(kv0 + r) * QKVW + ch * 8;
            CP_ASYNC_16(sw128(st + mat * 8192, r, ch), src);
        }
        CP_COMMIT();
    };

    load_stage(0);
    load_stage(1);

    float m_r[2] = {-1e30f, -1e30f};
    float l_r[2] = {0.f, 0.f};
    float O[8][4] = {};
    int qr0 = wid * 16;
    const float LS = SCALE * 1.4426950408889634f;

    for (int c = 0; c < 16; c++) {
        if (c == 0)       { CP_WAIT1(); }
        else if (c < 15)  { load_stage(c + 1); CP_WAIT1(); }
        else              { CP_WAIT0(); }
        __syncthreads();

        uint32_t st = soff + (c & 1) * 16384;
        uint32_t kh_o = st, vh_o = st + 8192;

        float S[8][4] = {};
        #pragma unroll
        for (int ks = 0; ks < 4; ks++) {
            uint32_t ah[4], al[4];
            {
                int row = qr0 + ((mi & 1) << 3) + lr;
                int ch  = ks * 2 + (mi >> 1);
                ldsm4(ah, sw128(qoff,         row, ch));
                ldsm4(al, sw128(qoff + 16384, row, ch));
            }
            #pragma unroll
            for (int np = 0; np < 4; np++) {
                uint32_t bh[4];
                int row = np * 16 + ((mi >> 1) << 3) + lr;
                int ch  = ks * 2 + (mi & 1);
                ldsm4(bh, sw128(kh_o, row, ch));
                mma_fp16(S[np * 2],     ah, &bh[0]);
                mma_fp16(S[np * 2 + 1], ah, &bh[2]);
                mma_fp16(S[np * 2],     al, &bh[0]);
                mma_fp16(S[np * 2 + 1], al, &bh[2]);
            }
        }

        #pragma unroll
        for (int hf = 0; hf < 2; hf++) {
            float mx = -1e30f;
            #pragma unroll
            for (int j = 0; j < 8; j++) {
                S[j][hf * 2]     *= LS;
                S[j][hf * 2 + 1] *= LS;
                mx = fmaxf(mx, fmaxf(S[j][hf * 2], S[j][hf * 2 + 1]));
            }
            mx = fmaxf(mx, __shfl_xor_sync(0xffffffffu, mx, 1));
            mx = fmaxf(mx, __shfl_xor_sync(0xffffffffu, mx, 2));
            float mnew = fmaxf(m_r[hf], mx);
            float alpha = exp2f(m_r[hf] - mnew);
            m_r[hf] = mnew;
            float s = 0.f;
            #pragma unroll
            for (int j = 0; j < 8; j++) {
                float p0 = exp2f(S[j][hf * 2]     - mnew);
                float p1 = exp2f(S[j][hf * 2 + 1] - mnew);
                S[j][hf * 2] = p0; S[j][hf * 2 + 1] = p1;
                s += p0 + p1;
            }
            s += __shfl_xor_sync(0xffffffffu, s, 1);
            s += __shfl_xor_sync(0xffffffffu, s, 2);
            l_r[hf] = l_r[hf] * alpha + s;
            #pragma unroll
            for (int j = 0; j < 8; j++) {
                O[j][hf * 2]     *= alpha;
                O[j][hf * 2 + 1] *= alpha;
            }
        }

        // pack P hi-only (C-frag -> A-frag correspondence)
        uint32_t ph[4][4];
        #pragma unroll
        for (int s_ = 0; s_ < 4; s_++) {
            #pragma unroll
            for (int q4 = 0; q4 < 4; q4++) {
                int j  = s_ * 2 + (q4 >> 1);
                int k0 = (q4 & 1) * 2;
                ph[s_][q4] = pack_h2(__float2half_rn(S[j][k0]),
                                     __float2half_rn(S[j][k0 + 1]));
            }
        }

        // O += P V  (single pass), V via ldmatrix.trans
        #pragma unroll
        for (int s_ = 0; s_ < 4; s_++) {
            #pragma unroll
            for (int dp = 0; dp < 4; dp++) {
                uint32_t vhh[4];
                int row = s_ * 16 + ((mi & 1) << 3) + lr;
                int chk = dp * 2 + (mi >> 1);
                ldsm4t(vhh, sw128(vh_o, row, chk));
                mma_fp16(O[dp * 2],     ph[s_], &vhh[0]);
                mma_fp16(O[dp * 2 + 1], ph[s_], &vhh[2]);
            }
        }
        __syncthreads();
    }

    float inv0 = 1.0f / l_r[0], inv1 = 1.0f / l_r[1];
    size_t obase = (size_t)(b * 8 + h) * NSEQ;
    #pragma unroll
    for (int dp = 0; dp < 8; dp++) {
        int d = dp * 8 + tc * 2;
        #pragma unroll
        for (int hf = 0; hf < 2; hf++) {
            float inv = hf ? inv1 : inv0;
            int n = row0 + qr0 + g + hf * 8;
            float v0 = O[dp][hf * 2]     * inv;
            float v1 = O[dp][hf * 2 + 1] * inv;
            size_t off = (obase + n) * DIM + p * 64 + d;
            *(uint32_t*)(aoh + off) =
                pack_h2(__float2half_rn(v0), __float2half_rn(v1));
        }
    }
}

// ---------------------------------------------------------------------------
// Fused weight transpose + cast for all 4 weights: W[K,N] fp32 -> T[N,K] fp16
// Segments: wqkv (512x1536), wo (512x512), w1 (512x2048), w2 (2048x512)
// ---------------------------------------------------------------------------
__global__ void __launch_bounds__(256) tcast_all(
    const float* __restrict__ Wq, fp16* __restrict__ Tq,
    const float* __restrict__ Wo, fp16* __restrict__ To,
    const float* __restrict__ W1, fp16* __restrict__ T1,
    const float* __restrict__ W2, fp16* __restrict__ T2)
{
    int id = blockIdx.x * 256 + threadIdx.x;
    const int S0 = 512 * 1536, S1 = S0 + 512 * 512, S2 = S1 + 512 * 2048;
    const float* W; fp16* T; int K, N, i;
    if (id < S0)      { W = Wq; T = Tq; K = 512;  N = 1536; i = id; }
    else if (id < S1) { W = Wo; T = To; K = 512;  N = 512;  i = id - S0; }
    else if (id < S2) { W = W1; T = T1; K = 512;  N = 2048; i = id - S1; }
    else              { W = W2; T = T2; K = 2048; N = 512;  i = id - S2; }
    int n = i / K, k = i - n * K;
    T[i] = __float2half_rn(W[(size_t)k * N + n]);
}

// ---------------------------------------------------------------------------
// LN0 + LN1
// ---------------------------------------------------------------------------
__device__ __forceinline__ float block_sum(float v, float* sm) {
    #pragma unroll
    for (int o = 16; o > 0; o >>= 1) v += __shfl_down_sync(0xffffffffu, v, o);
    int lane = threadIdx.x & 31, wid = threadIdx.x >> 5;
    if (lane == 0) sm[wid] = v;
    __syncthreads();
    v = (threadIdx.x < 8) ? sm[threadIdx.x] : 0.0f;
    if (wid == 0) {
        #pragma unroll
        for (int o = 4; o > 0; o >>= 1) v += __shfl_down_sync(0xffffffffu, v, o);
        if (lane == 0) sm[0] = v;
    }
    __syncthreads();
    float r = sm[0];
    __syncthreads();
    return r;
}

__global__ void __launch_bounds__(256) ln_kernel(
    const float* __restrict__ x,
    const float* __restrict__ w0, const float* __restrict__ b0,
    const float* __restrict__ w1, const float* __restrict__ b1,
    float* __restrict__ xn, fp16* __restrict__ hh)
{
    __shared__ float sm[32];
    size_t row = blockIdx.x;
    const float* xr = x + row * DIM;
    int t = threadIdx.x;

    float v0 = xr[t], v1 = xr[t + 256];
    float mu = block_sum(v0 + v1, sm) * (1.0f / DIM);
    float d0 = v0 - mu, d1 = v1 - mu;
    float var = block_sum(d0 * d0 + d1 * d1, sm) * (1.0f / DIM);
    float r = rsqrtf(var + EPS);
    float y0 = d0 * r * w0[t] + b0[t];
    float y1 = d1 * r * w0[t + 256] + b0[t + 256];
    xn[row * DIM + t]       = y0;
    xn[row * DIM + t + 256] = y1;

    float mu2 = block_sum(y0 + y1, sm) * (1.0f / DIM);
    float e0 = y0 - mu2, e1 = y1 - mu2;
    float var2 = block_sum(e0 * e0 + e1 * e1, sm) * (1.0f / DIM);
    float r2 = rsqrtf(var2 + EPS);
    hh[row * DIM + t]       = __float2half_rn(e0 * r2 * w1[t] + b1[t]);
    hh[row * DIM + t + 256] = __float2half_rn(e1 * r2 * w1[t + 256] + b1[t + 256]);
}

// ---------------------------------------------------------------------------
// Launch
// ---------------------------------------------------------------------------
extern "C" void kernel_launch(void* const* d_in, const int* in_sizes, int n_in,
                              void* d_out, int out_size)
{
    (void)in_sizes; (void)n_in; (void)out_size;
    const float* x     = (const float*)d_in[0];
    const float* ln0_w = (const float*)d_in[1];
    const float* ln0_b = (const float*)d_in[2];
    const float* ln1_w = (const float*)d_in[3];
    const float* ln1_b = (const float*)d_in[4];
    const float* w_qkv = (const float*)d_in[5];
    const float* w_o   = (const float*)d_in[6];
    const float* b_o   = (const float*)d_in[7];
    const float* w1    = (const float*)d_in[8];
    const float* b1    = (const float*)d_in[9];
    const float* w2    = (const float*)d_in[10];
    const float* b2    = (const float*)d_in[11];
    float* out = (float*)d_out;

    void *p;
    cudaGetSymbolAddress(&p, g_xn);    float* xn   = (float*)p;
    cudaGetSymbolAddress(&p, g_hh);    fp16* hh    = (fp16*)p;
    cudaGetSymbolAddress(&p, g_qkvh);  fp16* qkvh  = (fp16*)p;
    cudaGetSymbolAddress(&p, g_qlo);   fp16* qlo   = (fp16*)p;
    cudaGetSymbolAddress(&p, g_aoh);   fp16* aoh   = (fp16*)p;
    cudaGetSymbolAddress(&p, g_x2);    float* x2   = (float*)p;
    cudaGetSymbolAddress(&p, g_x2h);   fp16* x2h   = (fp16*)p;
    cudaGetSymbolAddress(&p, g_midh);  fp16* midh  = (fp16*)p;
    cudaGetSymbolAddress(&p, g_wqkvt); fp16* wqkvt = (fp16*)p;
    cudaGetSymbolAddress(&p, g_wot);   fp16* wot   = (fp16*)p;
    cudaGetSymbolAddress(&p, g_w1t);   fp16* w1t   = (fp16*)p;
    cudaGetSymbolAddress(&p, g_w2t);   fp16* w2t   = (fp16*)p;

    cudaFuncSetAttribute(mma_gemm<1>, cudaFuncAttributeMaxDynamicSharedMemorySize, GSMEM);
    cudaFuncSetAttribute(mma_gemm<2>, cudaFuncAttributeMaxDynamicSharedMemorySize, GSMEM);
    cudaFuncSetAttribute(mma_gemm<3>, cudaFuncAttributeMaxDynamicSharedMemorySize, GSMEM);
    cudaFuncSetAttribute(mma_gemm<4>, cudaFuncAttributeMaxDynamicSharedMemorySize, GSMEM);
    cudaFuncSetAttribute(flash_kernel, cudaFuncAttributeMaxDynamicSharedMemorySize, FA_SMEM);

    // weight prep (one fused transpose+cast launch; 3,145,728 elements)
    tcast_all<<<12288, 256>>>(w_qkv, wqkvt, w_o, wot, w1, w1t, w2, w2t);

    // 1) LN0 + LN1
    ln_kernel<<<ROWS, 256>>>(x, ln0_w, ln0_b, ln1_w, ln1_b, xn, hh);
    // 2) qkv = h @ w_qkv  (hi out; q-lo out)
    mma_gemm<1><<<dim3(QKVW / 128, ROWS / 128), 256, GSMEM>>>(
        hh, wqkvt, ROWS, QKVW, DIM, DIM, DIM,
        nullptr, nullptr, nullptr, qkvh, qlo);
    // 3) fused attention
    flash_kernel<<<dim3(8, NZ), 256, FA_SMEM>>>(qkvh, qlo, aoh);
    // 4) x2 = ao @ w_o + b_o + xn  (fp32 + hi)
    mma_gemm<2><<<dim3(DIM / 128, ROWS / 128), 256, GSMEM>>>(
        aoh, wot, ROWS, DIM, INNER, INNER, INNER,
        b_o, xn, x2, x2h, nullptr);
    // 5) mid = gelu(x2 @ w1 + b1)  (hi out)
    mma_gemm<3><<<dim3(HIDDEN / 128, ROWS / 128), 256, GSMEM>>>(
        x2h, w1t, ROWS, HIDDEN, DIM, DIM, DIM,
        b1, nullptr, nullptr, midh, nullptr);
    // 6) out = mid @ w2 + b2 + x2  (fp32)
    mma_gemm<4><<<dim3(DIM / 128, ROWS / 128), 256, GSMEM>>>(
        midh, w2t, ROWS, DIM, HIDDEN, HIDDEN, HIDDEN,
        b2, x2, out, nullptr, nullptr);
}

// round 8
// speedup vs baseline: 12.3160x; 1.2867x over previous
#include <cuda_runtime.h>
#include <cuda_fp16.h>
#include <cstdint>
#include <math.h>

// ---------------------------------------------------------------------------
// ViT transformer block. fp16 single-pass mma.sync everywhere.
// Dense GEMMs: 4-stage cp.async ring, 1 barrier/iter, 2 CTAs/SM.
// Flash attention: Q resident, K/V 4-stage ring, 1 barrier/iter.
// B=2, P=8, N=1024, DIM=512, HEADS=8, DIM_HEAD=64, INNER=512, HIDDEN=2048
// ---------------------------------------------------------------------------

#define ROWS   16384
#define DIM    512
#define INNER  512
#define QKVW   1536
#define HIDDEN 2048
#define NSEQ   1024
#define NZ     128
#define SCALE  0.125f
#define EPS    1e-5f

typedef __half fp16;

// ------------------------- device scratch ---------------------------------
__device__ __align__(256) float g_xn  [(size_t)ROWS * DIM];
__device__ __align__(256) fp16  g_hh  [(size_t)ROWS * DIM];
__device__ __align__(256) fp16  g_qkvh[(size_t)ROWS * QKVW];
__device__ __align__(256) fp16  g_aoh [(size_t)ROWS * DIM];
__device__ __align__(256) float g_x2  [(size_t)ROWS * DIM];
__device__ __align__(256) fp16  g_x2h [(size_t)ROWS * DIM];
__device__ __align__(256) fp16  g_midh[(size_t)ROWS * HIDDEN];
// transposed weights [N, K], fp16
__device__ __align__(256) fp16  g_wqkvt[(size_t)QKVW * DIM];
__device__ __align__(256) fp16  g_wot  [(size_t)DIM * INNER];
__device__ __align__(256) fp16  g_w1t  [(size_t)HIDDEN * DIM];
__device__ __align__(256) fp16  g_w2t  [(size_t)DIM * HIDDEN];

// ------------------------- PTX helpers ------------------------------------
__device__ __forceinline__ uint32_t smem_u32(const void* p) {
    uint32_t a;
    asm("{ .reg .u64 t; cvta.to.shared.u64 t, %1; cvt.u32.u64 %0, t; }"
        : "=r"(a) : "l"(p));
    return a;
}
#define CP_ASYNC_16(sa, ga) \
    asm volatile("cp.async.cg.shared.global [%0], [%1], 16;" \
                 :: "r"((uint32_t)(sa)), "l"(ga) : "memory")
#define CP_COMMIT() asm volatile("cp.async.commit_group;" ::: "memory")
#define CP_WAIT0()  asm volatile("cp.async.wait_group 0;" ::: "memory")
#define CP_WAIT1()  asm volatile("cp.async.wait_group 1;" ::: "memory")
#define CP_WAIT2()  asm volatile("cp.async.wait_group 2;" ::: "memory")

__device__ __forceinline__ void ldsm4(uint32_t* r, uint32_t addr) {
    asm volatile("ldmatrix.sync.aligned.m8n8.x4.shared.b16 {%0,%1,%2,%3}, [%4];"
        : "=r"(r[0]), "=r"(r[1]), "=r"(r[2]), "=r"(r[3]) : "r"(addr));
}
__device__ __forceinline__ void ldsm4t(uint32_t* r, uint32_t addr) {
    asm volatile("ldmatrix.sync.aligned.m8n8.x4.trans.shared.b16 {%0,%1,%2,%3}, [%4];"
        : "=r"(r[0]), "=r"(r[1]), "=r"(r[2]), "=r"(r[3]) : "r"(addr));
}
__device__ __forceinline__ void mma_fp16(float* c, const uint32_t* a, const uint32_t* b) {
    asm volatile(
        "mma.sync.aligned.m16n8k16.row.col.f32.f16.f16.f32 "
        "{%0,%1,%2,%3}, {%4,%5,%6,%7}, {%8,%9}, {%0,%1,%2,%3};"
        : "+f"(c[0]), "+f"(c[1]), "+f"(c[2]), "+f"(c[3])
        : "r"(a[0]), "r"(a[1]), "r"(a[2]), "r"(a[3]), "r"(b[0]), "r"(b[1]));
}

__device__ __forceinline__ float gelu_f(float x) {
    return 0.5f * x * (1.0f + erff(x * 0.7071067811865475f));
}
__device__ __forceinline__ uint32_t pack_h2(fp16 a, fp16 b) {
    __half2 t = __halves2half2(a, b);
    return *(uint32_t*)&t;
}

// swizzled smem addr for a 64B-row tile (rows x 32 fp16)
__device__ __forceinline__ uint32_t sw64(uint32_t base, int row, int chunk) {
    return base + row * 64 + ((chunk ^ ((row >> 1) & 3)) << 4);
}
// swizzled smem addr for a 128B-row tile (rows x 64 fp16)
__device__ __forceinline__ uint32_t sw128(uint32_t base, int row, int chunk) {
    return base + row * 128 + ((chunk ^ (row & 7)) << 4);
}

// ---------------------------------------------------------------------------
// Single-pass fp16 GEMM: C[M,N] = A[M,K] @ Bt[N,K]^T
// BM=128, BN=128, BK=32, 4-stage ring, 1 barrier/iter, 2 CTAs/SM.
// 8 warps (2x4), warp tile 64x32.
// EPI: 1 hi out; 2 fp32(acc+bias+res) + hi; 3 hi(gelu(acc+bias));
//      4 fp32(acc+bias+res)
// ---------------------------------------------------------------------------
#define GSTAGE 16384
#define GSMEM  (4 * GSTAGE)

template <int EPI>
__global__ void __launch_bounds__(256, 2) mma_gemm(
    const fp16* __restrict__ Ahi, const fp16* __restrict__ Bhi,
    int M, int N, int K, int lda, int ldb,
    const float* __restrict__ bias, const float* __restrict__ res,
    float* __restrict__ Cf, fp16* __restrict__ Chi)
{
    extern __shared__ char smem[];
    uint32_t sb = smem_u32(smem);
    int tid = threadIdx.x, wid = tid >> 5, lane = tid & 31;
    int row0 = blockIdx.y * 128, col0 = blockIdx.x * 128;

    const int NC = K >> 5;

    auto load_stage = [&](int c) {
        uint32_t st = sb + (c & 3) * GSTAGE;
        int k0 = c << 5;
        #pragma unroll
        for (int l = 0; l < 4; l++) {
            int idx = tid + l * 256;
            int mat = idx >> 9, r = (idx >> 2) & 127, ch = idx & 3;
            uint32_t dst = sw64(st + mat * 8192, r, ch);
            const fp16* src = mat == 0
                ? Ahi + (size_t)(row0 + r) * lda + k0 + ch * 8
                : Bhi + (size_t)(col0 + r) * ldb + k0 + ch * 8;
            CP_ASYNC_16(dst, src);
        }
        CP_COMMIT();
    };

    float acc[4][4][4] = {};
    int mi = lane >> 3, lr = lane & 7;
    int wm = (wid >> 2) * 64;
    int wn = (wid & 3) * 32;

    load_stage(0);
    load_stage(1);
    load_stage(2);

    for (int c = 0; c < NC; c++) {
        if (c + 1 == NC)      { CP_WAIT0(); }
        else if (c + 2 == NC) { CP_WAIT1(); }
        else                  { CP_WAIT2(); }
        __syncthreads();
        if (c + 3 < NC) load_stage(c + 3);

        uint32_t st = sb + (c & 3) * GSTAGE;
        #pragma unroll
        for (int s16 = 0; s16 < 2; s16++) {
            uint32_t ah[4][4], bh[2][4];
            #pragma unroll
            for (int t = 0; t < 4; t++) {
                int row = wm + t * 16 + ((mi & 1) << 3) + lr;
                int ch  = s16 * 2 + (mi >> 1);
                ldsm4(ah[t], sw64(st, row, ch));
            }
            #pragma unroll
            for (int p = 0; p < 2; p++) {
                int row = wn + p * 16 + ((mi >> 1) << 3) + lr;
                int ch  = s16 * 2 + (mi & 1);
                ldsm4(bh[p], sw64(st + 8192, row, ch));
            }
            #pragma unroll
            for (int tm = 0; tm < 4; tm++)
                #pragma unroll
                for (int tn = 0; tn < 4; tn++)
                    mma_fp16(acc[tm][tn], ah[tm], &bh[tn >> 1][(tn & 1) * 2]);
        }
    }

    int g = lane >> 2, tc = lane & 3;
    #pragma unroll
    for (int tm = 0; tm < 4; tm++) {
        #pragma unroll
        for (int tn = 0; tn < 4; tn++) {
            int rr = row0 + wm + tm * 16 + g;
            int cc = col0 + wn + tn * 8 + tc * 2;
            #pragma unroll
            for (int half_ = 0; half_ < 2; half_++) {
                int r_ = rr + half_ * 8;
                float v0 = acc[tm][tn][half_ * 2 + 0];
                float v1 = acc[tm][tn][half_ * 2 + 1];
                size_t off = (size_t)r_ * N + cc;
                if (EPI == 2 || EPI == 4) {
                    float2 b2 = *(const float2*)(bias + cc);
                    float2 r2 = *(const float2*)(res + off);
                    v0 += b2.x + r2.x; v1 += b2.y + r2.y;
                    *(float2*)(Cf + off) = make_float2(v0, v1);
                } else if (EPI == 3) {
                    float2 b2 = *(const float2*)(bias + cc);
                    v0 = gelu_f(v0 + b2.x); v1 = gelu_f(v1 + b2.y);
                }
                if (EPI == 1 || EPI == 2 || EPI == 3) {
                    *(uint32_t*)(Chi + off) =
                        pack_h2(__float2half_rn(v0), __float2half_rn(v1));
                }
            }
        }
    }
}

// ---------------------------------------------------------------------------
// Fused flash attention, all single-pass fp16. Q resident (16KB);
// K/V 4-stage ring (64KB), 1 barrier/iter.
// grid (8 q-blocks, 128 z). 8 warps, 16 q-rows/warp.
// ---------------------------------------------------------------------------
#define FA_SMEM 81920

__global__ void __launch_bounds__(256, 1) flash_kernel(
    const fp16* __restrict__ qkvh, fp16* __restrict__ aoh)
{
    extern __shared__ char smem[];
    uint32_t sb = smem_u32(smem);
    int tid = threadIdx.x, wid = tid >> 5, lane = tid & 31;
    int mi = lane >> 3, lr = lane & 7;
    int g = lane >> 2, tc = lane & 3;
    int z = blockIdx.y;
    int b = z >> 6, h = (z >> 3) & 7, p = z & 7;
    int row0 = blockIdx.x * 128;
    size_t base = (size_t)((b * 8 + p)) * NSEQ * QKVW + h * 64;
    const fp16* Qh = qkvh + base;
    const fp16* Kh = qkvh + base + 512;
    const fp16* Vh = qkvh + base + 1024;

    uint32_t qoff = sb;           // Q 16KB
    uint32_t soff = sb + 16384;   // 4 stages x 16KB (Kh, Vh @ 8KB)

    // Q tile: 128 rows x 64 fp16, folded into stage-0 commit
    #pragma unroll
    for (int l = 0; l < 4; l++) {
        int idx = tid + l * 256;
        int r = idx >> 3, ch = idx & 7;
        CP_ASYNC_16(sw128(qoff, r, ch), Qh + (size_t)(row0 + r) * QKVW + ch * 8);
    }

    auto load_stage = [&](int c) {
        uint32_t st = soff + (c & 3) * 16384;
        int kv0 = c << 6;
        #pragma unroll
        for (int l = 0; l < 4; l++) {
            int idx = tid + l * 256;
            int mat = idx >> 9, r = (idx >> 3) & 63, ch = idx & 7;
            const fp16* src = (mat == 0 ? Kh : Vh) + (size_t)(kv0 + r) * QKVW + ch * 8;
            CP_ASYNC_16(sw128(st + mat * 8192, r, ch), src);
        }
        CP_COMMIT();
    };

    load_stage(0);   // commits {Q, stage0}
    load_stage(1);
    load_stage(2);

    float m_r[2] = {-1e30f, -1e30f};
    float l_r[2] = {0.f, 0.f};
    float O[8][4] = {};
    int qr0 = wid * 16;
    const float LS = SCALE * 1.4426950408889634f;

    for (int c = 0; c < 16; c++) {
        if (c == 15)      { CP_WAIT0(); }
        else if (c == 14) { CP_WAIT1(); }
        else              { CP_WAIT2(); }
        __syncthreads();
        if (c + 3 < 16) load_stage(c + 3);

        uint32_t st = soff + (c & 3) * 16384;
        uint32_t kh_o = st, vh_o = st + 8192;

        // S = Q K^T  (16x64 per warp), single pass
        float S[8][4] = {};
        #pragma unroll
        for (int ks = 0; ks < 4; ks++) {
            uint32_t ah[4];
            {
                int row = qr0 + ((mi & 1) << 3) + lr;
                int ch  = ks * 2 + (mi >> 1);
                ldsm4(ah, sw128(qoff, row, ch));
            }
            #pragma unroll
            for (int np = 0; np < 4; np++) {
                uint32_t bh[4];
                int row = np * 16 + ((mi >> 1) << 3) + lr;
                int ch  = ks * 2 + (mi & 1);
                ldsm4(bh, sw128(kh_o, row, ch));
                mma_fp16(S[np * 2],     ah, &bh[0]);
                mma_fp16(S[np * 2 + 1], ah, &bh[2]);
            }
        }

        // online softmax (log2 domain)
        #pragma unroll
        for (int hf = 0; hf < 2; hf++) {
            float mx = -1e30f;
            #pragma unroll
            for (int j = 0; j < 8; j++) {
                S[j][hf * 2]     *= LS;
                S[j][hf * 2 + 1] *= LS;
                mx = fmaxf(mx, fmaxf(S[j][hf * 2], S[j][hf * 2 + 1]));
            }
            mx = fmaxf(mx, __shfl_xor_sync(0xffffffffu, mx, 1));
            mx = fmaxf(mx, __shfl_xor_sync(0xffffffffu, mx, 2));
            float mnew = fmaxf(m_r[hf], mx);
            float alpha = exp2f(m_r[hf] - mnew);
            m_r[hf] = mnew;
            float s = 0.f;
            #pragma unroll
            for (int j = 0; j < 8; j++) {
                float p0 = exp2f(S[j][hf * 2]     - mnew);
                float p1 = exp2f(S[j][hf * 2 + 1] - mnew);
                S[j][hf * 2] = p0; S[j][hf * 2 + 1] = p1;
                s += p0 + p1;
            }
            s += __shfl_xor_sync(0xffffffffu, s, 1);
            s += __shfl_xor_sync(0xffffffffu, s, 2);
            l_r[hf] = l_r[hf] * alpha + s;
            #pragma unroll
            for (int j = 0; j < 8; j++) {
                O[j][hf * 2]     *= alpha;
                O[j][hf * 2 + 1] *= alpha;
            }
        }

        // pack P hi (C-frag -> A-frag correspondence)
        uint32_t ph[4][4];
        #pragma unroll
        for (int s_ = 0; s_ < 4; s_++) {
            #pragma unroll
            for (int q4 = 0; q4 < 4; q4++) {
                int j  = s_ * 2 + (q4 >> 1);
                int k0 = (q4 & 1) * 2;
                ph[s_][q4] = pack_h2(__float2half_rn(S[j][k0]),
                                     __float2half_rn(S[j][k0 + 1]));
            }
        }

        // O += P V  (single pass), V via ldmatrix.trans
        #pragma unroll
        for (int s_ = 0; s_ < 4; s_++) {
            #pragma unroll
            for (int dp = 0; dp < 4; dp++) {
                uint32_t vhh[4];
                int row = s_ * 16 + ((mi & 1) << 3) + lr;
                int chk = dp * 2 + (mi >> 1);
                ldsm4t(vhh, sw128(vh_o, row, chk));
                mma_fp16(O[dp * 2],     ph[s_], &vhh[0]);
                mma_fp16(O[dp * 2 + 1], ph[s_], &vhh[2]);
            }
        }
    }

    float inv0 = 1.0f / l_r[0], inv1 = 1.0f / l_r[1];
    size_t obase = (size_t)(b * 8 + h) * NSEQ;
    #pragma unroll
    for (int dp = 0; dp < 8; dp++) {
        int d = dp * 8 + tc * 2;
        #pragma unroll
        for (int hf = 0; hf < 2; hf++) {
            float inv = hf ? inv1 : inv0;
            int n = row0 + qr0 + g + hf * 8;
            float v0 = O[dp][hf * 2]     * inv;
            float v1 = O[dp][hf * 2 + 1] * inv;
            size_t off = (obase + n) * DIM + p * 64 + d;
            *(uint32_t*)(aoh + off) =
                pack_h2(__float2half_rn(v0), __float2half_rn(v1));
        }
    }
}

// ---------------------------------------------------------------------------
// Fused weight transpose + cast for all 4 weights: W[K,N] fp32 -> T[N,K] fp16
// ---------------------------------------------------------------------------
__global__ void __launch_bounds__(256) tcast_all(
    const float* __restrict__ Wq, fp16* __restrict__ Tq,
    const float* __restrict__ Wo, fp16* __restrict__ To,
    const float* __restrict__ W1, fp16* __restrict__ T1,
    const float* __restrict__ W2, fp16* __restrict__ T2)
{
    int id = blockIdx.x * 256 + threadIdx.x;
    const int S0 = 512 * 1536, S1 = S0 + 512 * 512, S2 = S1 + 512 * 2048;
    const float* W; fp16* T; int K, N, i;
    if (id < S0)      { W = Wq; T = Tq; K = 512;  N = 1536; i = id; }
    else if (id < S1) { W = Wo; T = To; K = 512;  N = 512;  i = id - S0; }
    else if (id < S2) { W = W1; T = T1; K = 512;  N = 2048; i = id - S1; }
    else              { W = W2; T = T2; K = 2048; N = 512;  i = id - S2; }
    int n = i / K, k = i - n * K;
    T[i] = __float2half_rn(W[(size_t)k * N + n]);
}

// ---------------------------------------------------------------------------
// LN0 + LN1
// ---------------------------------------------------------------------------
__device__ __forceinline__ float block_sum(float v, float* sm) {
    #pragma unroll
    for (int o = 16; o > 0; o >>= 1) v += __shfl_down_sync(0xffffffffu, v, o);
    int lane = threadIdx.x & 31, wid = threadIdx.x >> 5;
    if (lane == 0) sm[wid] = v;
    __syncthreads();
    v = (threadIdx.x < 8) ? sm[threadIdx.x] : 0.0f;
    if (wid == 0) {
        #pragma unroll
        for (int o = 4; o > 0; o >>= 1) v += __shfl_down_sync(0xffffffffu, v, o);
        if (lane == 0) sm[0] = v;
    }
    __syncthreads();
    float r = sm[0];
    __syncthreads();
    return r;
}

__global__ void __launch_bounds__(256) ln_kernel(
    const float* __restrict__ x,
    const float* __restrict__ w0, const float* __restrict__ b0,
    const float* __restrict__ w1, const float* __restrict__ b1,
    float* __restrict__ xn, fp16* __restrict__ hh)
{
    __shared__ float sm[32];
    size_t row = blockIdx.x;
    const float* xr = x + row * DIM;
    int t = threadIdx.x;

    float v0 = xr[t], v1 = xr[t + 256];
    float mu = block_sum(v0 + v1, sm) * (1.0f / DIM);
    float d0 = v0 - mu, d1 = v1 - mu;
    float var = block_sum(d0 * d0 + d1 * d1, sm) * (1.0f / DIM);
    float r = rsqrtf(var + EPS);
    float y0 = d0 * r * w0[t] + b0[t];
    float y1 = d1 * r * w0[t + 256] + b0[t + 256];
    xn[row * DIM + t]       = y0;
    xn[row * DIM + t + 256] = y1;

    float mu2 = block_sum(y0 + y1, sm) * (1.0f / DIM);
    float e0 = y0 - mu2, e1 = y1 - mu2;
    float var2 = block_sum(e0 * e0 + e1 * e1, sm) * (1.0f / DIM);
    float r2 = rsqrtf(var2 + EPS);
    hh[row * DIM + t]       = __float2half_rn(e0 * r2 * w1[t] + b1[t]);
    hh[row * DIM + t + 256] = __float2half_rn(e1 * r2 * w1[t + 256] + b1[t + 256]);
}

// ---------------------------------------------------------------------------
// Launch
// ---------------------------------------------------------------------------
extern "C" void kernel_launch(void* const* d_in, const int* in_sizes, int n_in,
                              void* d_out, int out_size)
{
    (void)in_sizes; (void)n_in; (void)out_size;
    const float* x     = (const float*)d_in[0];
    const float* ln0_w = (const float*)d_in[1];
    const float* ln0_b = (const float*)d_in[2];
    const float* ln1_w = (const float*)d_in[3];
    const float* ln1_b = (const float*)d_in[4];
    const float* w_qkv = (const float*)d_in[5];
    const float* w_o   = (const float*)d_in[6];
    const float* b_o   = (const float*)d_in[7];
    const float* w1    = (const float*)d_in[8];
    const float* b1    = (const float*)d_in[9];
    const float* w2    = (const float*)d_in[10];
    const float* b2    = (const float*)d_in[11];
    float* out = (float*)d_out;

    void *p;
    cudaGetSymbolAddress(&p, g_xn);    float* xn   = (float*)p;
    cudaGetSymbolAddress(&p, g_hh);    fp16* hh    = (fp16*)p;
    cudaGetSymbolAddress(&p, g_qkvh);  fp16* qkvh  = (fp16*)p;
    cudaGetSymbolAddress(&p, g_aoh);   fp16* aoh   = (fp16*)p;
    cudaGetSymbolAddress(&p, g_x2);    float* x2   = (float*)p;
    cudaGetSymbolAddress(&p, g_x2h);   fp16* x2h   = (fp16*)p;
    cudaGetSymbolAddress(&p, g_midh);  fp16* midh  = (fp16*)p;
    cudaGetSymbolAddress(&p, g_wqkvt); fp16* wqkvt = (fp16*)p;
    cudaGetSymbolAddress(&p, g_wot);   fp16* wot   = (fp16*)p;
    cudaGetSymbolAddress(&p, g_w1t);   fp16* w1t   = (fp16*)p;
    cudaGetSymbolAddress(&p, g_w2t);   fp16* w2t   = (fp16*)p;

    cudaFuncSetAttribute(mma_gemm<1>, cudaFuncAttributeMaxDynamicSharedMemorySize, GSMEM);
    cudaFuncSetAttribute(mma_gemm<2>, cudaFuncAttributeMaxDynamicSharedMemorySize, GSMEM);
    cudaFuncSetAttribute(mma_gemm<3>, cudaFuncAttributeMaxDynamicSharedMemorySize, GSMEM);
    cudaFuncSetAttribute(mma_gemm<4>, cudaFuncAttributeMaxDynamicSharedMemorySize, GSMEM);
    cudaFuncSetAttribute(flash_kernel, cudaFuncAttributeMaxDynamicSharedMemorySize, FA_SMEM);

    // weight prep (one fused transpose+cast launch)
    tcast_all<<<12288, 256>>>(w_qkv, wqkvt, w_o, wot, w1, w1t, w2, w2t);

    // 1) LN0 + LN1
    ln_kernel<<<ROWS, 256>>>(x, ln0_w, ln0_b, ln1_w, ln1_b, xn, hh);
    // 2) qkv = h @ w_qkv  (hi out)
    mma_gemm<1><<<dim3(QKVW / 128, ROWS / 128), 256, GSMEM>>>(
        hh, wqkvt, ROWS, QKVW, DIM, DIM, DIM,
        nullptr, nullptr, nullptr, qkvh);
    // 3) fused attention
    flash_kernel<<<dim3(8, NZ), 256, FA_SMEM>>>(qkvh, aoh);
    // 4) x2 = ao @ w_o + b_o + xn  (fp32 + hi)
    mma_gemm<2><<<dim3(DIM / 128, ROWS / 128), 256, GSMEM>>>(
        aoh, wot, ROWS, DIM, INNER, INNER, INNER,
        b_o, xn, x2, x2h);
    // 5) mid = gelu(x2 @ w1 + b1)  (hi out)
    mma_gemm<3><<<dim3(HIDDEN / 128, ROWS / 128), 256, GSMEM>>>(
        x2h, w1t, ROWS, HIDDEN, DIM, DIM, DIM,
        b1, nullptr, nullptr, midh);
    // 6) out = mid @ w2 + b2 + x2  (fp32)
    mma_gemm<4><<<dim3(DIM / 128, ROWS / 128), 256, GSMEM>>>(
        midh, w2t, ROWS, DIM, HIDDEN, HIDDEN, HIDDEN,
        b2, x2, out, nullptr);
}

// round 9
// speedup vs baseline: 12.8575x; 1.0440x over previous
#include <cuda_runtime.h>
#include <cuda_fp16.h>
#include <cstdint>
#include <math.h>

// ---------------------------------------------------------------------------
// ViT transformer block. fp16 single-pass mma.sync everywhere.
// Dense GEMMs: 4-stage cp.async ring, 1 barrier/iter, 2 CTAs/SM.
// Flash attention: Q resident, K/V 4-stage ring, 1 barrier/iter, 2 CTAs/SM,
// softmax scale pre-folded into q weights.
// ---------------------------------------------------------------------------

#define ROWS   16384
#define DIM    512
#define INNER  512
#define QKVW   1536
#define HIDDEN 2048
#define NSEQ   1024
#define NZ     128
#define SCALE  0.125f
#define EPS    1e-5f

typedef __half fp16;

// ------------------------- device scratch ---------------------------------
__device__ __align__(256) float g_xn  [(size_t)ROWS * DIM];
__device__ __align__(256) fp16  g_hh  [(size_t)ROWS * DIM];
__device__ __align__(256) fp16  g_qkvh[(size_t)ROWS * QKVW];
__device__ __align__(256) fp16  g_aoh [(size_t)ROWS * DIM];
__device__ __align__(256) float g_x2  [(size_t)ROWS * DIM];
__device__ __align__(256) fp16  g_x2h [(size_t)ROWS * DIM];
__device__ __align__(256) fp16  g_midh[(size_t)ROWS * HIDDEN];
// transposed weights [N, K], fp16
__device__ __align__(256) fp16  g_wqkvt[(size_t)QKVW * DIM];
__device__ __align__(256) fp16  g_wot  [(size_t)DIM * INNER];
__device__ __align__(256) fp16  g_w1t  [(size_t)HIDDEN * DIM];
__device__ __align__(256) fp16  g_w2t  [(size_t)DIM * HIDDEN];

// ------------------------- PTX helpers ------------------------------------
__device__ __forceinline__ uint32_t smem_u32(const void* p) {
    uint32_t a;
    asm("{ .reg .u64 t; cvta.to.shared.u64 t, %1; cvt.u32.u64 %0, t; }"
        : "=r"(a) : "l"(p));
    return a;
}
#define CP_ASYNC_16(sa, ga) \
    asm volatile("cp.async.cg.shared.global [%0], [%1], 16;" \
                 :: "r"((uint32_t)(sa)), "l"(ga) : "memory")
#define CP_COMMIT() asm volatile("cp.async.commit_group;" ::: "memory")
#define CP_WAIT0()  asm volatile("cp.async.wait_group 0;" ::: "memory")
#define CP_WAIT1()  asm volatile("cp.async.wait_group 1;" ::: "memory")
#define CP_WAIT2()  asm volatile("cp.async.wait_group 2;" ::: "memory")

__device__ __forceinline__ void ldsm4(uint32_t* r, uint32_t addr) {
    asm volatile("ldmatrix.sync.aligned.m8n8.x4.shared.b16 {%0,%1,%2,%3}, [%4];"
        : "=r"(r[0]), "=r"(r[1]), "=r"(r[2]), "=r"(r[3]) : "r"(addr));
}
__device__ __forceinline__ void ldsm4t(uint32_t* r, uint32_t addr) {
    asm volatile("ldmatrix.sync.aligned.m8n8.x4.trans.shared.b16 {%0,%1,%2,%3}, [%4];"
        : "=r"(r[0]), "=r"(r[1]), "=r"(r[2]), "=r"(r[3]) : "r"(addr));
}
__device__ __forceinline__ void mma_fp16(float* c, const uint32_t* a, const uint32_t* b) {
    asm volatile(
        "mma.sync.aligned.m16n8k16.row.col.f32.f16.f16.f32 "
        "{%0,%1,%2,%3}, {%4,%5,%6,%7}, {%8,%9}, {%0,%1,%2,%3};"
        : "+f"(c[0]), "+f"(c[1]), "+f"(c[2]), "+f"(c[3])
        : "r"(a[0]), "r"(a[1]), "r"(a[2]), "r"(a[3]), "r"(b[0]), "r"(b[1]));
}

__device__ __forceinline__ float gelu_f(float x) {
    return 0.5f * x * (1.0f + erff(x * 0.7071067811865475f));
}
__device__ __forceinline__ uint32_t pack_h2(fp16 a, fp16 b) {
    __half2 t = __halves2half2(a, b);
    return *(uint32_t*)&t;
}

// swizzled smem addr for a 64B-row tile (rows x 32 fp16)
__device__ __forceinline__ uint32_t sw64(uint32_t base, int row, int chunk) {
    return base + row * 64 + ((chunk ^ ((row >> 1) & 3)) << 4);
}
// swizzled smem addr for a 128B-row tile (rows x 64 fp16)
__device__ __forceinline__ uint32_t sw128(uint32_t base, int row, int chunk) {
    return base + row * 128 + ((chunk ^ (row & 7)) << 4);
}

// ---------------------------------------------------------------------------
// Single-pass fp16 GEMM: C[M,N] = A[M,K] @ Bt[N,K]^T
// BM=128, BN=128, BK=32, 4-stage ring, 1 barrier/iter, 2 CTAs/SM.
// ---------------------------------------------------------------------------
#define GSTAGE 16384
#define GSMEM  (4 * GSTAGE)

template <int EPI>
__global__ void __launch_bounds__(256, 2) mma_gemm(
    const fp16* __restrict__ Ahi, const fp16* __restrict__ Bhi,
    int M, int N, int K, int lda, int ldb,
    const float* __restrict__ bias, const float* __restrict__ res,
    float* __restrict__ Cf, fp16* __restrict__ Chi)
{
    extern __shared__ char smem[];
    uint32_t sb = smem_u32(smem);
    int tid = threadIdx.x, wid = tid >> 5, lane = tid & 31;
    int row0 = blockIdx.y * 128, col0 = blockIdx.x * 128;

    const int NC = K >> 5;

    auto load_stage = [&](int c) {
        uint32_t st = sb + (c & 3) * GSTAGE;
        int k0 = c << 5;
        #pragma unroll
        for (int l = 0; l < 4; l++) {
            int idx = tid + l * 256;
            int mat = idx >> 9, r = (idx >> 2) & 127, ch = idx & 3;
            uint32_t dst = sw64(st + mat * 8192, r, ch);
            const fp16* src = mat == 0
                ? Ahi + (size_t)(row0 + r) * lda + k0 + ch * 8
                : Bhi + (size_t)(col0 + r) * ldb + k0 + ch * 8;
            CP_ASYNC_16(dst, src);
        }
        CP_COMMIT();
    };

    float acc[4][4][4] = {};
    int mi = lane >> 3, lr = lane & 7;
    int wm = (wid >> 2) * 64;
    int wn = (wid & 3) * 32;

    load_stage(0);
    load_stage(1);
    load_stage(2);

    for (int c = 0; c < NC; c++) {
        if (c + 1 == NC)      { CP_WAIT0(); }
        else if (c + 2 == NC) { CP_WAIT1(); }
        else                  { CP_WAIT2(); }
        __syncthreads();
        if (c + 3 < NC) load_stage(c + 3);

        uint32_t st = sb + (c & 3) * GSTAGE;
        #pragma unroll
        for (int s16 = 0; s16 < 2; s16++) {
            uint32_t ah[4][4], bh[2][4];
            #pragma unroll
            for (int t = 0; t < 4; t++) {
                int row = wm + t * 16 + ((mi & 1) << 3) + lr;
                int ch  = s16 * 2 + (mi >> 1);
                ldsm4(ah[t], sw64(st, row, ch));
            }
            #pragma unroll
            for (int p = 0; p < 2; p++) {
                int row = wn + p * 16 + ((mi >> 1) << 3) + lr;
                int ch  = s16 * 2 + (mi & 1);
                ldsm4(bh[p], sw64(st + 8192, row, ch));
            }
            #pragma unroll
            for (int tm = 0; tm < 4; tm++)
                #pragma unroll
                for (int tn = 0; tn < 4; tn++)
                    mma_fp16(acc[tm][tn], ah[tm], &bh[tn >> 1][(tn & 1) * 2]);
        }
    }

    int g = lane >> 2, tc = lane & 3;
    #pragma unroll
    for (int tm = 0; tm < 4; tm++) {
        #pragma unroll
        for (int tn = 0; tn < 4; tn++) {
            int rr = row0 + wm + tm * 16 + g;
            int cc = col0 + wn + tn * 8 + tc * 2;
            #pragma unroll
            for (int half_ = 0; half_ < 2; half_++) {
                int r_ = rr + half_ * 8;
                float v0 = acc[tm][tn][half_ * 2 + 0];
                float v1 = acc[tm][tn][half_ * 2 + 1];
                size_t off = (size_t)r_ * N + cc;
                if (EPI == 2 || EPI == 4) {
                    float2 b2 = *(const float2*)(bias + cc);
                    float2 r2 = *(const float2*)(res + off);
                    v0 += b2.x + r2.x; v1 += b2.y + r2.y;
                    *(float2*)(Cf + off) = make_float2(v0, v1);
                } else if (EPI == 3) {
                    float2 b2 = *(const float2*)(bias + cc);
                    v0 = gelu_f(v0 + b2.x); v1 = gelu_f(v1 + b2.y);
                }
                if (EPI == 1 || EPI == 2 || EPI == 3) {
                    *(uint32_t*)(Chi + off) =
                        pack_h2(__float2half_rn(v0), __float2half_rn(v1));
                }
            }
        }
    }
}

// ---------------------------------------------------------------------------
// Fused flash attention. Q (pre-scaled by SCALE*log2e) resident in smem;
// K/V 4-stage ring, 1 barrier/iter, 2 CTAs/SM.
// ---------------------------------------------------------------------------
#define FA_SMEM 81920

__global__ void __launch_bounds__(256, 2) flash_kernel(
    const fp16* __restrict__ qkvh, fp16* __restrict__ aoh)
{
    extern __shared__ char smem[];
    uint32_t sb = smem_u32(smem);
    int tid = threadIdx.x, wid = tid >> 5, lane = tid & 31;
    int mi = lane >> 3, lr = lane & 7;
    int g = lane >> 2, tc = lane & 3;
    int z = blockIdx.y;
    int b = z >> 6, h = (z >> 3) & 7, p = z & 7;
    int row0 = blockIdx.x * 128;
    size_t base = (size_t)((b * 8 + p)) * NSEQ * QKVW + h * 64;
    const fp16* Qh = qkvh + base;
    const fp16* Kh = qkvh + base + 512;
    const fp16* Vh = qkvh + base + 1024;

    uint32_t qoff = sb;           // Q 16KB
    uint32_t soff = sb + 16384;   // 4 stages x 16KB (Kh, Vh @ 8KB)

    #pragma unroll
    for (int l = 0; l < 4; l++) {
        int idx = tid + l * 256;
        int r = idx >> 3, ch = idx & 7;
        CP_ASYNC_16(sw128(qoff, r, ch), Qh + (size_t)(row0 + r) * QKVW + ch * 8);
    }

    auto load_stage = [&](int c) {
        uint32_t st = soff + (c & 3) * 16384;
        int kv0 = c << 6;
        #pragma unroll
        for (int l = 0; l < 4; l++) {
            int idx = tid + l * 256;
            int mat = idx >> 9, r = (idx >> 3) & 63, ch = idx & 7;
            const fp16* src = (mat == 0 ? Kh : Vh) + (size_t)(kv0 + r) * QKVW + ch * 8;
            CP_ASYNC_16(sw128(st + mat * 8192, r, ch), src);
        }
        CP_COMMIT();
    };

    load_stage(0);   // commits {Q, stage0}
    load_stage(1);
    load_stage(2);

    float m_r[2] = {-1e30f, -1e30f};
    float l_r[2] = {0.f, 0.f};
    float O[8][4] = {};
    int qr0 = wid * 16;

    for (int c = 0; c < 16; c++) {
        if (c == 15)      { CP_WAIT0(); }
        else if (c == 14) { CP_WAIT1(); }
        else              { CP_WAIT2(); }
        __syncthreads();
        if (c + 3 < 16) load_stage(c + 3);

        uint32_t st = soff + (c & 3) * 16384;
        uint32_t kh_o = st, vh_o = st + 8192;

        // S = Q K^T (scale pre-folded into Q), 16x64 per warp
        float S[8][4] = {};
        #pragma unroll
        for (int ks = 0; ks < 4; ks++) {
            uint32_t ah[4];
            {
                int row = qr0 + ((mi & 1) << 3) + lr;
                int ch  = ks * 2 + (mi >> 1);
                ldsm4(ah, sw128(qoff, row, ch));
            }
            #pragma unroll
            for (int np = 0; np < 4; np++) {
                uint32_t bh[4];
                int row = np * 16 + ((mi >> 1) << 3) + lr;
                int ch  = ks * 2 + (mi & 1);
                ldsm4(bh, sw128(kh_o, row, ch));
                mma_fp16(S[np * 2],     ah, &bh[0]);
                mma_fp16(S[np * 2 + 1], ah, &bh[2]);
            }
        }

        // online softmax (log2 domain, S already scaled)
        #pragma unroll
        for (int hf = 0; hf < 2; hf++) {
            float mx = -1e30f;
            #pragma unroll
            for (int j = 0; j < 8; j++)
                mx = fmaxf(mx, fmaxf(S[j][hf * 2], S[j][hf * 2 + 1]));
            mx = fmaxf(mx, __shfl_xor_sync(0xffffffffu, mx, 1));
            mx = fmaxf(mx, __shfl_xor_sync(0xffffffffu, mx, 2));
            float mnew = fmaxf(m_r[hf], mx);
            float alpha = exp2f(m_r[hf] - mnew);
            m_r[hf] = mnew;
            float s = 0.f;
            #pragma unroll
            for (int j = 0; j < 8; j++) {
                float p0 = exp2f(S[j][hf * 2]     - mnew);
                float p1 = exp2f(S[j][hf * 2 + 1] - mnew);
                S[j][hf * 2] = p0; S[j][hf * 2 + 1] = p1;
                s += p0 + p1;
            }
            s += __shfl_xor_sync(0xffffffffu, s, 1);
            s += __shfl_xor_sync(0xffffffffu, s, 2);
            l_r[hf] = l_r[hf] * alpha + s;
            #pragma unroll
            for (int j = 0; j < 8; j++) {
                O[j][hf * 2]     *= alpha;
                O[j][hf * 2 + 1] *= alpha;
            }
        }

        // pack P hi (C-frag -> A-frag correspondence)
        uint32_t ph[4][4];
        #pragma unroll
        for (int s_ = 0; s_ < 4; s_++) {
            #pragma unroll
            for (int q4 = 0; q4 < 4; q4++) {
                int j  = s_ * 2 + (q4 >> 1);
                int k0 = (q4 & 1) * 2;
                ph[s_][q4] = pack_h2(__float2half_rn(S[j][k0]),
                                     __float2half_rn(S[j][k0 + 1]));
            }
        }

        // O += P V, V via ldmatrix.trans
        #pragma unroll
        for (int s_ = 0; s_ < 4; s_++) {
            #pragma unroll
            for (int dp = 0; dp < 4; dp++) {
                uint32_t vhh[4];
                int row = s_ * 16 + ((mi & 1) << 3) + lr;
                int chk = dp * 2 + (mi >> 1);
                ldsm4t(vhh, sw128(vh_o, row, chk));
                mma_fp16(O[dp * 2],     ph[s_], &vhh[0]);
                mma_fp16(O[dp * 2 + 1], ph[s_], &vhh[2]);
            }
        }
    }

    float inv0 = 1.0f / l_r[0], inv1 = 1.0f / l_r[1];
    size_t obase = (size_t)(b * 8 + h) * NSEQ;
    #pragma unroll
    for (int dp = 0; dp < 8; dp++) {
        int d = dp * 8 + tc * 2;
        #pragma unroll
        for (int hf = 0; hf < 2; hf++) {
            float inv = hf ? inv1 : inv0;
            int n = row0 + qr0 + g + hf * 8;
            float v0 = O[dp][hf * 2]     * inv;
            float v1 = O[dp][hf * 2 + 1] * inv;
            size_t off = (obase + n) * DIM + p * 64 + d;
            *(uint32_t*)(aoh + off) =
                pack_h2(__float2half_rn(v0), __float2half_rn(v1));
        }
    }
}

// ---------------------------------------------------------------------------
// Fused weight transpose + cast. q-columns of wqkv (n < 512) pre-scaled
// by SCALE * log2(e) so flash softmax needs no scale multiply.
// ---------------------------------------------------------------------------
__global__ void __launch_bounds__(256) tcast_all(
    const float* __restrict__ Wq, fp16* __restrict__ Tq,
    const float* __restrict__ Wo, fp16* __restrict__ To,
    const float* __restrict__ W1, fp16* __restrict__ T1,
    const float* __restrict__ W2, fp16* __restrict__ T2)
{
    int id = blockIdx.x * 256 + threadIdx.x;
    const int S0 = 512 * 1536, S1 = S0 + 512 * 512, S2 = S1 + 512 * 2048;
    const float* W; fp16* T; int K, N, i;
    bool qscale = false;
    if (id < S0)      { W = Wq; T = Tq; K = 512;  N = 1536; i = id; qscale = true; }
    else if (id < S1) { W = Wo; T = To; K = 512;  N = 512;  i = id - S0; }
    else if (id < S2) { W = W1; T = T1; K = 512;  N = 2048; i = id - S1; }
    else              { W = W2; T = T2; K = 2048; N = 512;  i = id - S2; }
    int n = i / K, k = i - n * K;
    float v = W[(size_t)k * N + n];
    if (qscale && n < 512) v *= SCALE * 1.4426950408889634f;
    T[i] = __float2half_rn(v);
}

// ---------------------------------------------------------------------------
// LN0 + LN1
// ---------------------------------------------------------------------------
__device__ __forceinline__ float block_sum(float v, float* sm) {
    #pragma unroll
    for (int o = 16; o > 0; o >>= 1) v += __shfl_down_sync(0xffffffffu, v, o);
    int lane = threadIdx.x & 31, wid = threadIdx.x >> 5;
    if (lane == 0) sm[wid] = v;
    __syncthreads();
    v = (threadIdx.x < 8) ? sm[threadIdx.x] : 0.0f;
    if (wid == 0) {
        #pragma unroll
        for (int o = 4; o > 0; o >>= 1) v += __shfl_down_sync(0xffffffffu, v, o);
        if (lane == 0) sm[0] = v;
    }
    __syncthreads();
    float r = sm[0];
    __syncthreads();
    return r;
}

__global__ void __launch_bounds__(256) ln_kernel(
    const float* __restrict__ x,
    const float* __restrict__ w0, const float* __restrict__ b0,
    const float* __restrict__ w1, const float* __restrict__ b1,
    float* __restrict__ xn, fp16* __restrict__ hh)
{
    __shared__ float sm[32];
    size_t row = blockIdx.x;
    const float* xr = x + row * DIM;
    int t = threadIdx.x;

    float v0 = xr[t], v1 = xr[t + 256];
    float mu = block_sum(v0 + v1, sm) * (1.0f / DIM);
    float d0 = v0 - mu, d1 = v1 - mu;
    float var = block_sum(d0 * d0 + d1 * d1, sm) * (1.0f / DIM);
    float r = rsqrtf(var + EPS);
    float y0 = d0 * r * w0[t] + b0[t];
    float y1 = d1 * r * w0[t + 256] + b0[t + 256];
    xn[row * DIM + t]       = y0;
    xn[row * DIM + t + 256] = y1;

    float mu2 = block_sum(y0 + y1, sm) * (1.0f / DIM);
    float e0 = y0 - mu2, e1 = y1 - mu2;
    float var2 = block_sum(e0 * e0 + e1 * e1, sm) * (1.0f / DIM);
    float r2 = rsqrtf(var2 + EPS);
    hh[row * DIM + t]       = __float2half_rn(e0 * r2 * w1[t] + b1[t]);
    hh[row * DIM + t + 256] = __float2half_rn(e1 * r2 * w1[t + 256] + b1[t + 256]);
}

// ---------------------------------------------------------------------------
// Launch
// ---------------------------------------------------------------------------
extern "C" void kernel_launch(void* const* d_in, const int* in_sizes, int n_in,
                              void* d_out, int out_size)
{
    (void)in_sizes; (void)n_in; (void)out_size;
    const float* x     = (const float*)d_in[0];
    const float* ln0_w = (const float*)d_in[1];
    const float* ln0_b = (const float*)d_in[2];
    const float* ln1_w = (const float*)d_in[3];
    const float* ln1_b = (const float*)d_in[4];
    const float* w_qkv = (const float*)d_in[5];
    const float* w_o   = (const float*)d_in[6];
    const float* b_o   = (const float*)d_in[7];
    const float* w1    = (const float*)d_in[8];
    const float* b1    = (const float*)d_in[9];
    const float* w2    = (const float*)d_in[10];
    const float* b2    = (const float*)d_in[11];
    float* out = (float*)d_out;

    void *p;
    cudaGetSymbolAddress(&p, g_xn);    float* xn   = (float*)p;
    cudaGetSymbolAddress(&p, g_hh);    fp16* hh    = (fp16*)p;
    cudaGetSymbolAddress(&p, g_qkvh);  fp16* qkvh  = (fp16*)p;
    cudaGetSymbolAddress(&p, g_aoh);   fp16* aoh   = (fp16*)p;
    cudaGetSymbolAddress(&p, g_x2);    float* x2   = (float*)p;
    cudaGetSymbolAddress(&p, g_x2h);   fp16* x2h   = (fp16*)p;
    cudaGetSymbolAddress(&p, g_midh);  fp16* midh  = (fp16*)p;
    cudaGetSymbolAddress(&p, g_wqkvt); fp16* wqkvt = (fp16*)p;
    cudaGetSymbolAddress(&p, g_wot);   fp16* wot   = (fp16*)p;
    cudaGetSymbolAddress(&p, g_w1t);   fp16* w1t   = (fp16*)p;
    cudaGetSymbolAddress(&p, g_w2t);   fp16* w2t   = (fp16*)p;

    cudaFuncSetAttribute(mma_gemm<1>, cudaFuncAttributeMaxDynamicSharedMemorySize, GSMEM);
    cudaFuncSetAttribute(mma_gemm<2>, cudaFuncAttributeMaxDynamicSharedMemorySize, GSMEM);
    cudaFuncSetAttribute(mma_gemm<3>, cudaFuncAttributeMaxDynamicSharedMemorySize, GSMEM);
    cudaFuncSetAttribute(mma_gemm<4>, cudaFuncAttributeMaxDynamicSharedMemorySize, GSMEM);
    cudaFuncSetAttribute(flash_kernel, cudaFuncAttributeMaxDynamicSharedMemorySize, FA_SMEM);

    // weight prep
    tcast_all<<<12288, 256>>>(w_qkv, wqkvt, w_o, wot, w1, w1t, w2, w2t);

    // 1) LN0 + LN1
    ln_kernel<<<ROWS, 256>>>(x, ln0_w, ln0_b, ln1_w, ln1_b, xn, hh);
    // 2) qkv = h @ w_qkv  (hi out; q pre-scaled)
    mma_gemm<1><<<dim3(QKVW / 128, ROWS / 128), 256, GSMEM>>>(
        hh, wqkvt, ROWS, QKVW, DIM, DIM, DIM,
        nullptr, nullptr, nullptr, qkvh);
    // 3) fused attention
    flash_kernel<<<dim3(8, NZ), 256, FA_SMEM>>>(qkvh, aoh);
    // 4) x2 = ao @ w_o + b_o + xn  (fp32 + hi)
    mma_gemm<2><<<dim3(DIM / 128, ROWS / 128), 256, GSMEM>>>(
        aoh, wot, ROWS, DIM, INNER, INNER, INNER,
        b_o, xn, x2, x2h);
    // 5) mid = gelu(x2 @ w1 + b1)  (hi out)
    mma_gemm<3><<<dim3(HIDDEN / 128, ROWS / 128), 256, GSMEM>>>(
        x2h, w1t, ROWS, HIDDEN, DIM, DIM, DIM,
        b1, nullptr, nullptr, midh);
    // 6) out = mid @ w2 + b2 + x2  (fp32)
    mma_gemm<4><<<dim3(DIM / 128, ROWS / 128), 256, GSMEM>>>(
        midh, w2t, ROWS, DIM, HIDDEN, HIDDEN, HIDDEN,
        b2, x2, out, nullptr);
}

// round 10
// speedup vs baseline: 13.5160x; 1.0512x over previous
#include <cuda_runtime.h>
#include <cuda_fp16.h>
#include <cstdint>
#include <math.h>

// ---------------------------------------------------------------------------
// ViT transformer block. fp16 single-pass mma.sync everywhere.
// Dense GEMMs: BK=64, 3-stage cp.async ring, 1 barrier/iter, 2 CTAs/SM.
// Flash attention: 128-thread CTAs, 64 q-rows, Q resident, K/V 3-stage ring,
// 4 CTAs/SM, softmax scale pre-folded into q weights.
// ---------------------------------------------------------------------------

#define ROWS   16384
#define DIM    512
#define INNER  512
#define QKVW   1536
#define HIDDEN 2048
#define NSEQ   1024
#define NZ     128
#define SCALE  0.125f
#define EPS    1e-5f

typedef __half fp16;

// ------------------------- device scratch ---------------------------------
__device__ __align__(256) float g_xn  [(size_t)ROWS * DIM];
__device__ __align__(256) fp16  g_hh  [(size_t)ROWS * DIM];
__device__ __align__(256) fp16  g_qkvh[(size_t)ROWS * QKVW];
__device__ __align__(256) fp16  g_aoh [(size_t)ROWS * DIM];
__device__ __align__(256) float g_x2  [(size_t)ROWS * DIM];
__device__ __align__(256) fp16  g_x2h [(size_t)ROWS * DIM];
__device__ __align__(256) fp16  g_midh[(size_t)ROWS * HIDDEN];
// transposed weights [N, K], fp16
__device__ __align__(256) fp16  g_wqkvt[(size_t)QKVW * DIM];
__device__ __align__(256) fp16  g_wot  [(size_t)DIM * INNER];
__device__ __align__(256) fp16  g_w1t  [(size_t)HIDDEN * DIM];
__device__ __align__(256) fp16  g_w2t  [(size_t)DIM * HIDDEN];

// ------------------------- PTX helpers ------------------------------------
__device__ __forceinline__ uint32_t smem_u32(const void* p) {
    uint32_t a;
    asm("{ .reg .u64 t; cvta.to.shared.u64 t, %1; cvt.u32.u64 %0, t; }"
        : "=r"(a) : "l"(p));
    return a;
}
#define CP_ASYNC_16(sa, ga) \
    asm volatile("cp.async.cg.shared.global [%0], [%1], 16;" \
                 :: "r"((uint32_t)(sa)), "l"(ga) : "memory")
#define CP_COMMIT() asm volatile("cp.async.commit_group;" ::: "memory")
#define CP_WAIT0()  asm volatile("cp.async.wait_group 0;" ::: "memory")
#define CP_WAIT1()  asm volatile("cp.async.wait_group 1;" ::: "memory")

__device__ __forceinline__ void ldsm4(uint32_t* r, uint32_t addr) {
    asm volatile("ldmatrix.sync.aligned.m8n8.x4.shared.b16 {%0,%1,%2,%3}, [%4];"
        : "=r"(r[0]), "=r"(r[1]), "=r"(r[2]), "=r"(r[3]) : "r"(addr));
}
__device__ __forceinline__ void ldsm4t(uint32_t* r, uint32_t addr) {
    asm volatile("ldmatrix.sync.aligned.m8n8.x4.trans.shared.b16 {%0,%1,%2,%3}, [%4];"
        : "=r"(r[0]), "=r"(r[1]), "=r"(r[2]), "=r"(r[3]) : "r"(addr));
}
__device__ __forceinline__ void mma_fp16(float* c, const uint32_t* a, const uint32_t* b) {
    asm volatile(
        "mma.sync.aligned.m16n8k16.row.col.f32.f16.f16.f32 "
        "{%0,%1,%2,%3}, {%4,%5,%6,%7}, {%8,%9}, {%0,%1,%2,%3};"
        : "+f"(c[0]), "+f"(c[1]), "+f"(c[2]), "+f"(c[3])
        : "r"(a[0]), "r"(a[1]), "r"(a[2]), "r"(a[3]), "r"(b[0]), "r"(b[1]));
}

__device__ __forceinline__ float gelu_f(float x) {
    return 0.5f * x * (1.0f + erff(x * 0.7071067811865475f));
}
__device__ __forceinline__ uint32_t pack_h2(fp16 a, fp16 b) {
    __half2 t = __halves2half2(a, b);
    return *(uint32_t*)&t;
}

// swizzled smem addr for a 128B-row tile (rows x 64 fp16)
__device__ __forceinline__ uint32_t sw128(uint32_t base, int row, int chunk) {
    return base + row * 128 + ((chunk ^ (row & 7)) << 4);
}

// ---------------------------------------------------------------------------
// Single-pass fp16 GEMM: C[M,N] = A[M,K] @ Bt[N,K]^T
// BM=128, BN=128, BK=64 (128B rows, sw128), 3-stage ring, 1 barrier/iter,
// 2 CTAs/SM. 8 warps (2x4), warp tile 64x32.
// ---------------------------------------------------------------------------
#define GSTAGE 32768
#define GSMEM  (3 * GSTAGE)

template <int EPI>
__global__ void __launch_bounds__(256, 2) mma_gemm(
    const fp16* __restrict__ Ahi, const fp16* __restrict__ Bhi,
    int M, int N, int K, int lda, int ldb,
    const float* __restrict__ bias, const float* __restrict__ res,
    float* __restrict__ Cf, fp16* __restrict__ Chi)
{
    extern __shared__ char smem[];
    uint32_t sb = smem_u32(smem);
    int tid = threadIdx.x, wid = tid >> 5, lane = tid & 31;
    int row0 = blockIdx.y * 128, col0 = blockIdx.x * 128;

    const int NC = K >> 6;   // 64-wide K chunks

    auto load_stage = [&](int c) {
        int s = c % 3;
        uint32_t st = sb + s * GSTAGE;
        int k0 = c << 6;
        #pragma unroll
        for (int l = 0; l < 8; l++) {
            int idx = tid + l * 256;        // 2048 chunks of 16B (A 1024, B 1024)
            int mat = idx >> 10, r = (idx >> 3) & 127, ch = idx & 7;
            uint32_t dst = sw128(st + mat * 16384, r, ch);
            const fp16* src = mat == 0
                ? Ahi + (size_t)(row0 + r) * lda + k0 + ch * 8
                : Bhi + (size_t)(col0 + r) * ldb + k0 + ch * 8;
            CP_ASYNC_16(dst, src);
        }
        CP_COMMIT();
    };

    float acc[4][4][4] = {};
    int mi = lane >> 3, lr = lane & 7;
    int wm = (wid >> 2) * 64;
    int wn = (wid & 3) * 32;

    load_stage(0);
    load_stage(1);

    for (int c = 0; c < NC; c++) {
        if (c + 1 < NC) { CP_WAIT1(); }
        else            { CP_WAIT0(); }
        __syncthreads();
        if (c + 2 < NC) load_stage(c + 2);

        int s = c % 3;
        uint32_t stA = sb + s * GSTAGE;
        uint32_t stB = stA + 16384;
        #pragma unroll
        for (int ks = 0; ks < 4; ks++) {
            uint32_t ah[4][4], bh[2][4];
            #pragma unroll
            for (int t = 0; t < 4; t++) {
                int row = wm + t * 16 + ((mi & 1) << 3) + lr;
                int ch  = ks * 2 + (mi >> 1);
                ldsm4(ah[t], sw128(stA, row, ch));
            }
            #pragma unroll
            for (int p = 0; p < 2; p++) {
                int row = wn + p * 16 + ((mi >> 1) << 3) + lr;
                int ch  = ks * 2 + (mi & 1);
                ldsm4(bh[p], sw128(stB, row, ch));
            }
            #pragma unroll
            for (int tm = 0; tm < 4; tm++)
                #pragma unroll
                for (int tn = 0; tn < 4; tn++)
                    mma_fp16(acc[tm][tn], ah[tm], &bh[tn >> 1][(tn & 1) * 2]);
        }
    }

    int g = lane >> 2, tc = lane & 3;
    #pragma unroll
    for (int tm = 0; tm < 4; tm++) {
        #pragma unroll
        for (int tn = 0; tn < 4; tn++) {
            int rr = row0 + wm + tm * 16 + g;
            int cc = col0 + wn + tn * 8 + tc * 2;
            #pragma unroll
            for (int half_ = 0; half_ < 2; half_++) {
                int r_ = rr + half_ * 8;
                float v0 = acc[tm][tn][half_ * 2 + 0];
                float v1 = acc[tm][tn][half_ * 2 + 1];
                size_t off = (size_t)r_ * N + cc;
                if (EPI == 2 || EPI == 4) {
                    float2 b2 = *(const float2*)(bias + cc);
                    float2 r2 = *(const float2*)(res + off);
                    v0 += b2.x + r2.x; v1 += b2.y + r2.y;
                    *(float2*)(Cf + off) = make_float2(v0, v1);
                } else if (EPI == 3) {
                    float2 b2 = *(const float2*)(bias + cc);
                    v0 = gelu_f(v0 + b2.x); v1 = gelu_f(v1 + b2.y);
                }
                if (EPI == 1 || EPI == 2 || EPI == 3) {
                    *(uint32_t*)(Chi + off) =
                        pack_h2(__float2half_rn(v0), __float2half_rn(v1));
                }
            }
        }
    }
}

// ---------------------------------------------------------------------------
// Fused flash attention. 128 threads, 64 q-rows/CTA, 16 q-rows/warp.
// Q (pre-scaled) resident 8KB; K/V 3-stage ring 48KB; 4 CTAs/SM.
// grid (16 q-blocks, 128 z).
// ---------------------------------------------------------------------------
#define FA_SMEM (8192 + 3 * 16384)

__global__ void __launch_bounds__(128, 4) flash_kernel(
    const fp16* __restrict__ qkvh, fp16* __restrict__ aoh)
{
    extern __shared__ char smem[];
    uint32_t sb = smem_u32(smem);
    int tid = threadIdx.x, wid = tid >> 5, lane = tid & 31;
    int mi = lane >> 3, lr = lane & 7;
    int g = lane >> 2, tc = lane & 3;
    int z = blockIdx.y;
    int b = z >> 6, h = (z >> 3) & 7, p = z & 7;
    int row0 = blockIdx.x * 64;
    size_t base = (size_t)((b * 8 + p)) * NSEQ * QKVW + h * 64;
    const fp16* Qh = qkvh + base;
    const fp16* Kh = qkvh + base + 512;
    const fp16* Vh = qkvh + base + 1024;

    uint32_t qoff = sb;          // Q 8KB (64 rows x 128B)
    uint32_t soff = sb + 8192;   // 3 stages x 16KB (Kh, Vh @ 8KB)

    // Q tile: 64 rows x 64 fp16, folded into stage-0 commit
    #pragma unroll
    for (int l = 0; l < 4; l++) {
        int idx = tid + l * 128;           // 512 chunks
        int r = idx >> 3, ch = idx & 7;
        CP_ASYNC_16(sw128(qoff, r, ch), Qh + (size_t)(row0 + r) * QKVW + ch * 8);
    }

    auto load_stage = [&](int c) {
        int s = c % 3;
        uint32_t st = soff + s * 16384;
        int kv0 = c << 6;
        #pragma unroll
        for (int l = 0; l < 8; l++) {
            int idx = tid + l * 128;       // 1024 chunks
            int mat = idx >> 9, r = (idx >> 3) & 63, ch = idx & 7;
            const fp16* src = (mat == 0 ? Kh : Vh) + (size_t)(kv0 + r) * QKVW + ch * 8;
            CP_ASYNC_16(sw128(st + mat * 8192, r, ch), src);
        }
        CP_COMMIT();
    };

    load_stage(0);   // commits {Q, stage0}
    load_stage(1);

    float m_r[2] = {-1e30f, -1e30f};
    float l_r[2] = {0.f, 0.f};
    float O[8][4] = {};
    int qr0 = wid * 16;

    for (int c = 0; c < 16; c++) {
        if (c + 1 < 16) { CP_WAIT1(); }
        else            { CP_WAIT0(); }
        __syncthreads();
        if (c + 2 < 16) load_stage(c + 2);

        int s = c % 3;
        uint32_t kh_o = soff + s * 16384;
        uint32_t vh_o = kh_o + 8192;

        // S = Q K^T (scale pre-folded into Q), 16x64 per warp
        float S[8][4] = {};
        #pragma unroll
        for (int ks = 0; ks < 4; ks++) {
            uint32_t ah[4];
            {
                int row = qr0 + ((mi & 1) << 3) + lr;
                int ch  = ks * 2 + (mi >> 1);
                ldsm4(ah, sw128(qoff, row, ch));
            }
            #pragma unroll
            for (int np = 0; np < 4; np++) {
                uint32_t bh[4];
                int row = np * 16 + ((mi >> 1) << 3) + lr;
                int ch  = ks * 2 + (mi & 1);
                ldsm4(bh, sw128(kh_o, row, ch));
                mma_fp16(S[np * 2],     ah, &bh[0]);
                mma_fp16(S[np * 2 + 1], ah, &bh[2]);
            }
        }

        // online softmax (log2 domain, S already scaled)
        #pragma unroll
        for (int hf = 0; hf < 2; hf++) {
            float mx = -1e30f;
            #pragma unroll
            for (int j = 0; j < 8; j++)
                mx = fmaxf(mx, fmaxf(S[j][hf * 2], S[j][hf * 2 + 1]));
            mx = fmaxf(mx, __shfl_xor_sync(0xffffffffu, mx, 1));
            mx = fmaxf(mx, __shfl_xor_sync(0xffffffffu, mx, 2));
            float mnew = fmaxf(m_r[hf], mx);
            float alpha = exp2f(m_r[hf] - mnew);
            m_r[hf] = mnew;
            float s_ = 0.f;
            #pragma unroll
            for (int j = 0; j < 8; j++) {
                float p0 = exp2f(S[j][hf * 2]     - mnew);
                float p1 = exp2f(S[j][hf * 2 + 1] - mnew);
                S[j][hf * 2] = p0; S[j][hf * 2 + 1] = p1;
                s_ += p0 + p1;
            }
            s_ += __shfl_xor_sync(0xffffffffu, s_, 1);
            s_ += __shfl_xor_sync(0xffffffffu, s_, 2);
            l_r[hf] = l_r[hf] * alpha + s_;
            #pragma unroll
            for (int j = 0; j < 8; j++) {
                O[j][hf * 2]     *= alpha;
                O[j][hf * 2 + 1] *= alpha;
            }
        }

        // pack P hi (C-frag -> A-frag correspondence)
        uint32_t ph[4][4];
        #pragma unroll
        for (int s2 = 0; s2 < 4; s2++) {
            #pragma unroll
            for (int q4 = 0; q4 < 4; q4++) {
                int j  = s2 * 2 + (q4 >> 1);
                int k0 = (q4 & 1) * 2;
                ph[s2][q4] = pack_h2(__float2half_rn(S[j][k0]),
                                     __float2half_rn(S[j][k0 + 1]));
            }
        }

        // O += P V, V via ldmatrix.trans
        #pragma unroll
        for (int s2 = 0; s2 < 4; s2++) {
            #pragma unroll
            for (int dp = 0; dp < 4; dp++) {
                uint32_t vhh[4];
                int row = s2 * 16 + ((mi & 1) << 3) + lr;
                int chk = dp * 2 + (mi >> 1);
                ldsm4t(vhh, sw128(vh_o, row, chk));
                mma_fp16(O[dp * 2],     ph[s2], &vhh[0]);
                mma_fp16(O[dp * 2 + 1], ph[s2], &vhh[2]);
            }
        }
    }

    float inv0 = 1.0f / l_r[0], inv1 = 1.0f / l_r[1];
    size_t obase = (size_t)(b * 8 + h) * NSEQ;
    #pragma unroll
    for (int dp = 0; dp < 8; dp++) {
        int d = dp * 8 + tc * 2;
        #pragma unroll
        for (int hf = 0; hf < 2; hf++) {
            float inv = hf ? inv1 : inv0;
            int n = row0 + qr0 + g + hf * 8;
            float v0 = O[dp][hf * 2]     * inv;
            float v1 = O[dp][hf * 2 + 1] * inv;
            size_t off = (obase + n) * DIM + p * 64 + d;
            *(uint32_t*)(aoh + off) =
                pack_h2(__float2half_rn(v0), __float2half_rn(v1));
        }
    }
}

// ---------------------------------------------------------------------------
// Fused weight transpose + cast. q-columns of wqkv (n < 512) pre-scaled
// by SCALE * log2(e).
// ---------------------------------------------------------------------------
__global__ void __launch_bounds__(256) tcast_all(
    const float* __restrict__ Wq, fp16* __restrict__ Tq,
    const float* __restrict__ Wo, fp16* __restrict__ To,
    const float* __restrict__ W1, fp16* __restrict__ T1,
    const float* __restrict__ W2, fp16* __restrict__ T2)
{
    int id = blockIdx.x * 256 + threadIdx.x;
    const int S0 = 512 * 1536, S1 = S0 + 512 * 512, S2 = S1 + 512 * 2048;
    const float* W; fp16* T; int K, N, i;
    bool qscale = false;
    if (id < S0)      { W = Wq; T = Tq; K = 512;  N = 1536; i = id; qscale = true; }
    else if (id < S1) { W = Wo; T = To; K = 512;  N = 512;  i = id - S0; }
    else if (id < S2) { W = W1; T = T1; K = 512;  N = 2048; i = id - S1; }
    else              { W = W2; T = T2; K = 2048; N = 512;  i = id - S2; }
    int n = i / K, k = i - n * K;
    float v = W[(size_t)k * N + n];
    if (qscale && n < 512) v *= SCALE * 1.4426950408889634f;
    T[i] = __float2half_rn(v);
}

// ---------------------------------------------------------------------------
// LN0 + LN1
// ---------------------------------------------------------------------------
__device__ __forceinline__ float block_sum(float v, float* sm) {
    #pragma unroll
    for (int o = 16; o > 0; o >>= 1) v += __shfl_down_sync(0xffffffffu, v, o);
    int lane = threadIdx.x & 31, wid = threadIdx.x >> 5;
    if (lane == 0) sm[wid] = v;
    __syncthreads();
    v = (threadIdx.x < 8) ? sm[threadIdx.x] : 0.0f;
    if (wid == 0) {
        #pragma unroll
        for (int o = 4; o > 0; o >>= 1) v += __shfl_down_sync(0xffffffffu, v, o);
        if (lane == 0) sm[0] = v;
    }
    __syncthreads();
    float r = sm[0];
    __syncthreads();
    return r;
}

__global__ void __launch_bounds__(256) ln_kernel(
    const float* __restrict__ x,
    const float* __restrict__ w0, const float* __restrict__ b0,
    const float* __restrict__ w1, const float* __restrict__ b1,
    float* __restrict__ xn, fp16* __restrict__ hh)
{
    __shared__ float sm[32];
    size_t row = blockIdx.x;
    const float* xr = x + row * DIM;
    int t = threadIdx.x;

    float v0 = xr[t], v1 = xr[t + 256];
    float mu = block_sum(v0 + v1, sm) * (1.0f / DIM);
    float d0 = v0 - mu, d1 = v1 - mu;
    float var = block_sum(d0 * d0 + d1 * d1, sm) * (1.0f / DIM);
    float r = rsqrtf(var + EPS);
    float y0 = d0 * r * w0[t] + b0[t];
    float y1 = d1 * r * w0[t + 256] + b0[t + 256];
    xn[row * DIM + t]       = y0;
    xn[row * DIM + t + 256] = y1;

    float mu2 = block_sum(y0 + y1, sm) * (1.0f / DIM);
    float e0 = y0 - mu2, e1 = y1 - mu2;
    float var2 = block_sum(e0 * e0 + e1 * e1, sm) * (1.0f / DIM);
    float r2 = rsqrtf(var2 + EPS);
    hh[row * DIM + t]       = __float2half_rn(e0 * r2 * w1[t] + b1[t]);
    hh[row * DIM + t + 256] = __float2half_rn(e1 * r2 * w1[t + 256] + b1[t + 256]);
}

// ---------------------------------------------------------------------------
// Launch
// ---------------------------------------------------------------------------
extern "C" void kernel_launch(void* const* d_in, const int* in_sizes, int n_in,
                              void* d_out, int out_size)
{
    (void)in_sizes; (void)n_in; (void)out_size;
    const float* x     = (const float*)d_in[0];
    const float* ln0_w = (const float*)d_in[1];
    const float* ln0_b = (const float*)d_in[2];
    const float* ln1_w = (const float*)d_in[3];
    const float* ln1_b = (const float*)d_in[4];
    const float* w_qkv = (const float*)d_in[5];
    const float* w_o   = (const float*)d_in[6];
    const float* b_o   = (const float*)d_in[7];
    const float* w1    = (const float*)d_in[8];
    const float* b1    = (const float*)d_in[9];
    const float* w2    = (const float*)d_in[10];
    const float* b2    = (const float*)d_in[11];
    float* out = (float*)d_out;

    void *p;
    cudaGetSymbolAddress(&p, g_xn);    float* xn   = (float*)p;
    cudaGetSymbolAddress(&p, g_hh);    fp16* hh    = (fp16*)p;
    cudaGetSymbolAddress(&p, g_qkvh);  fp16* qkvh  = (fp16*)p;
    cudaGetSymbolAddress(&p, g_aoh);   fp16* aoh   = (fp16*)p;
    cudaGetSymbolAddress(&p, g_x2);    float* x2   = (float*)p;
    cudaGetSymbolAddress(&p, g_x2h);   fp16* x2h   = (fp16*)p;
    cudaGetSymbolAddress(&p, g_midh);  fp16* midh  = (fp16*)p;
    cudaGetSymbolAddress(&p, g_wqkvt); fp16* wqkvt = (fp16*)p;
    cudaGetSymbolAddress(&p, g_wot);   fp16* wot   = (fp16*)p;
    cudaGetSymbolAddress(&p, g_w1t);   fp16* w1t   = (fp16*)p;
    cudaGetSymbolAddress(&p, g_w2t);   fp16* w2t   = (fp16*)p;

    cudaFuncSetAttribute(mma_gemm<1>, cudaFuncAttributeMaxDynamicSharedMemorySize, GSMEM);
    cudaFuncSetAttribute(mma_gemm<2>, cudaFuncAttributeMaxDynamicSharedMemorySize, GSMEM);
    cudaFuncSetAttribute(mma_gemm<3>, cudaFuncAttributeMaxDynamicSharedMemorySize, GSMEM);
    cudaFuncSetAttribute(mma_gemm<4>, cudaFuncAttributeMaxDynamicSharedMemorySize, GSMEM);
    cudaFuncSetAttribute(flash_kernel, cudaFuncAttributeMaxDynamicSharedMemorySize, FA_SMEM);

    // weight prep
    tcast_all<<<12288, 256>>>(w_qkv, wqkvt, w_o, wot, w1, w1t, w2, w2t);

    // 1) LN0 + LN1
    ln_kernel<<<ROWS, 256>>>(x, ln0_w, ln0_b, ln1_w, ln1_b, xn, hh);
    // 2) qkv = h @ w_qkv  (hi out; q pre-scaled)
    mma_gemm<1><<<dim3(QKVW / 128, ROWS / 128), 256, GSMEM>>>(
        hh, wqkvt, ROWS, QKVW, DIM, DIM, DIM,
        nullptr, nullptr, nullptr, qkvh);
    // 3) fused attention
    flash_kernel<<<dim3(16, NZ), 128, FA_SMEM>>>(qkvh, aoh);
    // 4) x2 = ao @ w_o + b_o + xn  (fp32 + hi)
    mma_gemm<2><<<dim3(DIM / 128, ROWS / 128), 256, GSMEM>>>(
        aoh, wot, ROWS, DIM, INNER, INNER, INNER,
        b_o, xn, x2, x2h);
    // 5) mid = gelu(x2 @ w1 + b1)  (hi out)
    mma_gemm<3><<<dim3(HIDDEN / 128, ROWS / 128), 256, GSMEM>>>(
        x2h, w1t, ROWS, HIDDEN, DIM, DIM, DIM,
        b1, nullptr, nullptr, midh);
    // 6) out = mid @ w2 + b2 + x2  (fp32)
    mma_gemm<4><<<dim3(DIM / 128, ROWS / 128), 256, GSMEM>>>(
        midh, w2t, ROWS, DIM, HIDDEN, HIDDEN, HIDDEN,
        b2, x2, out, nullptr);
}